// round 11
// baseline (speedup 1.0000x reference)
#include <cuda_runtime.h>
#include <cuda_bf16.h>
#include <math.h>
#include <stdint.h>

// Problem constants (fixed by the dataset)
#define B_   4
#define S_   512
#define N_   8
#define D_   256
#define H_   8
#define HD_  32
#define BN_  (B_ * N_)          // 32
#define T_   (BN_ * S_)         // 16384 rows
#define QKVN 768                // 3*D

// ---------------- warp-mma helpers (baseline PTX, sm_80+) ---------------------
__device__ __forceinline__ uint32_t smem_u32(const void* p) {
    uint32_t a;
    asm("{ .reg .u64 t; cvta.to.shared.u64 t, %1; cvt.u32.u64 %0, t; }" : "=r"(a) : "l"(p));
    return a;
}
__device__ __forceinline__ void ldsm_x4(uint32_t& r0, uint32_t& r1, uint32_t& r2, uint32_t& r3,
                                        uint32_t addr) {
    asm volatile("ldmatrix.sync.aligned.m8n8.x4.shared.b16 {%0,%1,%2,%3}, [%4];"
        : "=r"(r0), "=r"(r1), "=r"(r2), "=r"(r3) : "r"(addr));
}
__device__ __forceinline__ void mma_bf16(float* c, const uint32_t* a, uint32_t b0, uint32_t b1) {
    asm volatile(
        "mma.sync.aligned.m16n8k16.row.col.f32.bf16.bf16.f32 "
        "{%0,%1,%2,%3}, {%4,%5,%6,%7}, {%8,%9}, {%0,%1,%2,%3};"
        : "+f"(c[0]), "+f"(c[1]), "+f"(c[2]), "+f"(c[3])
        : "r"(a[0]), "r"(a[1]), "r"(a[2]), "r"(a[3]), "r"(b0), "r"(b1));
}
__device__ __forceinline__ uint32_t bf16x2pack(float v0, float v1) {
    uint32_t r;
    asm("cvt.rn.bf16x2.f32 %0, %1, %2;" : "=r"(r) : "f"(v1), "f"(v0));
    return r;
}
__device__ __forceinline__ void split2(float v0, float v1, uint32_t& hi, uint32_t& lo) {
    hi = bf16x2pack(v0, v1);
    float h0 = __uint_as_float(hi << 16);
    float h1 = __uint_as_float(hi & 0xFFFF0000u);
    lo = bf16x2pack(v0 - h0, v1 - h1);
}
__device__ __forceinline__ void cp16(uint32_t dst, const void* src) {
    asm volatile("cp.async.cg.shared.global [%0], [%1], 16;" :: "r"(dst), "l"(src));
}
#define CP_COMMIT() asm volatile("cp.async.commit_group;" ::: "memory")
#define CP_WAIT3()  asm volatile("cp.async.wait_group 3;" ::: "memory")
#define CP_WAIT2()  asm volatile("cp.async.wait_group 2;" ::: "memory")
#define CP_WAIT1()  asm volatile("cp.async.wait_group 1;" ::: "memory")
#define CP_WAIT0()  asm volatile("cp.async.wait_group 0;" ::: "memory")
#define SWZ128(off) ((off) ^ (((off) >> 3) & 0x70))
// SW64 for 64-byte-pitch rows: XOR 16B-column bits [5:4] with row bits [2:1].
#define SWZ64(off)  ((off) ^ (((off) >> 3) & 0x30))

// ---------------- scratch (device globals; no runtime allocation) -------------
__device__ float g_pe[S_ * D_];
__device__ __nv_bfloat16 g_a2[(long)T_ * 512];         // [hi(256)|lo(256)] per row
__device__ __nv_bfloat16 g_w2[QKVN * 512];
__device__ __nv_bfloat16 g_wo2[D_ * 512];
__device__ float g_bcat[QKVN];
__device__ __nv_bfloat16 g_qh[(long)BN_ * H_ * S_ * HD_];   // [bnh][s][e] Q*scale hi
__device__ __nv_bfloat16 g_ql[(long)BN_ * H_ * S_ * HD_];
__device__ __nv_bfloat16 g_kh[(long)BN_ * H_ * S_ * HD_];
__device__ __nv_bfloat16 g_kl[(long)BN_ * H_ * S_ * HD_];
__device__ __nv_bfloat16 g_vth[(long)BN_ * H_ * HD_ * S_];  // [bnh][e][s]  V^T
__device__ __nv_bfloat16 g_vtl[(long)BN_ * H_ * HD_ * S_];
__device__ __nv_bfloat16 g_att2[(long)T_ * 512];

// ---------------- 1) positional encoding table -------------------------------
__global__ void pe_kernel() {
    int idx = blockIdx.x * 256 + threadIdx.x;       // 65536 = S * D/2
    int s = idx >> 7;
    int i = idx & 127;
    float div = expf((float)(2 * i) * (-0.035977892078031970f)); // -ln(10000)/256
    float sn, cs;
    sincosf((float)s * div, &sn, &cs);
    g_pe[s * D_ + 2 * i]     = sn;
    g_pe[s * D_ + 2 * i + 1] = cs;
}

// ---------------- 2) x + pe -> bf16 hi/lo split, (B,S,N,D)->(BN,S,D) ----------
__global__ void addpe_split_kernel(const float* __restrict__ x) {
    int idx = blockIdx.x * 256 + threadIdx.x;       // 1,048,576 groups of 4
    int d4 = idx & 63;
    int s  = (idx >> 6) & 511;
    int bn = idx >> 15;
    int b = bn >> 3, n = bn & 7;
    const float4 xv = *(const float4*)(x + ((((long)b * S_ + s) * N_ + n) * D_ + d4 * 4));
    const float4 pv = *(const float4*)(g_pe + (s * D_ + d4 * 4));
    float v[4] = {xv.x + pv.x, xv.y + pv.y, xv.z + pv.z, xv.w + pv.w};
    long t = (long)bn * S_ + s;
    __nv_bfloat16* hb = g_a2 + t * 512 + d4 * 4;
    uint32_t h01, l01, h23, l23;
    split2(v[0], v[1], h01, l01);
    split2(v[2], v[3], h23, l23);
    ((uint32_t*)hb)[0] = h01;
    ((uint32_t*)hb)[1] = h23;
    ((uint32_t*)(hb + 256))[0] = l01;
    ((uint32_t*)(hb + 256))[1] = l23;
}

// ---------------- 3) all weights: concat + hi/lo split (one launch) -----------
__global__ void wsplit_all_kernel(const float* __restrict__ Wq, const float* __restrict__ bq,
                                  const float* __restrict__ Wk, const float* __restrict__ bk,
                                  const float* __restrict__ Wv, const float* __restrict__ bv,
                                  const float* __restrict__ Wo) {
    int idx = blockIdx.x * 256 + threadIdx.x;       // 262144 = 1024 rows * 256
    int j = idx >> 8, k = idx & 255;
    int jj = j & 255;
    if (j < 768) {
        const float* src; const float* bsrc;
        if (j < 256)      { src = Wq; bsrc = bq; }
        else if (j < 512) { src = Wk; bsrc = bk; }
        else              { src = Wv; bsrc = bv; }
        float v = src[jj * D_ + k];
        __nv_bfloat16 h = __float2bfloat16(v);
        g_w2[j * 512 + k]       = h;
        g_w2[j * 512 + 256 + k] = __float2bfloat16(v - __bfloat162float(h));
        if (k == 0) g_bcat[j] = bsrc[jj];
    } else {
        float v = Wo[jj * D_ + k];
        __nv_bfloat16 h = __float2bfloat16(v);
        g_wo2[jj * 512 + k]       = h;
        g_wo2[jj * 512 + 256 + k] = __float2bfloat16(v - __bfloat162float(h));
    }
}

// ---------------- 4) qkv GEMM: 4-stage cp.async + SW64 (conflict-free) --------
// C[16384,768]. Block 128x128, K-chunk 32, 4-stage pipeline, dynamic smem 64KB.
// Epilogue writes split bf16 Q(scaled)/K and transposed V.
#define QKV_SMEM (4 * 8192 * 2)
__global__ void __launch_bounds__(256) qkv_gemm_kernel() {
    extern __shared__ __align__(128) char dsmem[];
    const int tid = threadIdx.x;
    const int wid = tid >> 5, lane = tid & 31;
    const int wm = wid & 3;          // 4 warps along M
    const int wn = wid >> 2;         // 2 warps along N
    const int mBase = blockIdx.y * 128;
    const int nBase = blockIdx.x * 128;

    const uint32_t baseA = smem_u32(dsmem);            // 4 bufs x 8KB
    const uint32_t baseW = baseA + 32768;              // 4 bufs x 8KB

    float acc[2][8][4];
    #pragma unroll
    for (int i = 0; i < 2; ++i)
        #pragma unroll
        for (int j = 0; j < 8; ++j)
            #pragma unroll
            for (int q = 0; q < 4; ++q) acc[i][j][q] = 0.f;

    auto issue = [&](int s) {
        int buf = s & 3;
        int t = s >> 3, kc = s & 7;
        int aoff = ((t == 2) ? 256 : 0) + kc * 32;
        int woff = ((t == 1) ? 256 : 0) + kc * 32;
        #pragma unroll
        for (int i = 0; i < 2; ++i) {
            int f = i * 256 + tid;
            int row = f >> 2, c = f & 3;
            uint32_t so = SWZ64((uint32_t)(row * 64 + c * 16));
            cp16(baseA + (uint32_t)(buf * 8192) + so,
                 g_a2 + ((long)(mBase + row)) * 512 + aoff + c * 8);
            cp16(baseW + (uint32_t)(buf * 8192) + so,
                 g_w2 + ((long)(nBase + row)) * 512 + woff + c * 8);
        }
    };

    issue(0); CP_COMMIT();
    issue(1); CP_COMMIT();
    issue(2); CP_COMMIT();

    for (int s = 0; s < 24; ++s) {
        const int buf = s & 3;
        if (s + 3 < 24) { issue(s + 3); CP_COMMIT(); }
        if (s < 21)      { CP_WAIT3(); }
        else if (s == 21) { CP_WAIT2(); }
        else if (s == 22) { CP_WAIT1(); }
        else              { CP_WAIT0(); }
        __syncthreads();

        const uint32_t bA = baseA + buf * 8192;
        const uint32_t bW = baseW + buf * 8192;
        #pragma unroll
        for (int ks = 0; ks < 2; ++ks) {
            uint32_t a[2][4];
            #pragma unroll
            for (int mf = 0; mf < 2; ++mf) {
                uint32_t off = SWZ64((uint32_t)((wm * 32 + mf * 16 + (lane & 15)) * 64
                                                + ks * 32 + (lane >> 4) * 16));
                ldsm_x4(a[mf][0], a[mf][1], a[mf][2], a[mf][3], bA + off);
            }
            uint32_t b[4][4];
            #pragma unroll
            for (int g = 0; g < 4; ++g) {
                uint32_t off = SWZ64((uint32_t)((wn * 64 + g * 16 + (lane >> 4) * 8 + (lane & 7)) * 64
                                                + ks * 32 + ((lane >> 3) & 1) * 16));
                ldsm_x4(b[g][0], b[g][1], b[g][2], b[g][3], bW + off);
            }
            #pragma unroll
            for (int mf = 0; mf < 2; ++mf)
                #pragma unroll
                for (int nf = 0; nf < 8; ++nf) {
                    const uint32_t* bp = b[nf >> 1];
                    if (nf & 1) mma_bf16(acc[mf][nf], a[mf], bp[2], bp[3]);
                    else        mma_bf16(acc[mf][nf], a[mf], bp[0], bp[1]);
                }
        }
        __syncthreads();
    }

    // epilogue: route to split Q (scaled) / K / V^T
    const int colq = (lane & 3) * 2;
    const float qscale = 0.17677669529663687f;   // 1/sqrt(32)
    #pragma unroll
    for (int mf = 0; mf < 2; ++mf) {
        int r0 = mBase + wm * 32 + mf * 16 + (lane >> 2);
        #pragma unroll
        for (int nf = 0; nf < 8; ++nf) {
            int col = nBase + wn * 64 + nf * 8 + colq;
            float bx = g_bcat[col], by = g_bcat[col + 1];
            float v00 = acc[mf][nf][0] + bx, v01 = acc[mf][nf][1] + by;   // row r0
            float v10 = acc[mf][nf][2] + bx, v11 = acc[mf][nf][3] + by;   // row r0+8
            int type = col >> 8, d = col & 255, hh = d >> 5, e = d & 31;
            if (type == 0) { v00 *= qscale; v01 *= qscale; v10 *= qscale; v11 *= qscale; }
            uint32_t h01, l01, h23, l23;
            split2(v00, v01, h01, l01);
            split2(v10, v11, h23, l23);
            int bnh0 = ((r0 >> 9) * H_ + hh);
            int s0 = r0 & 511;
            if (type < 2) {
                __nv_bfloat16* dh = type ? g_kh : g_qh;
                __nv_bfloat16* dl = type ? g_kl : g_ql;
                long a0 = ((long)bnh0 * S_ + s0) * HD_ + e;
                *(uint32_t*)(dh + a0)            = h01;
                *(uint32_t*)(dl + a0)            = l01;
                *(uint32_t*)(dh + a0 + 8 * HD_)  = h23;
                *(uint32_t*)(dl + a0 + 8 * HD_)  = l23;
            } else {
                long vb = ((long)bnh0 * HD_ + e) * S_ + s0;
                unsigned short* vh = (unsigned short*)g_vth;
                unsigned short* vl = (unsigned short*)g_vtl;
                vh[vb]           = (unsigned short)(h01 & 0xFFFF);
                vh[vb + S_]      = (unsigned short)(h01 >> 16);
                vh[vb + 8]       = (unsigned short)(h23 & 0xFFFF);
                vh[vb + S_ + 8]  = (unsigned short)(h23 >> 16);
                vl[vb]           = (unsigned short)(l01 & 0xFFFF);
                vl[vb + S_]      = (unsigned short)(l01 >> 16);
                vl[vb + 8]       = (unsigned short)(l23 & 0xFFFF);
                vl[vb + S_ + 8]  = (unsigned short)(l23 >> 16);
            }
        }
    }
}

// ---------------- 5) causal flash attention (tensor cores, bf16 split) --------
__global__ void __launch_bounds__(256) attn_mma_kernel() {
    __shared__ __align__(128)  __nv_bfloat16 sQh[128 * 40];
    __shared__ __align__(128)  __nv_bfloat16 sQl[128 * 40];
    __shared__ __align__(128)  __nv_bfloat16 sKh[64 * 40];
    __shared__ __align__(128)  __nv_bfloat16 sKl[64 * 40];
    __shared__ __align__(1024) __nv_bfloat16 sVh[32 * 64];
    __shared__ __align__(1024) __nv_bfloat16 sVl[32 * 64];
    const int tid = threadIdx.x, wid = tid >> 5, lane = tid & 31;
    const int qBase = blockIdx.x * 128;
    const int h = blockIdx.y, bn = blockIdx.z;
    const int bnh = bn * H_ + h;
    const int qw = qBase + wid * 16;
    const long kvoff = (long)bnh * S_ * HD_;
    const __nv_bfloat16* qhg = g_qh + kvoff;
    const __nv_bfloat16* qlg = g_ql + kvoff;
    const __nv_bfloat16* khg = g_kh + kvoff;
    const __nv_bfloat16* klg = g_kl + kvoff;
    const __nv_bfloat16* vhg = g_vth + kvoff;
    const __nv_bfloat16* vlg = g_vtl + kvoff;

    #pragma unroll
    for (int i = 0; i < 2; ++i) {
        int f = i * 256 + tid, row = f >> 2, c = f & 3;
        *(float4*)((char*)sQh + row * 80 + c * 16) = *(const float4*)(qhg + (long)(qBase + row) * 32 + c * 8);
        *(float4*)((char*)sQl + row * 80 + c * 16) = *(const float4*)(qlg + (long)(qBase + row) * 32 + c * 8);
    }
    __syncthreads();

    const uint32_t bQh = smem_u32(sQh), bQl = smem_u32(sQl);
    const uint32_t bKh = smem_u32(sKh), bKl = smem_u32(sKl);
    const uint32_t bVh = smem_u32(sVh), bVl = smem_u32(sVl);

    uint32_t qfh[2][4], qfl[2][4];
    #pragma unroll
    for (int ks = 0; ks < 2; ++ks) {
        uint32_t off = (uint32_t)((wid * 16 + (lane & 15)) * 80 + ks * 32 + (lane >> 4) * 16);
        ldsm_x4(qfh[ks][0], qfh[ks][1], qfh[ks][2], qfh[ks][3], bQh + off);
        ldsm_x4(qfl[ks][0], qfl[ks][1], qfl[ks][2], qfl[ks][3], bQl + off);
    }

    float o[4][4];
    #pragma unroll
    for (int i = 0; i < 4; ++i)
        #pragma unroll
        for (int j = 0; j < 4; ++j) o[i][j] = 0.f;
    float m0 = -1e30f, m1 = -1e30f, l0 = 0.f, l1 = 0.f;

    const int nkt_w = (qw >> 6) + 1;
    const int nkt_b = (qBase >> 6) + 2;

    for (int kt = 0; kt < nkt_b; ++kt) {
        {
            int row = tid >> 2, c = tid & 3;
            *(float4*)((char*)sKh + row * 80 + c * 16) = *(const float4*)(khg + (long)(kt * 64 + row) * 32 + c * 8);
            *(float4*)((char*)sKl + row * 80 + c * 16) = *(const float4*)(klg + (long)(kt * 64 + row) * 32 + c * 8);
            int vr = tid >> 3, vc = tid & 7;
            uint32_t so = SWZ128((uint32_t)(vr * 128 + vc * 16));
            *(float4*)((char*)sVh + so) = *(const float4*)(vhg + (long)vr * S_ + kt * 64 + vc * 8);
            *(float4*)((char*)sVl + so) = *(const float4*)(vlg + (long)vr * S_ + kt * 64 + vc * 8);
        }
        __syncthreads();

        if (kt < nkt_w) {
            float s[8][4];
            #pragma unroll
            for (int nt = 0; nt < 8; ++nt)
                #pragma unroll
                for (int j = 0; j < 4; ++j) s[nt][j] = 0.f;

            #pragma unroll
            for (int ks = 0; ks < 2; ++ks) {
                uint32_t bh[4][4], bl[4][4];
                #pragma unroll
                for (int g = 0; g < 4; ++g) {
                    uint32_t off = (uint32_t)((g * 16 + (lane >> 4) * 8 + (lane & 7)) * 80
                                              + ks * 32 + ((lane >> 3) & 1) * 16);
                    ldsm_x4(bh[g][0], bh[g][1], bh[g][2], bh[g][3], bKh + off);
                    ldsm_x4(bl[g][0], bl[g][1], bl[g][2], bl[g][3], bKl + off);
                }
                #pragma unroll
                for (int nt = 0; nt < 8; ++nt) {
                    const uint32_t* ph = bh[nt >> 1];
                    const uint32_t* pl = bl[nt >> 1];
                    int e0 = (nt & 1) * 2, e1 = e0 + 1;
                    mma_bf16(s[nt], qfh[ks], ph[e0], ph[e1]);
                    mma_bf16(s[nt], qfh[ks], pl[e0], pl[e1]);
                    mma_bf16(s[nt], qfl[ks], ph[e0], ph[e1]);
                }
            }

            if (kt == (qw >> 6)) {
                int q0 = qw + (lane >> 2), q1 = q0 + 8;
                #pragma unroll
                for (int nt = 0; nt < 8; ++nt) {
                    int k0 = kt * 64 + nt * 8 + ((lane & 3) << 1);
                    if (k0 > q0)     s[nt][0] = -1e9f;
                    if (k0 + 1 > q0) s[nt][1] = -1e9f;
                    if (k0 > q1)     s[nt][2] = -1e9f;
                    if (k0 + 1 > q1) s[nt][3] = -1e9f;
                }
            }

            float mx0 = -1e30f, mx1 = -1e30f;
            #pragma unroll
            for (int nt = 0; nt < 8; ++nt) {
                mx0 = fmaxf(mx0, fmaxf(s[nt][0], s[nt][1]));
                mx1 = fmaxf(mx1, fmaxf(s[nt][2], s[nt][3]));
            }
            mx0 = fmaxf(mx0, __shfl_xor_sync(0xFFFFFFFFu, mx0, 1));
            mx0 = fmaxf(mx0, __shfl_xor_sync(0xFFFFFFFFu, mx0, 2));
            mx1 = fmaxf(mx1, __shfl_xor_sync(0xFFFFFFFFu, mx1, 1));
            mx1 = fmaxf(mx1, __shfl_xor_sync(0xFFFFFFFFu, mx1, 2));
            float nm0 = fmaxf(m0, mx0), nm1 = fmaxf(m1, mx1);
            float a0 = __expf(m0 - nm0), a1 = __expf(m1 - nm1);
            m0 = nm0; m1 = nm1;

            float sum0 = 0.f, sum1 = 0.f;
            uint32_t aph[4][4], apl[4][4];
            #pragma unroll
            for (int nt = 0; nt < 8; ++nt) {
                float p0 = __expf(s[nt][0] - m0), p1 = __expf(s[nt][1] - m0);
                float p2 = __expf(s[nt][2] - m1), p3 = __expf(s[nt][3] - m1);
                sum0 += p0 + p1; sum1 += p2 + p3;
                uint32_t h01, l01, h23, l23;
                split2(p0, p1, h01, l01);
                split2(p2, p3, h23, l23);
                int kk = nt >> 1, r = (nt & 1) * 2;
                aph[kk][r]     = h01;
                aph[kk][r + 1] = h23;
                apl[kk][r]     = l01;
                apl[kk][r + 1] = l23;
            }
            sum0 += __shfl_xor_sync(0xFFFFFFFFu, sum0, 1);
            sum0 += __shfl_xor_sync(0xFFFFFFFFu, sum0, 2);
            sum1 += __shfl_xor_sync(0xFFFFFFFFu, sum1, 1);
            sum1 += __shfl_xor_sync(0xFFFFFFFFu, sum1, 2);
            l0 = l0 * a0 + sum0;
            l1 = l1 * a1 + sum1;
            #pragma unroll
            for (int nt = 0; nt < 4; ++nt) {
                o[nt][0] *= a0; o[nt][1] *= a0;
                o[nt][2] *= a1; o[nt][3] *= a1;
            }

            #pragma unroll
            for (int kk = 0; kk < 4; ++kk) {
                uint32_t vh[2][4], vl[2][4];
                #pragma unroll
                for (int g = 0; g < 2; ++g) {
                    uint32_t off = SWZ128((uint32_t)((g * 16 + (lane >> 4) * 8 + (lane & 7)) * 128
                                                     + kk * 32 + ((lane >> 3) & 1) * 16));
                    ldsm_x4(vh[g][0], vh[g][1], vh[g][2], vh[g][3], bVh + off);
                    ldsm_x4(vl[g][0], vl[g][1], vl[g][2], vl[g][3], bVl + off);
                }
                #pragma unroll
                for (int nt = 0; nt < 4; ++nt) {
                    const uint32_t* ph = vh[nt >> 1];
                    const uint32_t* pl = vl[nt >> 1];
                    int e0 = (nt & 1) * 2, e1 = e0 + 1;
                    mma_bf16(o[nt], aph[kk], ph[e0], ph[e1]);
                    mma_bf16(o[nt], aph[kk], pl[e0], pl[e1]);
                    mma_bf16(o[nt], apl[kk], ph[e0], ph[e1]);
                }
            }
        }
        __syncthreads();
    }

    float i0 = 1.f / l0, i1 = 1.f / l1;
    long t0 = (long)bn * S_ + qw + (lane >> 2);
    #pragma unroll
    for (int nt = 0; nt < 4; ++nt) {
        int col = h * 32 + nt * 8 + ((lane & 3) << 1);
        float v00 = o[nt][0] * i0, v01 = o[nt][1] * i0;
        float v10 = o[nt][2] * i1, v11 = o[nt][3] * i1;
        uint32_t h01, l01, h23, l23;
        split2(v00, v01, h01, l01);
        split2(v10, v11, h23, l23);
        *(uint32_t*)(g_att2 + t0 * 512 + col)             = h01;
        *(uint32_t*)(g_att2 + t0 * 512 + 256 + col)       = l01;
        *(uint32_t*)(g_att2 + (t0 + 8) * 512 + col)       = h23;
        *(uint32_t*)(g_att2 + (t0 + 8) * 512 + 256 + col) = l23;
    }
}

// ---------------- 6) fused out-proj GEMM + bias + residual + LayerNorm --------
// Block: 64 rows x 256 cols. 8 warps as 2(m) x 4(n), warp tile 32x64.
// K-chunk 32, 4-stage cp.async pipeline (dynamic smem 80KB), SW64. Writes d_out.
#define OPROJ_SMEM (4 * 4096 + 4 * 16384)
__global__ void __launch_bounds__(256) oproj_ln_kernel(
    const float* __restrict__ x,  const float* __restrict__ bo,
    const float* __restrict__ gamma, const float* __restrict__ beta,
    float* __restrict__ out)
{
    extern __shared__ __align__(128) char dsmem[];
    __shared__ float pSum[4][64], pSq[4][64];
    const int tid = threadIdx.x;
    const int wid = tid >> 5, lane = tid & 31;
    const int wm = wid & 1;          // 2 warps along M (32 rows each)
    const int wn = wid >> 1;         // 4 warps along N (64 cols each)
    const int mBase = blockIdx.x * 64;

    const uint32_t baseA = smem_u32(dsmem);            // 4 bufs x 4KB
    const uint32_t baseW = baseA + 16384;              // 4 bufs x 16KB

    float acc[2][8][4];
    #pragma unroll
    for (int i = 0; i < 2; ++i)
        #pragma unroll
        for (int j = 0; j < 8; ++j)
            #pragma unroll
            for (int q = 0; q < 4; ++q) acc[i][j][q] = 0.f;

    auto issue = [&](int s) {
        int buf = s & 3;
        int t = s >> 3, kc = s & 7;
        int aoff = ((t == 2) ? 256 : 0) + kc * 32;
        int woff = ((t == 1) ? 256 : 0) + kc * 32;
        {   // A: 64x32 = 4KB = 256 chunks, 1/thread
            int row = tid >> 2, c = tid & 3;
            uint32_t so = SWZ64((uint32_t)(row * 64 + c * 16));
            cp16(baseA + (uint32_t)(buf * 4096) + so,
                 g_att2 + ((long)(mBase + row)) * 512 + aoff + c * 8);
        }
        #pragma unroll
        for (int i = 0; i < 4; ++i) {  // W: 256x32 = 16KB = 1024 chunks, 4/thread
            int f = i * 256 + tid;
            int row = f >> 2, c = f & 3;
            uint32_t so = SWZ64((uint32_t)(row * 64 + c * 16));
            cp16(baseW + (uint32_t)(buf * 16384) + so,
                 g_wo2 + ((long)row) * 512 + woff + c * 8);
        }
    };

    issue(0); CP_COMMIT();
    issue(1); CP_COMMIT();
    issue(2); CP_COMMIT();

    for (int s = 0; s < 24; ++s) {
        const int buf = s & 3;
        if (s + 3 < 24) { issue(s + 3); CP_COMMIT(); }
        if (s < 21)      { CP_WAIT3(); }
        else if (s == 21) { CP_WAIT2(); }
        else if (s == 22) { CP_WAIT1(); }
        else              { CP_WAIT0(); }
        __syncthreads();

        const uint32_t bA = baseA + buf * 4096;
        const uint32_t bW = baseW + buf * 16384;
        #pragma unroll
        for (int ks = 0; ks < 2; ++ks) {
            uint32_t a[2][4];
            #pragma unroll
            for (int mf = 0; mf < 2; ++mf) {
                uint32_t off = SWZ64((uint32_t)((wm * 32 + mf * 16 + (lane & 15)) * 64
                                                + ks * 32 + (lane >> 4) * 16));
                ldsm_x4(a[mf][0], a[mf][1], a[mf][2], a[mf][3], bA + off);
            }
            uint32_t b[4][4];
            #pragma unroll
            for (int g = 0; g < 4; ++g) {
                uint32_t off = SWZ64((uint32_t)((wn * 64 + g * 16 + (lane >> 4) * 8 + (lane & 7)) * 64
                                                + ks * 32 + ((lane >> 3) & 1) * 16));
                ldsm_x4(b[g][0], b[g][1], b[g][2], b[g][3], bW + off);
            }
            #pragma unroll
            for (int mf = 0; mf < 2; ++mf)
                #pragma unroll
                for (int nf = 0; nf < 8; ++nf) {
                    const uint32_t* bp = b[nf >> 1];
                    if (nf & 1) mma_bf16(acc[mf][nf], a[mf], bp[2], bp[3]);
                    else        mma_bf16(acc[mf][nf], a[mf], bp[0], bp[1]);
                }
        }
        __syncthreads();
    }

    // epilogue: add bias + residual, per-row LN across warps, write d_out
    const int colq = (lane & 3) * 2;
    #pragma unroll
    for (int mf = 0; mf < 2; ++mf) {
        #pragma unroll
        for (int rr = 0; rr < 2; ++rr) {
            int rl = wm * 32 + mf * 16 + rr * 8 + (lane >> 2);   // local row 0..63
            int t = mBase + rl;
            int bnn = t >> 9, ss = t & 511;
            int bb = bnn >> 3, nn = bnn & 7;
            const float* xrow = x + (((long)(bb * S_ + ss)) * N_ + nn) * D_;
            float sum = 0.f, sq = 0.f;
            #pragma unroll
            for (int nf = 0; nf < 8; ++nf) {
                int col = wn * 64 + nf * 8 + colq;
                float2 xv = *(const float2*)(xrow + col);
                float2 bv = *(const float2*)(bo + col);
                float v0 = acc[mf][nf][rr * 2]     + xv.x + bv.x;
                float v1 = acc[mf][nf][rr * 2 + 1] + xv.y + bv.y;
                acc[mf][nf][rr * 2]     = v0;
                acc[mf][nf][rr * 2 + 1] = v1;
                sum += v0 + v1;
                sq = fmaf(v0, v0, sq);
                sq = fmaf(v1, v1, sq);
            }
            sum += __shfl_xor_sync(0xFFFFFFFFu, sum, 1);
            sum += __shfl_xor_sync(0xFFFFFFFFu, sum, 2);
            sq  += __shfl_xor_sync(0xFFFFFFFFu, sq,  1);
            sq  += __shfl_xor_sync(0xFFFFFFFFu, sq,  2);
            if ((lane & 3) == 0) {
                pSum[wn][rl] = sum;
                pSq[wn][rl]  = sq;
            }
        }
    }
    __syncthreads();

    #pragma unroll
    for (int mf = 0; mf < 2; ++mf) {
        #pragma unroll
        for (int rr = 0; rr < 2; ++rr) {
            int rl = wm * 32 + mf * 16 + rr * 8 + (lane >> 2);
            int t = mBase + rl;
            int bnn = t >> 9, ss = t & 511;
            int bb = bnn >> 3, nn = bnn & 7;
            float S  = pSum[0][rl] + pSum[1][rl] + pSum[2][rl] + pSum[3][rl];
            float Q  = pSq[0][rl]  + pSq[1][rl]  + pSq[2][rl]  + pSq[3][rl];
            float mu = S * (1.f / 256.f);
            float var = Q * (1.f / 256.f) - mu * mu;
            float rstd = rsqrtf(var + 1e-5f);
            float* orow = out + (((long)(bb * S_ + ss)) * N_ + nn) * D_;
            #pragma unroll
            for (int nf = 0; nf < 8; ++nf) {
                int col = wn * 64 + nf * 8 + colq;
                float2 gv = *(const float2*)(gamma + col);
                float2 tv = *(const float2*)(beta + col);
                float2 ov;
                ov.x = (acc[mf][nf][rr * 2]     - mu) * rstd * gv.x + tv.x;
                ov.y = (acc[mf][nf][rr * 2 + 1] - mu) * rstd * gv.y + tv.y;
                *(float2*)(orow + col) = ov;
            }
        }
    }
}

// ------------------------------ launch ----------------------------------------
// Input order per metadata (dict insertion order in setup_inputs):
//   0:x 1:Wq 2:Wk 3:Wv 4:Wo 5:bq 6:bk 7:bv 8:bo 9:gamma 10:beta 11:num_heads
extern "C" void kernel_launch(void* const* d_in, const int* in_sizes, int n_in,
                              void* d_out, int out_size) {
    const float* x     = (const float*)d_in[0];
    const float* Wq    = (const float*)d_in[1];
    const float* Wk    = (const float*)d_in[2];
    const float* Wv    = (const float*)d_in[3];
    const float* Wo    = (const float*)d_in[4];
    const float* bq    = (const float*)d_in[5];
    const float* bk    = (const float*)d_in[6];
    const float* bv    = (const float*)d_in[7];
    const float* bo    = (const float*)d_in[8];
    const float* gamma = (const float*)d_in[9];
    const float* beta  = (const float*)d_in[10];
    float* out = (float*)d_out;

    // idempotent; host-side attribute set (not a stream op, graph-capture safe)
    cudaFuncSetAttribute(qkv_gemm_kernel, cudaFuncAttributeMaxDynamicSharedMemorySize, QKV_SMEM);
    cudaFuncSetAttribute(oproj_ln_kernel, cudaFuncAttributeMaxDynamicSharedMemorySize, OPROJ_SMEM);

    pe_kernel<<<256, 256>>>();
    addpe_split_kernel<<<4096, 256>>>(x);
    wsplit_all_kernel<<<1024, 256>>>(Wq, bq, Wk, bk, Wv, bv, Wo);
    qkv_gemm_kernel<<<dim3(6, 128), 256, QKV_SMEM>>>();
    attn_mma_kernel<<<dim3(4, H_, BN_), 256>>>();
    oproj_ln_kernel<<<256, 256, OPROJ_SMEM>>>(x, bo, gamma, beta, out);
}

// round 12
// speedup vs baseline: 1.0462x; 1.0462x over previous
#include <cuda_runtime.h>
#include <cuda_bf16.h>
#include <math.h>
#include <stdint.h>

// Problem constants (fixed by the dataset)
#define B_   4
#define S_   512
#define N_   8
#define D_   256
#define H_   8
#define HD_  32
#define BN_  (B_ * N_)          // 32
#define T_   (BN_ * S_)         // 16384 rows
#define QKVN 768                // 3*D

// ---------------- warp-mma helpers (baseline PTX, sm_80+) ---------------------
__device__ __forceinline__ uint32_t smem_u32(const void* p) {
    uint32_t a;
    asm("{ .reg .u64 t; cvta.to.shared.u64 t, %1; cvt.u32.u64 %0, t; }" : "=r"(a) : "l"(p));
    return a;
}
__device__ __forceinline__ void ldsm_x4(uint32_t& r0, uint32_t& r1, uint32_t& r2, uint32_t& r3,
                                        uint32_t addr) {
    asm volatile("ldmatrix.sync.aligned.m8n8.x4.shared.b16 {%0,%1,%2,%3}, [%4];"
        : "=r"(r0), "=r"(r1), "=r"(r2), "=r"(r3) : "r"(addr));
}
__device__ __forceinline__ void mma_bf16(float* c, const uint32_t* a, uint32_t b0, uint32_t b1) {
    asm volatile(
        "mma.sync.aligned.m16n8k16.row.col.f32.bf16.bf16.f32 "
        "{%0,%1,%2,%3}, {%4,%5,%6,%7}, {%8,%9}, {%0,%1,%2,%3};"
        : "+f"(c[0]), "+f"(c[1]), "+f"(c[2]), "+f"(c[3])
        : "r"(a[0]), "r"(a[1]), "r"(a[2]), "r"(a[3]), "r"(b0), "r"(b1));
}
__device__ __forceinline__ uint32_t bf16x2pack(float v0, float v1) {
    uint32_t r;
    asm("cvt.rn.bf16x2.f32 %0, %1, %2;" : "=r"(r) : "f"(v1), "f"(v0));
    return r;
}
__device__ __forceinline__ void split2(float v0, float v1, uint32_t& hi, uint32_t& lo) {
    hi = bf16x2pack(v0, v1);
    float h0 = __uint_as_float(hi << 16);
    float h1 = __uint_as_float(hi & 0xFFFF0000u);
    lo = bf16x2pack(v0 - h0, v1 - h1);
}
__device__ __forceinline__ void cp16(uint32_t dst, const void* src) {
    asm volatile("cp.async.cg.shared.global [%0], [%1], 16;" :: "r"(dst), "l"(src));
}
#define CP_COMMIT() asm volatile("cp.async.commit_group;" ::: "memory")
#define CP_WAIT2()  asm volatile("cp.async.wait_group 2;" ::: "memory")
#define CP_WAIT1()  asm volatile("cp.async.wait_group 1;" ::: "memory")
#define CP_WAIT0()  asm volatile("cp.async.wait_group 0;" ::: "memory")
#define SWZ128(off) ((off) ^ (((off) >> 3) & 0x70))
// SW64 for 64-byte-pitch rows: XOR 16B-column bits [5:4] with row bits [2:1].
#define SWZ64(off)  ((off) ^ (((off) >> 3) & 0x30))

// ---------------- scratch (device globals; no runtime allocation) -------------
__device__ float g_pe[S_ * D_];
__device__ __nv_bfloat16 g_a2[(long)T_ * 512];         // [hi(256)|lo(256)] per row
__device__ __nv_bfloat16 g_w2[QKVN * 512];
__device__ __nv_bfloat16 g_wo2[D_ * 512];
__device__ float g_bcat[QKVN];
__device__ __nv_bfloat16 g_qh[(long)BN_ * H_ * S_ * HD_];   // [bnh][s][e] Q*scale hi
__device__ __nv_bfloat16 g_ql[(long)BN_ * H_ * S_ * HD_];
__device__ __nv_bfloat16 g_kh[(long)BN_ * H_ * S_ * HD_];
__device__ __nv_bfloat16 g_kl[(long)BN_ * H_ * S_ * HD_];
__device__ __nv_bfloat16 g_vth[(long)BN_ * H_ * HD_ * S_];  // [bnh][e][s]  V^T
__device__ __nv_bfloat16 g_vtl[(long)BN_ * H_ * HD_ * S_];
__device__ __nv_bfloat16 g_att2[(long)T_ * 512];

// ---------------- 1) positional encoding table -------------------------------
__global__ void pe_kernel() {
    int idx = blockIdx.x * 256 + threadIdx.x;       // 65536 = S * D/2
    int s = idx >> 7;
    int i = idx & 127;
    float div = expf((float)(2 * i) * (-0.035977892078031970f)); // -ln(10000)/256
    float sn, cs;
    sincosf((float)s * div, &sn, &cs);
    g_pe[s * D_ + 2 * i]     = sn;
    g_pe[s * D_ + 2 * i + 1] = cs;
}

// ---------------- 2) x + pe -> bf16 hi/lo split, (B,S,N,D)->(BN,S,D) ----------
__global__ void addpe_split_kernel(const float* __restrict__ x) {
    int idx = blockIdx.x * 256 + threadIdx.x;       // 1,048,576 groups of 4
    int d4 = idx & 63;
    int s  = (idx >> 6) & 511;
    int bn = idx >> 15;
    int b = bn >> 3, n = bn & 7;
    const float4 xv = *(const float4*)(x + ((((long)b * S_ + s) * N_ + n) * D_ + d4 * 4));
    const float4 pv = *(const float4*)(g_pe + (s * D_ + d4 * 4));
    float v[4] = {xv.x + pv.x, xv.y + pv.y, xv.z + pv.z, xv.w + pv.w};
    long t = (long)bn * S_ + s;
    __nv_bfloat16* hb = g_a2 + t * 512 + d4 * 4;
    uint32_t h01, l01, h23, l23;
    split2(v[0], v[1], h01, l01);
    split2(v[2], v[3], h23, l23);
    ((uint32_t*)hb)[0] = h01;
    ((uint32_t*)hb)[1] = h23;
    ((uint32_t*)(hb + 256))[0] = l01;
    ((uint32_t*)(hb + 256))[1] = l23;
}

// ---------------- 3) all weights: concat + hi/lo split (one launch) -----------
__global__ void wsplit_all_kernel(const float* __restrict__ Wq, const float* __restrict__ bq,
                                  const float* __restrict__ Wk, const float* __restrict__ bk,
                                  const float* __restrict__ Wv, const float* __restrict__ bv,
                                  const float* __restrict__ Wo) {
    int idx = blockIdx.x * 256 + threadIdx.x;       // 262144 = 1024 rows * 256
    int j = idx >> 8, k = idx & 255;
    int jj = j & 255;
    if (j < 768) {
        const float* src; const float* bsrc;
        if (j < 256)      { src = Wq; bsrc = bq; }
        else if (j < 512) { src = Wk; bsrc = bk; }
        else              { src = Wv; bsrc = bv; }
        float v = src[jj * D_ + k];
        __nv_bfloat16 h = __float2bfloat16(v);
        g_w2[j * 512 + k]       = h;
        g_w2[j * 512 + 256 + k] = __float2bfloat16(v - __bfloat162float(h));
        if (k == 0) g_bcat[j] = bsrc[jj];
    } else {
        float v = Wo[jj * D_ + k];
        __nv_bfloat16 h = __float2bfloat16(v);
        g_wo2[jj * 512 + k]       = h;
        g_wo2[jj * 512 + 256 + k] = __float2bfloat16(v - __bfloat162float(h));
    }
}

// ---------------- 4) qkv GEMM: 4-stage multistage (1 barrier/stage) + SW64 ----
// C[16384,768]. Block 128x128, K-chunk 32, dynamic smem 64KB.
// Epilogue writes split bf16 Q(scaled)/K and transposed V.
#define QKV_SMEM (4 * 8192 * 2)
__global__ void __launch_bounds__(256) qkv_gemm_kernel() {
    extern __shared__ __align__(128) char dsmem[];
    const int tid = threadIdx.x;
    const int wid = tid >> 5, lane = tid & 31;
    const int wm = wid & 3;          // 4 warps along M
    const int wn = wid >> 2;         // 2 warps along N
    const int mBase = blockIdx.y * 128;
    const int nBase = blockIdx.x * 128;

    const uint32_t baseA = smem_u32(dsmem);            // 4 bufs x 8KB
    const uint32_t baseW = baseA + 32768;              // 4 bufs x 8KB

    float acc[2][8][4];
    #pragma unroll
    for (int i = 0; i < 2; ++i)
        #pragma unroll
        for (int j = 0; j < 8; ++j)
            #pragma unroll
            for (int q = 0; q < 4; ++q) acc[i][j][q] = 0.f;

    auto issue = [&](int s) {
        int buf = s & 3;
        int t = s >> 3, kc = s & 7;
        int aoff = ((t == 2) ? 256 : 0) + kc * 32;
        int woff = ((t == 1) ? 256 : 0) + kc * 32;
        #pragma unroll
        for (int i = 0; i < 2; ++i) {
            int f = i * 256 + tid;
            int row = f >> 2, c = f & 3;
            uint32_t so = SWZ64((uint32_t)(row * 64 + c * 16));
            cp16(baseA + (uint32_t)(buf * 8192) + so,
                 g_a2 + ((long)(mBase + row)) * 512 + aoff + c * 8);
            cp16(baseW + (uint32_t)(buf * 8192) + so,
                 g_w2 + ((long)(nBase + row)) * 512 + woff + c * 8);
        }
    };

    issue(0); CP_COMMIT();
    issue(1); CP_COMMIT();
    issue(2); CP_COMMIT();

    for (int s = 0; s < 24; ++s) {
        // ensure group s is complete (oldest pending); tail drains precisely
        if (s <= 21)      { CP_WAIT2(); }
        else if (s == 22) { CP_WAIT1(); }
        else              { CP_WAIT0(); }
        __syncthreads();   // single barrier per stage: data visible + skew bound

        const int buf = s & 3;
        const uint32_t bA = baseA + buf * 8192;
        const uint32_t bW = baseW + buf * 8192;
        #pragma unroll
        for (int ks = 0; ks < 2; ++ks) {
            uint32_t a[2][4];
            #pragma unroll
            for (int mf = 0; mf < 2; ++mf) {
                uint32_t off = SWZ64((uint32_t)((wm * 32 + mf * 16 + (lane & 15)) * 64
                                                + ks * 32 + (lane >> 4) * 16));
                ldsm_x4(a[mf][0], a[mf][1], a[mf][2], a[mf][3], bA + off);
            }
            uint32_t b[4][4];
            #pragma unroll
            for (int g = 0; g < 4; ++g) {
                uint32_t off = SWZ64((uint32_t)((wn * 64 + g * 16 + (lane >> 4) * 8 + (lane & 7)) * 64
                                                + ks * 32 + ((lane >> 3) & 1) * 16));
                ldsm_x4(b[g][0], b[g][1], b[g][2], b[g][3], bW + off);
            }
            #pragma unroll
            for (int mf = 0; mf < 2; ++mf)
                #pragma unroll
                for (int nf = 0; nf < 8; ++nf) {
                    const uint32_t* bp = b[nf >> 1];
                    if (nf & 1) mma_bf16(acc[mf][nf], a[mf], bp[2], bp[3]);
                    else        mma_bf16(acc[mf][nf], a[mf], bp[0], bp[1]);
                }
        }
        if (s + 3 < 24) { issue(s + 3); CP_COMMIT(); }   // overlapped with next wait
    }

    // epilogue: route to split Q (scaled) / K / V^T
    const int colq = (lane & 3) * 2;
    const float qscale = 0.17677669529663687f;   // 1/sqrt(32)
    #pragma unroll
    for (int mf = 0; mf < 2; ++mf) {
        int r0 = mBase + wm * 32 + mf * 16 + (lane >> 2);
        #pragma unroll
        for (int nf = 0; nf < 8; ++nf) {
            int col = nBase + wn * 64 + nf * 8 + colq;
            float bx = g_bcat[col], by = g_bcat[col + 1];
            float v00 = acc[mf][nf][0] + bx, v01 = acc[mf][nf][1] + by;   // row r0
            float v10 = acc[mf][nf][2] + bx, v11 = acc[mf][nf][3] + by;   // row r0+8
            int type = col >> 8, d = col & 255, hh = d >> 5, e = d & 31;
            if (type == 0) { v00 *= qscale; v01 *= qscale; v10 *= qscale; v11 *= qscale; }
            uint32_t h01, l01, h23, l23;
            split2(v00, v01, h01, l01);
            split2(v10, v11, h23, l23);
            int bnh0 = ((r0 >> 9) * H_ + hh);
            int s0 = r0 & 511;
            if (type < 2) {
                __nv_bfloat16* dh = type ? g_kh : g_qh;
                __nv_bfloat16* dl = type ? g_kl : g_ql;
                long a0 = ((long)bnh0 * S_ + s0) * HD_ + e;
                *(uint32_t*)(dh + a0)            = h01;
                *(uint32_t*)(dl + a0)            = l01;
                *(uint32_t*)(dh + a0 + 8 * HD_)  = h23;
                *(uint32_t*)(dl + a0 + 8 * HD_)  = l23;
            } else {
                long vb = ((long)bnh0 * HD_ + e) * S_ + s0;
                unsigned short* vh = (unsigned short*)g_vth;
                unsigned short* vl = (unsigned short*)g_vtl;
                vh[vb]           = (unsigned short)(h01 & 0xFFFF);
                vh[vb + S_]      = (unsigned short)(h01 >> 16);
                vh[vb + 8]       = (unsigned short)(h23 & 0xFFFF);
                vh[vb + S_ + 8]  = (unsigned short)(h23 >> 16);
                vl[vb]           = (unsigned short)(l01 & 0xFFFF);
                vl[vb + S_]      = (unsigned short)(l01 >> 16);
                vl[vb + 8]       = (unsigned short)(l23 & 0xFFFF);
                vl[vb + S_ + 8]  = (unsigned short)(l23 >> 16);
            }
        }
    }
}

// ---------------- 5) causal flash attention (tensor cores, bf16 split) --------
__global__ void __launch_bounds__(256) attn_mma_kernel() {
    __shared__ __align__(128)  __nv_bfloat16 sQh[128 * 40];
    __shared__ __align__(128)  __nv_bfloat16 sQl[128 * 40];
    __shared__ __align__(128)  __nv_bfloat16 sKh[64 * 40];
    __shared__ __align__(128)  __nv_bfloat16 sKl[64 * 40];
    __shared__ __align__(1024) __nv_bfloat16 sVh[32 * 64];
    __shared__ __align__(1024) __nv_bfloat16 sVl[32 * 64];
    const int tid = threadIdx.x, wid = tid >> 5, lane = tid & 31;
    const int qBase = blockIdx.x * 128;
    const int h = blockIdx.y, bn = blockIdx.z;
    const int bnh = bn * H_ + h;
    const int qw = qBase + wid * 16;
    const long kvoff = (long)bnh * S_ * HD_;
    const __nv_bfloat16* qhg = g_qh + kvoff;
    const __nv_bfloat16* qlg = g_ql + kvoff;
    const __nv_bfloat16* khg = g_kh + kvoff;
    const __nv_bfloat16* klg = g_kl + kvoff;
    const __nv_bfloat16* vhg = g_vth + kvoff;
    const __nv_bfloat16* vlg = g_vtl + kvoff;

    #pragma unroll
    for (int i = 0; i < 2; ++i) {
        int f = i * 256 + tid, row = f >> 2, c = f & 3;
        *(float4*)((char*)sQh + row * 80 + c * 16) = *(const float4*)(qhg + (long)(qBase + row) * 32 + c * 8);
        *(float4*)((char*)sQl + row * 80 + c * 16) = *(const float4*)(qlg + (long)(qBase + row) * 32 + c * 8);
    }
    __syncthreads();

    const uint32_t bQh = smem_u32(sQh), bQl = smem_u32(sQl);
    const uint32_t bKh = smem_u32(sKh), bKl = smem_u32(sKl);
    const uint32_t bVh = smem_u32(sVh), bVl = smem_u32(sVl);

    uint32_t qfh[2][4], qfl[2][4];
    #pragma unroll
    for (int ks = 0; ks < 2; ++ks) {
        uint32_t off = (uint32_t)((wid * 16 + (lane & 15)) * 80 + ks * 32 + (lane >> 4) * 16);
        ldsm_x4(qfh[ks][0], qfh[ks][1], qfh[ks][2], qfh[ks][3], bQh + off);
        ldsm_x4(qfl[ks][0], qfl[ks][1], qfl[ks][2], qfl[ks][3], bQl + off);
    }

    float o[4][4];
    #pragma unroll
    for (int i = 0; i < 4; ++i)
        #pragma unroll
        for (int j = 0; j < 4; ++j) o[i][j] = 0.f;
    float m0 = -1e30f, m1 = -1e30f, l0 = 0.f, l1 = 0.f;

    const int nkt_w = (qw >> 6) + 1;
    const int nkt_b = (qBase >> 6) + 2;

    for (int kt = 0; kt < nkt_b; ++kt) {
        {
            int row = tid >> 2, c = tid & 3;
            *(float4*)((char*)sKh + row * 80 + c * 16) = *(const float4*)(khg + (long)(kt * 64 + row) * 32 + c * 8);
            *(float4*)((char*)sKl + row * 80 + c * 16) = *(const float4*)(klg + (long)(kt * 64 + row) * 32 + c * 8);
            int vr = tid >> 3, vc = tid & 7;
            uint32_t so = SWZ128((uint32_t)(vr * 128 + vc * 16));
            *(float4*)((char*)sVh + so) = *(const float4*)(vhg + (long)vr * S_ + kt * 64 + vc * 8);
            *(float4*)((char*)sVl + so) = *(const float4*)(vlg + (long)vr * S_ + kt * 64 + vc * 8);
        }
        __syncthreads();

        if (kt < nkt_w) {
            float s[8][4];
            #pragma unroll
            for (int nt = 0; nt < 8; ++nt)
                #pragma unroll
                for (int j = 0; j < 4; ++j) s[nt][j] = 0.f;

            #pragma unroll
            for (int ks = 0; ks < 2; ++ks) {
                uint32_t bh[4][4], bl[4][4];
                #pragma unroll
                for (int g = 0; g < 4; ++g) {
                    uint32_t off = (uint32_t)((g * 16 + (lane >> 4) * 8 + (lane & 7)) * 80
                                              + ks * 32 + ((lane >> 3) & 1) * 16);
                    ldsm_x4(bh[g][0], bh[g][1], bh[g][2], bh[g][3], bKh + off);
                    ldsm_x4(bl[g][0], bl[g][1], bl[g][2], bl[g][3], bKl + off);
                }
                #pragma unroll
                for (int nt = 0; nt < 8; ++nt) {
                    const uint32_t* ph = bh[nt >> 1];
                    const uint32_t* pl = bl[nt >> 1];
                    int e0 = (nt & 1) * 2, e1 = e0 + 1;
                    mma_bf16(s[nt], qfh[ks], ph[e0], ph[e1]);
                    mma_bf16(s[nt], qfh[ks], pl[e0], pl[e1]);
                    mma_bf16(s[nt], qfl[ks], ph[e0], ph[e1]);
                }
            }

            if (kt == (qw >> 6)) {
                int q0 = qw + (lane >> 2), q1 = q0 + 8;
                #pragma unroll
                for (int nt = 0; nt < 8; ++nt) {
                    int k0 = kt * 64 + nt * 8 + ((lane & 3) << 1);
                    if (k0 > q0)     s[nt][0] = -1e9f;
                    if (k0 + 1 > q0) s[nt][1] = -1e9f;
                    if (k0 > q1)     s[nt][2] = -1e9f;
                    if (k0 + 1 > q1) s[nt][3] = -1e9f;
                }
            }

            float mx0 = -1e30f, mx1 = -1e30f;
            #pragma unroll
            for (int nt = 0; nt < 8; ++nt) {
                mx0 = fmaxf(mx0, fmaxf(s[nt][0], s[nt][1]));
                mx1 = fmaxf(mx1, fmaxf(s[nt][2], s[nt][3]));
            }
            mx0 = fmaxf(mx0, __shfl_xor_sync(0xFFFFFFFFu, mx0, 1));
            mx0 = fmaxf(mx0, __shfl_xor_sync(0xFFFFFFFFu, mx0, 2));
            mx1 = fmaxf(mx1, __shfl_xor_sync(0xFFFFFFFFu, mx1, 1));
            mx1 = fmaxf(mx1, __shfl_xor_sync(0xFFFFFFFFu, mx1, 2));
            float nm0 = fmaxf(m0, mx0), nm1 = fmaxf(m1, mx1);
            float a0 = __expf(m0 - nm0), a1 = __expf(m1 - nm1);
            m0 = nm0; m1 = nm1;

            float sum0 = 0.f, sum1 = 0.f;
            uint32_t aph[4][4], apl[4][4];
            #pragma unroll
            for (int nt = 0; nt < 8; ++nt) {
                float p0 = __expf(s[nt][0] - m0), p1 = __expf(s[nt][1] - m0);
                float p2 = __expf(s[nt][2] - m1), p3 = __expf(s[nt][3] - m1);
                sum0 += p0 + p1; sum1 += p2 + p3;
                uint32_t h01, l01, h23, l23;
                split2(p0, p1, h01, l01);
                split2(p2, p3, h23, l23);
                int kk = nt >> 1, r = (nt & 1) * 2;
                aph[kk][r]     = h01;
                aph[kk][r + 1] = h23;
                apl[kk][r]     = l01;
                apl[kk][r + 1] = l23;
            }
            sum0 += __shfl_xor_sync(0xFFFFFFFFu, sum0, 1);
            sum0 += __shfl_xor_sync(0xFFFFFFFFu, sum0, 2);
            sum1 += __shfl_xor_sync(0xFFFFFFFFu, sum1, 1);
            sum1 += __shfl_xor_sync(0xFFFFFFFFu, sum1, 2);
            l0 = l0 * a0 + sum0;
            l1 = l1 * a1 + sum1;
            #pragma unroll
            for (int nt = 0; nt < 4; ++nt) {
                o[nt][0] *= a0; o[nt][1] *= a0;
                o[nt][2] *= a1; o[nt][3] *= a1;
            }

            #pragma unroll
            for (int kk = 0; kk < 4; ++kk) {
                uint32_t vh[2][4], vl[2][4];
                #pragma unroll
                for (int g = 0; g < 2; ++g) {
                    uint32_t off = SWZ128((uint32_t)((g * 16 + (lane >> 4) * 8 + (lane & 7)) * 128
                                                     + kk * 32 + ((lane >> 3) & 1) * 16));
                    ldsm_x4(vh[g][0], vh[g][1], vh[g][2], vh[g][3], bVh + off);
                    ldsm_x4(vl[g][0], vl[g][1], vl[g][2], vl[g][3], bVl + off);
                }
                #pragma unroll
                for (int nt = 0; nt < 4; ++nt) {
                    const uint32_t* ph = vh[nt >> 1];
                    const uint32_t* pl = vl[nt >> 1];
                    int e0 = (nt & 1) * 2, e1 = e0 + 1;
                    mma_bf16(o[nt], aph[kk], ph[e0], ph[e1]);
                    mma_bf16(o[nt], aph[kk], pl[e0], pl[e1]);
                    mma_bf16(o[nt], apl[kk], ph[e0], ph[e1]);
                }
            }
        }
        __syncthreads();
    }

    float i0 = 1.f / l0, i1 = 1.f / l1;
    long t0 = (long)bn * S_ + qw + (lane >> 2);
    #pragma unroll
    for (int nt = 0; nt < 4; ++nt) {
        int col = h * 32 + nt * 8 + ((lane & 3) << 1);
        float v00 = o[nt][0] * i0, v01 = o[nt][1] * i0;
        float v10 = o[nt][2] * i1, v11 = o[nt][3] * i1;
        uint32_t h01, l01, h23, l23;
        split2(v00, v01, h01, l01);
        split2(v10, v11, h23, l23);
        *(uint32_t*)(g_att2 + t0 * 512 + col)             = h01;
        *(uint32_t*)(g_att2 + t0 * 512 + 256 + col)       = l01;
        *(uint32_t*)(g_att2 + (t0 + 8) * 512 + col)       = h23;
        *(uint32_t*)(g_att2 + (t0 + 8) * 512 + 256 + col) = l23;
    }
}

// ---------------- 6) fused out-proj GEMM + bias + residual + LayerNorm --------
// Block: 64 rows x 256 cols. 8 warps as 2(m) x 4(n), warp tile 32x64.
// K-chunk 32, 4-stage multistage (1 barrier/stage), SW64. Writes d_out.
#define OPROJ_SMEM (4 * 4096 + 4 * 16384)
__global__ void __launch_bounds__(256) oproj_ln_kernel(
    const float* __restrict__ x,  const float* __restrict__ bo,
    const float* __restrict__ gamma, const float* __restrict__ beta,
    float* __restrict__ out)
{
    extern __shared__ __align__(128) char dsmem[];
    __shared__ float pSum[4][64], pSq[4][64];
    const int tid = threadIdx.x;
    const int wid = tid >> 5, lane = tid & 31;
    const int wm = wid & 1;          // 2 warps along M (32 rows each)
    const int wn = wid >> 1;         // 4 warps along N (64 cols each)
    const int mBase = blockIdx.x * 64;

    const uint32_t baseA = smem_u32(dsmem);            // 4 bufs x 4KB
    const uint32_t baseW = baseA + 16384;              // 4 bufs x 16KB

    float acc[2][8][4];
    #pragma unroll
    for (int i = 0; i < 2; ++i)
        #pragma unroll
        for (int j = 0; j < 8; ++j)
            #pragma unroll
            for (int q = 0; q < 4; ++q) acc[i][j][q] = 0.f;

    auto issue = [&](int s) {
        int buf = s & 3;
        int t = s >> 3, kc = s & 7;
        int aoff = ((t == 2) ? 256 : 0) + kc * 32;
        int woff = ((t == 1) ? 256 : 0) + kc * 32;
        {   // A: 64x32 = 4KB = 256 chunks, 1/thread
            int row = tid >> 2, c = tid & 3;
            uint32_t so = SWZ64((uint32_t)(row * 64 + c * 16));
            cp16(baseA + (uint32_t)(buf * 4096) + so,
                 g_att2 + ((long)(mBase + row)) * 512 + aoff + c * 8);
        }
        #pragma unroll
        for (int i = 0; i < 4; ++i) {  // W: 256x32 = 16KB = 1024 chunks, 4/thread
            int f = i * 256 + tid;
            int row = f >> 2, c = f & 3;
            uint32_t so = SWZ64((uint32_t)(row * 64 + c * 16));
            cp16(baseW + (uint32_t)(buf * 16384) + so,
                 g_wo2 + ((long)row) * 512 + woff + c * 8);
        }
    };

    issue(0); CP_COMMIT();
    issue(1); CP_COMMIT();
    issue(2); CP_COMMIT();

    for (int s = 0; s < 24; ++s) {
        if (s <= 21)      { CP_WAIT2(); }
        else if (s == 22) { CP_WAIT1(); }
        else              { CP_WAIT0(); }
        __syncthreads();

        const int buf = s & 3;
        const uint32_t bA = baseA + buf * 4096;
        const uint32_t bW = baseW + buf * 16384;
        #pragma unroll
        for (int ks = 0; ks < 2; ++ks) {
            uint32_t a[2][4];
            #pragma unroll
            for (int mf = 0; mf < 2; ++mf) {
                uint32_t off = SWZ64((uint32_t)((wm * 32 + mf * 16 + (lane & 15)) * 64
                                                + ks * 32 + (lane >> 4) * 16));
                ldsm_x4(a[mf][0], a[mf][1], a[mf][2], a[mf][3], bA + off);
            }
            uint32_t b[4][4];
            #pragma unroll
            for (int g = 0; g < 4; ++g) {
                uint32_t off = SWZ64((uint32_t)((wn * 64 + g * 16 + (lane >> 4) * 8 + (lane & 7)) * 64
                                                + ks * 32 + ((lane >> 3) & 1) * 16));
                ldsm_x4(b[g][0], b[g][1], b[g][2], b[g][3], bW + off);
            }
            #pragma unroll
            for (int mf = 0; mf < 2; ++mf)
                #pragma unroll
                for (int nf = 0; nf < 8; ++nf) {
                    const uint32_t* bp = b[nf >> 1];
                    if (nf & 1) mma_bf16(acc[mf][nf], a[mf], bp[2], bp[3]);
                    else        mma_bf16(acc[mf][nf], a[mf], bp[0], bp[1]);
                }
        }
        if (s + 3 < 24) { issue(s + 3); CP_COMMIT(); }
    }
    __syncthreads();

    // epilogue: add bias + residual, per-row LN across warps, write d_out
    const int colq = (lane & 3) * 2;
    #pragma unroll
    for (int mf = 0; mf < 2; ++mf) {
        #pragma unroll
        for (int rr = 0; rr < 2; ++rr) {
            int rl = wm * 32 + mf * 16 + rr * 8 + (lane >> 2);   // local row 0..63
            int t = mBase + rl;
            int bnn = t >> 9, ss = t & 511;
            int bb = bnn >> 3, nn = bnn & 7;
            const float* xrow = x + (((long)(bb * S_ + ss)) * N_ + nn) * D_;
            float sum = 0.f, sq = 0.f;
            #pragma unroll
            for (int nf = 0; nf < 8; ++nf) {
                int col = wn * 64 + nf * 8 + colq;
                float2 xv = *(const float2*)(xrow + col);
                float2 bv = *(const float2*)(bo + col);
                float v0 = acc[mf][nf][rr * 2]     + xv.x + bv.x;
                float v1 = acc[mf][nf][rr * 2 + 1] + xv.y + bv.y;
                acc[mf][nf][rr * 2]     = v0;
                acc[mf][nf][rr * 2 + 1] = v1;
                sum += v0 + v1;
                sq = fmaf(v0, v0, sq);
                sq = fmaf(v1, v1, sq);
            }
            sum += __shfl_xor_sync(0xFFFFFFFFu, sum, 1);
            sum += __shfl_xor_sync(0xFFFFFFFFu, sum, 2);
            sq  += __shfl_xor_sync(0xFFFFFFFFu, sq,  1);
            sq  += __shfl_xor_sync(0xFFFFFFFFu, sq,  2);
            if ((lane & 3) == 0) {
                pSum[wn][rl] = sum;
                pSq[wn][rl]  = sq;
            }
        }
    }
    __syncthreads();

    #pragma unroll
    for (int mf = 0; mf < 2; ++mf) {
        #pragma unroll
        for (int rr = 0; rr < 2; ++rr) {
            int rl = wm * 32 + mf * 16 + rr * 8 + (lane >> 2);
            int t = mBase + rl;
            int bnn = t >> 9, ss = t & 511;
            int bb = bnn >> 3, nn = bnn & 7;
            float S  = pSum[0][rl] + pSum[1][rl] + pSum[2][rl] + pSum[3][rl];
            float Q  = pSq[0][rl]  + pSq[1][rl]  + pSq[2][rl]  + pSq[3][rl];
            float mu = S * (1.f / 256.f);
            float var = Q * (1.f / 256.f) - mu * mu;
            float rstd = rsqrtf(var + 1e-5f);
            float* orow = out + (((long)(bb * S_ + ss)) * N_ + nn) * D_;
            #pragma unroll
            for (int nf = 0; nf < 8; ++nf) {
                int col = wn * 64 + nf * 8 + colq;
                float2 gv = *(const float2*)(gamma + col);
                float2 tv = *(const float2*)(beta + col);
                float2 ov;
                ov.x = (acc[mf][nf][rr * 2]     - mu) * rstd * gv.x + tv.x;
                ov.y = (acc[mf][nf][rr * 2 + 1] - mu) * rstd * gv.y + tv.y;
                *(float2*)(orow + col) = ov;
            }
        }
    }
}

// ------------------------------ launch ----------------------------------------
// Input order per metadata (dict insertion order in setup_inputs):
//   0:x 1:Wq 2:Wk 3:Wv 4:Wo 5:bq 6:bk 7:bv 8:bo 9:gamma 10:beta 11:num_heads
extern "C" void kernel_launch(void* const* d_in, const int* in_sizes, int n_in,
                              void* d_out, int out_size) {
    const float* x     = (const float*)d_in[0];
    const float* Wq    = (const float*)d_in[1];
    const float* Wk    = (const float*)d_in[2];
    const float* Wv    = (const float*)d_in[3];
    const float* Wo    = (const float*)d_in[4];
    const float* bq    = (const float*)d_in[5];
    const float* bk    = (const float*)d_in[6];
    const float* bv    = (const float*)d_in[7];
    const float* bo    = (const float*)d_in[8];
    const float* gamma = (const float*)d_in[9];
    const float* beta  = (const float*)d_in[10];
    float* out = (float*)d_out;

    // idempotent; host-side attribute set (not a stream op, graph-capture safe)
    cudaFuncSetAttribute(qkv_gemm_kernel, cudaFuncAttributeMaxDynamicSharedMemorySize, QKV_SMEM);
    cudaFuncSetAttribute(oproj_ln_kernel, cudaFuncAttributeMaxDynamicSharedMemorySize, OPROJ_SMEM);

    pe_kernel<<<256, 256>>>();
    addpe_split_kernel<<<4096, 256>>>(x);
    wsplit_all_kernel<<<1024, 256>>>(Wq, bq, Wk, bk, Wv, bv, Wo);
    qkv_gemm_kernel<<<dim3(6, 128), 256, QKV_SMEM>>>();
    attn_mma_kernel<<<dim3(4, H_, BN_), 256>>>();
    oproj_ln_kernel<<<256, 256, OPROJ_SMEM>>>(x, bo, gamma, beta, out);
}

// round 13
// speedup vs baseline: 1.0625x; 1.0156x over previous
#include <cuda_runtime.h>
#include <cuda_bf16.h>
#include <math.h>
#include <stdint.h>

// Problem constants (fixed by the dataset)
#define B_   4
#define S_   512
#define N_   8
#define D_   256
#define H_   8
#define HD_  32
#define BN_  (B_ * N_)          // 32
#define T_   (BN_ * S_)         // 16384 rows
#define QKVN 768                // 3*D

// ---------------- warp-mma helpers (baseline PTX, sm_80+) ---------------------
__device__ __forceinline__ uint32_t smem_u32(const void* p) {
    uint32_t a;
    asm("{ .reg .u64 t; cvta.to.shared.u64 t, %1; cvt.u32.u64 %0, t; }" : "=r"(a) : "l"(p));
    return a;
}
__device__ __forceinline__ void ldsm_x4(uint32_t& r0, uint32_t& r1, uint32_t& r2, uint32_t& r3,
                                        uint32_t addr) {
    asm volatile("ldmatrix.sync.aligned.m8n8.x4.shared.b16 {%0,%1,%2,%3}, [%4];"
        : "=r"(r0), "=r"(r1), "=r"(r2), "=r"(r3) : "r"(addr));
}
__device__ __forceinline__ void mma_bf16(float* c, const uint32_t* a, uint32_t b0, uint32_t b1) {
    asm volatile(
        "mma.sync.aligned.m16n8k16.row.col.f32.bf16.bf16.f32 "
        "{%0,%1,%2,%3}, {%4,%5,%6,%7}, {%8,%9}, {%0,%1,%2,%3};"
        : "+f"(c[0]), "+f"(c[1]), "+f"(c[2]), "+f"(c[3])
        : "r"(a[0]), "r"(a[1]), "r"(a[2]), "r"(a[3]), "r"(b0), "r"(b1));
}
__device__ __forceinline__ uint32_t bf16x2pack(float v0, float v1) {
    uint32_t r;
    asm("cvt.rn.bf16x2.f32 %0, %1, %2;" : "=r"(r) : "f"(v1), "f"(v0));
    return r;
}
__device__ __forceinline__ void split2(float v0, float v1, uint32_t& hi, uint32_t& lo) {
    hi = bf16x2pack(v0, v1);
    float h0 = __uint_as_float(hi << 16);
    float h1 = __uint_as_float(hi & 0xFFFF0000u);
    lo = bf16x2pack(v0 - h0, v1 - h1);
}
__device__ __forceinline__ void cp16(uint32_t dst, const void* src) {
    asm volatile("cp.async.cg.shared.global [%0], [%1], 16;" :: "r"(dst), "l"(src));
}
#define CP_COMMIT() asm volatile("cp.async.commit_group;" ::: "memory")
#define CP_WAIT2()  asm volatile("cp.async.wait_group 2;" ::: "memory")
#define CP_WAIT1()  asm volatile("cp.async.wait_group 1;" ::: "memory")
#define CP_WAIT0()  asm volatile("cp.async.wait_group 0;" ::: "memory")
#define SWZ128(off) ((off) ^ (((off) >> 3) & 0x70))
// SW64 for 64-byte-pitch rows: XOR 16B-column bits [5:4] with row bits [2:1].
#define SWZ64(off)  ((off) ^ (((off) >> 3) & 0x30))

// ---------------- scratch (device globals; no runtime allocation) -------------
__device__ float g_pe[S_ * D_];
__device__ __nv_bfloat16 g_a2[(long)T_ * 512];         // [hi(256)|lo(256)] per row
__device__ __nv_bfloat16 g_w2[QKVN * 512];
__device__ __nv_bfloat16 g_wo2[D_ * 512];
__device__ float g_bcat[QKVN];
__device__ __nv_bfloat16 g_qh[(long)BN_ * H_ * S_ * HD_];   // [bnh][s][e] Q*scale hi
__device__ __nv_bfloat16 g_ql[(long)BN_ * H_ * S_ * HD_];
__device__ __nv_bfloat16 g_kh[(long)BN_ * H_ * S_ * HD_];
__device__ __nv_bfloat16 g_kl[(long)BN_ * H_ * S_ * HD_];
__device__ __nv_bfloat16 g_vth[(long)BN_ * H_ * HD_ * S_];  // [bnh][e][s]  V^T
__device__ __nv_bfloat16 g_vtl[(long)BN_ * H_ * HD_ * S_];
__device__ __nv_bfloat16 g_att2[(long)T_ * 512];

// ---------------- 1) positional encoding table -------------------------------
__global__ void pe_kernel() {
    int idx = blockIdx.x * 256 + threadIdx.x;       // 65536 = S * D/2
    int s = idx >> 7;
    int i = idx & 127;
    float div = expf((float)(2 * i) * (-0.035977892078031970f)); // -ln(10000)/256
    float sn, cs;
    sincosf((float)s * div, &sn, &cs);
    g_pe[s * D_ + 2 * i]     = sn;
    g_pe[s * D_ + 2 * i + 1] = cs;
}

// ---------------- 2) x + pe -> bf16 hi/lo split, (B,S,N,D)->(BN,S,D) ----------
__global__ void addpe_split_kernel(const float* __restrict__ x) {
    int idx = blockIdx.x * 256 + threadIdx.x;       // 1,048,576 groups of 4
    int d4 = idx & 63;
    int s  = (idx >> 6) & 511;
    int bn = idx >> 15;
    int b = bn >> 3, n = bn & 7;
    const float4 xv = *(const float4*)(x + ((((long)b * S_ + s) * N_ + n) * D_ + d4 * 4));
    const float4 pv = *(const float4*)(g_pe + (s * D_ + d4 * 4));
    float v[4] = {xv.x + pv.x, xv.y + pv.y, xv.z + pv.z, xv.w + pv.w};
    long t = (long)bn * S_ + s;
    __nv_bfloat16* hb = g_a2 + t * 512 + d4 * 4;
    uint32_t h01, l01, h23, l23;
    split2(v[0], v[1], h01, l01);
    split2(v[2], v[3], h23, l23);
    ((uint32_t*)hb)[0] = h01;
    ((uint32_t*)hb)[1] = h23;
    ((uint32_t*)(hb + 256))[0] = l01;
    ((uint32_t*)(hb + 256))[1] = l23;
}

// ---------------- 3) all weights: concat + hi/lo split (one launch) -----------
__global__ void wsplit_all_kernel(const float* __restrict__ Wq, const float* __restrict__ bq,
                                  const float* __restrict__ Wk, const float* __restrict__ bk,
                                  const float* __restrict__ Wv, const float* __restrict__ bv,
                                  const float* __restrict__ Wo) {
    int idx = blockIdx.x * 256 + threadIdx.x;       // 262144 = 1024 rows * 256
    int j = idx >> 8, k = idx & 255;
    int jj = j & 255;
    if (j < 768) {
        const float* src; const float* bsrc;
        if (j < 256)      { src = Wq; bsrc = bq; }
        else if (j < 512) { src = Wk; bsrc = bk; }
        else              { src = Wv; bsrc = bv; }
        float v = src[jj * D_ + k];
        __nv_bfloat16 h = __float2bfloat16(v);
        g_w2[j * 512 + k]       = h;
        g_w2[j * 512 + 256 + k] = __float2bfloat16(v - __bfloat162float(h));
        if (k == 0) g_bcat[j] = bsrc[jj];
    } else {
        float v = Wo[jj * D_ + k];
        __nv_bfloat16 h = __float2bfloat16(v);
        g_wo2[jj * 512 + k]       = h;
        g_wo2[jj * 512 + 256 + k] = __float2bfloat16(v - __bfloat162float(h));
    }
}

// ---------------- 4) qkv GEMM: 4-stage multistage (1 barrier/stage) + SW64 ----
// C[16384,768]. Block 128x128, K-chunk 32, dynamic smem 64KB.
// Epilogue writes split bf16 Q(scaled)/K and transposed V.
#define QKV_SMEM (4 * 8192 * 2)
__global__ void __launch_bounds__(256) qkv_gemm_kernel() {
    extern __shared__ __align__(128) char dsmem[];
    const int tid = threadIdx.x;
    const int wid = tid >> 5, lane = tid & 31;
    const int wm = wid & 3;          // 4 warps along M
    const int wn = wid >> 2;         // 2 warps along N
    const int mBase = blockIdx.y * 128;
    const int nBase = blockIdx.x * 128;

    const uint32_t baseA = smem_u32(dsmem);            // 4 bufs x 8KB
    const uint32_t baseW = baseA + 32768;              // 4 bufs x 8KB

    float acc[2][8][4];
    #pragma unroll
    for (int i = 0; i < 2; ++i)
        #pragma unroll
        for (int j = 0; j < 8; ++j)
            #pragma unroll
            for (int q = 0; q < 4; ++q) acc[i][j][q] = 0.f;

    auto issue = [&](int s) {
        int buf = s & 3;
        int t = s >> 3, kc = s & 7;
        int aoff = ((t == 2) ? 256 : 0) + kc * 32;
        int woff = ((t == 1) ? 256 : 0) + kc * 32;
        #pragma unroll
        for (int i = 0; i < 2; ++i) {
            int f = i * 256 + tid;
            int row = f >> 2, c = f & 3;
            uint32_t so = SWZ64((uint32_t)(row * 64 + c * 16));
            cp16(baseA + (uint32_t)(buf * 8192) + so,
                 g_a2 + ((long)(mBase + row)) * 512 + aoff + c * 8);
            cp16(baseW + (uint32_t)(buf * 8192) + so,
                 g_w2 + ((long)(nBase + row)) * 512 + woff + c * 8);
        }
    };

    issue(0); CP_COMMIT();
    issue(1); CP_COMMIT();
    issue(2); CP_COMMIT();

    for (int s = 0; s < 24; ++s) {
        if (s <= 21)      { CP_WAIT2(); }
        else if (s == 22) { CP_WAIT1(); }
        else              { CP_WAIT0(); }
        __syncthreads();   // single barrier per stage

        const int buf = s & 3;
        const uint32_t bA = baseA + buf * 8192;
        const uint32_t bW = baseW + buf * 8192;
        #pragma unroll
        for (int ks = 0; ks < 2; ++ks) {
            uint32_t a[2][4];
            #pragma unroll
            for (int mf = 0; mf < 2; ++mf) {
                uint32_t off = SWZ64((uint32_t)((wm * 32 + mf * 16 + (lane & 15)) * 64
                                                + ks * 32 + (lane >> 4) * 16));
                ldsm_x4(a[mf][0], a[mf][1], a[mf][2], a[mf][3], bA + off);
            }
            uint32_t b[4][4];
            #pragma unroll
            for (int g = 0; g < 4; ++g) {
                uint32_t off = SWZ64((uint32_t)((wn * 64 + g * 16 + (lane >> 4) * 8 + (lane & 7)) * 64
                                                + ks * 32 + ((lane >> 3) & 1) * 16));
                ldsm_x4(b[g][0], b[g][1], b[g][2], b[g][3], bW + off);
            }
            #pragma unroll
            for (int mf = 0; mf < 2; ++mf)
                #pragma unroll
                for (int nf = 0; nf < 8; ++nf) {
                    const uint32_t* bp = b[nf >> 1];
                    if (nf & 1) mma_bf16(acc[mf][nf], a[mf], bp[2], bp[3]);
                    else        mma_bf16(acc[mf][nf], a[mf], bp[0], bp[1]);
                }
        }
        if (s + 3 < 24) { issue(s + 3); CP_COMMIT(); }   // overlapped with next wait
    }

    // epilogue: route to split Q (scaled) / K / V^T
    const int colq = (lane & 3) * 2;
    const float qscale = 0.17677669529663687f;   // 1/sqrt(32)
    #pragma unroll
    for (int mf = 0; mf < 2; ++mf) {
        int r0 = mBase + wm * 32 + mf * 16 + (lane >> 2);
        #pragma unroll
        for (int nf = 0; nf < 8; ++nf) {
            int col = nBase + wn * 64 + nf * 8 + colq;
            float bx = g_bcat[col], by = g_bcat[col + 1];
            float v00 = acc[mf][nf][0] + bx, v01 = acc[mf][nf][1] + by;   // row r0
            float v10 = acc[mf][nf][2] + bx, v11 = acc[mf][nf][3] + by;   // row r0+8
            int type = col >> 8, d = col & 255, hh = d >> 5, e = d & 31;
            if (type == 0) { v00 *= qscale; v01 *= qscale; v10 *= qscale; v11 *= qscale; }
            uint32_t h01, l01, h23, l23;
            split2(v00, v01, h01, l01);
            split2(v10, v11, h23, l23);
            int bnh0 = ((r0 >> 9) * H_ + hh);
            int s0 = r0 & 511;
            if (type < 2) {
                __nv_bfloat16* dh = type ? g_kh : g_qh;
                __nv_bfloat16* dl = type ? g_kl : g_ql;
                long a0 = ((long)bnh0 * S_ + s0) * HD_ + e;
                *(uint32_t*)(dh + a0)            = h01;
                *(uint32_t*)(dl + a0)            = l01;
                *(uint32_t*)(dh + a0 + 8 * HD_)  = h23;
                *(uint32_t*)(dl + a0 + 8 * HD_)  = l23;
            } else {
                long vb = ((long)bnh0 * HD_ + e) * S_ + s0;
                unsigned short* vh = (unsigned short*)g_vth;
                unsigned short* vl = (unsigned short*)g_vtl;
                vh[vb]           = (unsigned short)(h01 & 0xFFFF);
                vh[vb + S_]      = (unsigned short)(h01 >> 16);
                vh[vb + 8]       = (unsigned short)(h23 & 0xFFFF);
                vh[vb + S_ + 8]  = (unsigned short)(h23 >> 16);
                vl[vb]           = (unsigned short)(l01 & 0xFFFF);
                vl[vb + S_]      = (unsigned short)(l01 >> 16);
                vl[vb + 8]       = (unsigned short)(l23 & 0xFFFF);
                vl[vb + S_ + 8]  = (unsigned short)(l23 >> 16);
            }
        }
    }
}

// ---------------- 5) causal flash attention: 3-buf cp.async K/V pipeline ------
// grid (4 q-tiles of 128, 8 heads, 32 bn); 8 warps; warp = 16 query rows.
// Dynamic smem: 3 buffers x 18KB, each [Kh(5K)|Kl(5K)|Vh(4K)|Vl(4K)].
#define ATTN_BUF   18432
#define ATTN_SMEM  (3 * ATTN_BUF)
__global__ void __launch_bounds__(256) attn_mma_kernel() {
    extern __shared__ __align__(128) char dsm[];
    __shared__ __align__(128)  __nv_bfloat16 sQh[128 * 40];
    __shared__ __align__(128)  __nv_bfloat16 sQl[128 * 40];
    const int tid = threadIdx.x, wid = tid >> 5, lane = tid & 31;
    const int qBase = blockIdx.x * 128;
    const int h = blockIdx.y, bn = blockIdx.z;
    const int bnh = bn * H_ + h;
    const int qw = qBase + wid * 16;
    const long kvoff = (long)bnh * S_ * HD_;
    const __nv_bfloat16* qhg = g_qh + kvoff;
    const __nv_bfloat16* qlg = g_ql + kvoff;
    const __nv_bfloat16* khg = g_kh + kvoff;
    const __nv_bfloat16* klg = g_kl + kvoff;
    const __nv_bfloat16* vhg = g_vth + kvoff;
    const __nv_bfloat16* vlg = g_vtl + kvoff;

    const uint32_t bufBase = smem_u32(dsm);
    const int nkt_w = (qw >> 6) + 1;          // tiles this warp computes
    const int nkt_b = (qBase >> 6) + 2;       // tiles the block loads

    // issue K/V tile kt into buffer kt%3 (4 cp16 per thread)
    auto issueKV = [&](int kt) {
        uint32_t bb = bufBase + (uint32_t)((kt % 3) * ATTN_BUF);
        int row = tid >> 2, c = tid & 3;
        cp16(bb + (uint32_t)(row * 80 + c * 16),        khg + (long)(kt * 64 + row) * 32 + c * 8);
        cp16(bb + 5120 + (uint32_t)(row * 80 + c * 16), klg + (long)(kt * 64 + row) * 32 + c * 8);
        int vr = tid >> 3, vc = tid & 7;
        uint32_t so = SWZ128((uint32_t)(vr * 128 + vc * 16));
        cp16(bb + 10240 + so, vhg + (long)vr * S_ + kt * 64 + vc * 8);
        cp16(bb + 14336 + so, vlg + (long)vr * S_ + kt * 64 + vc * 8);
    };

    issueKV(0); CP_COMMIT();
    issueKV(1); CP_COMMIT();           // nkt_b >= 2 always

    // load Q tile into static smem, then fragments (overlaps tile-0/1 loads)
    #pragma unroll
    for (int i = 0; i < 2; ++i) {
        int f = i * 256 + tid, row = f >> 2, c = f & 3;
        *(float4*)((char*)sQh + row * 80 + c * 16) = *(const float4*)(qhg + (long)(qBase + row) * 32 + c * 8);
        *(float4*)((char*)sQl + row * 80 + c * 16) = *(const float4*)(qlg + (long)(qBase + row) * 32 + c * 8);
    }
    __syncthreads();

    const uint32_t bQh = smem_u32(sQh), bQl = smem_u32(sQl);
    uint32_t qfh[2][4], qfl[2][4];
    #pragma unroll
    for (int ks = 0; ks < 2; ++ks) {
        uint32_t off = (uint32_t)((wid * 16 + (lane & 15)) * 80 + ks * 32 + (lane >> 4) * 16);
        ldsm_x4(qfh[ks][0], qfh[ks][1], qfh[ks][2], qfh[ks][3], bQh + off);
        ldsm_x4(qfl[ks][0], qfl[ks][1], qfl[ks][2], qfl[ks][3], bQl + off);
    }

    float o[4][4];
    #pragma unroll
    for (int i = 0; i < 4; ++i)
        #pragma unroll
        for (int j = 0; j < 4; ++j) o[i][j] = 0.f;
    float m0 = -1e30f, m1 = -1e30f, l0 = 0.f, l1 = 0.f;

    for (int kt = 0; kt < nkt_b; ++kt) {
        if (kt + 1 < nkt_b) { CP_WAIT1(); }    // tile kt complete
        else                { CP_WAIT0(); }
        __syncthreads();                        // single barrier per tile

        const uint32_t bb = bufBase + (uint32_t)((kt % 3) * ATTN_BUF);
        const uint32_t bKh = bb, bKl = bb + 5120, bVh = bb + 10240, bVl = bb + 14336;

        if (kt < nkt_w) {
            float s[8][4];
            #pragma unroll
            for (int nt = 0; nt < 8; ++nt)
                #pragma unroll
                for (int j = 0; j < 4; ++j) s[nt][j] = 0.f;

            #pragma unroll
            for (int ks = 0; ks < 2; ++ks) {
                uint32_t bh[4][4], bl[4][4];
                #pragma unroll
                for (int g = 0; g < 4; ++g) {
                    uint32_t off = (uint32_t)((g * 16 + (lane >> 4) * 8 + (lane & 7)) * 80
                                              + ks * 32 + ((lane >> 3) & 1) * 16);
                    ldsm_x4(bh[g][0], bh[g][1], bh[g][2], bh[g][3], bKh + off);
                    ldsm_x4(bl[g][0], bl[g][1], bl[g][2], bl[g][3], bKl + off);
                }
                #pragma unroll
                for (int nt = 0; nt < 8; ++nt) {
                    const uint32_t* ph = bh[nt >> 1];
                    const uint32_t* pl = bl[nt >> 1];
                    int e0 = (nt & 1) * 2, e1 = e0 + 1;
                    mma_bf16(s[nt], qfh[ks], ph[e0], ph[e1]);
                    mma_bf16(s[nt], qfh[ks], pl[e0], pl[e1]);
                    mma_bf16(s[nt], qfl[ks], ph[e0], ph[e1]);
                }
            }

            if (kt == (qw >> 6)) {
                int q0 = qw + (lane >> 2), q1 = q0 + 8;
                #pragma unroll
                for (int nt = 0; nt < 8; ++nt) {
                    int k0 = kt * 64 + nt * 8 + ((lane & 3) << 1);
                    if (k0 > q0)     s[nt][0] = -1e9f;
                    if (k0 + 1 > q0) s[nt][1] = -1e9f;
                    if (k0 > q1)     s[nt][2] = -1e9f;
                    if (k0 + 1 > q1) s[nt][3] = -1e9f;
                }
            }

            float mx0 = -1e30f, mx1 = -1e30f;
            #pragma unroll
            for (int nt = 0; nt < 8; ++nt) {
                mx0 = fmaxf(mx0, fmaxf(s[nt][0], s[nt][1]));
                mx1 = fmaxf(mx1, fmaxf(s[nt][2], s[nt][3]));
            }
            mx0 = fmaxf(mx0, __shfl_xor_sync(0xFFFFFFFFu, mx0, 1));
            mx0 = fmaxf(mx0, __shfl_xor_sync(0xFFFFFFFFu, mx0, 2));
            mx1 = fmaxf(mx1, __shfl_xor_sync(0xFFFFFFFFu, mx1, 1));
            mx1 = fmaxf(mx1, __shfl_xor_sync(0xFFFFFFFFu, mx1, 2));
            float nm0 = fmaxf(m0, mx0), nm1 = fmaxf(m1, mx1);
            float a0 = __expf(m0 - nm0), a1 = __expf(m1 - nm1);
            m0 = nm0; m1 = nm1;

            float sum0 = 0.f, sum1 = 0.f;
            uint32_t aph[4][4], apl[4][4];
            #pragma unroll
            for (int nt = 0; nt < 8; ++nt) {
                float p0 = __expf(s[nt][0] - m0), p1 = __expf(s[nt][1] - m0);
                float p2 = __expf(s[nt][2] - m1), p3 = __expf(s[nt][3] - m1);
                sum0 += p0 + p1; sum1 += p2 + p3;
                uint32_t h01, l01, h23, l23;
                split2(p0, p1, h01, l01);
                split2(p2, p3, h23, l23);
                int kk = nt >> 1, r = (nt & 1) * 2;
                aph[kk][r]     = h01;
                aph[kk][r + 1] = h23;
                apl[kk][r]     = l01;
                apl[kk][r + 1] = l23;
            }
            sum0 += __shfl_xor_sync(0xFFFFFFFFu, sum0, 1);
            sum0 += __shfl_xor_sync(0xFFFFFFFFu, sum0, 2);
            sum1 += __shfl_xor_sync(0xFFFFFFFFu, sum1, 1);
            sum1 += __shfl_xor_sync(0xFFFFFFFFu, sum1, 2);
            l0 = l0 * a0 + sum0;
            l1 = l1 * a1 + sum1;
            #pragma unroll
            for (int nt = 0; nt < 4; ++nt) {
                o[nt][0] *= a0; o[nt][1] *= a0;
                o[nt][2] *= a1; o[nt][3] *= a1;
            }

            #pragma unroll
            for (int kk = 0; kk < 4; ++kk) {
                uint32_t vh[2][4], vl[2][4];
                #pragma unroll
                for (int g = 0; g < 2; ++g) {
                    uint32_t off = SWZ128((uint32_t)((g * 16 + (lane >> 4) * 8 + (lane & 7)) * 128
                                                     + kk * 32 + ((lane >> 3) & 1) * 16));
                    ldsm_x4(vh[g][0], vh[g][1], vh[g][2], vh[g][3], bVh + off);
                    ldsm_x4(vl[g][0], vl[g][1], vl[g][2], vl[g][3], bVl + off);
                }
                #pragma unroll
                for (int nt = 0; nt < 4; ++nt) {
                    const uint32_t* ph = vh[nt >> 1];
                    const uint32_t* pl = vl[nt >> 1];
                    int e0 = (nt & 1) * 2, e1 = e0 + 1;
                    mma_bf16(o[nt], aph[kk], ph[e0], ph[e1]);
                    mma_bf16(o[nt], aph[kk], pl[e0], pl[e1]);
                    mma_bf16(o[nt], apl[kk], ph[e0], ph[e1]);
                }
            }
        }

        if (kt + 2 < nkt_b) { issueKV(kt + 2); CP_COMMIT(); }  // buf (kt+2)%3 != kt%3
    }

    float i0 = 1.f / l0, i1 = 1.f / l1;
    long t0 = (long)bn * S_ + qw + (lane >> 2);
    #pragma unroll
    for (int nt = 0; nt < 4; ++nt) {
        int col = h * 32 + nt * 8 + ((lane & 3) << 1);
        float v00 = o[nt][0] * i0, v01 = o[nt][1] * i0;
        float v10 = o[nt][2] * i1, v11 = o[nt][3] * i1;
        uint32_t h01, l01, h23, l23;
        split2(v00, v01, h01, l01);
        split2(v10, v11, h23, l23);
        *(uint32_t*)(g_att2 + t0 * 512 + col)             = h01;
        *(uint32_t*)(g_att2 + t0 * 512 + 256 + col)       = l01;
        *(uint32_t*)(g_att2 + (t0 + 8) * 512 + col)       = h23;
        *(uint32_t*)(g_att2 + (t0 + 8) * 512 + 256 + col) = l23;
    }
}

// ---------------- 6) fused out-proj GEMM + bias + residual + LayerNorm --------
// Block: 64 rows x 256 cols. 8 warps as 2(m) x 4(n), warp tile 32x64.
// K-chunk 32, 4-stage multistage (1 barrier/stage), SW64. Writes d_out.
#define OPROJ_SMEM (4 * 4096 + 4 * 16384)
__global__ void __launch_bounds__(256) oproj_ln_kernel(
    const float* __restrict__ x,  const float* __restrict__ bo,
    const float* __restrict__ gamma, const float* __restrict__ beta,
    float* __restrict__ out)
{
    extern __shared__ __align__(128) char dsmem[];
    __shared__ float pSum[4][64], pSq[4][64];
    const int tid = threadIdx.x;
    const int wid = tid >> 5, lane = tid & 31;
    const int wm = wid & 1;          // 2 warps along M (32 rows each)
    const int wn = wid >> 1;         // 4 warps along N (64 cols each)
    const int mBase = blockIdx.x * 64;

    const uint32_t baseA = smem_u32(dsmem);            // 4 bufs x 4KB
    const uint32_t baseW = baseA + 16384;              // 4 bufs x 16KB

    float acc[2][8][4];
    #pragma unroll
    for (int i = 0; i < 2; ++i)
        #pragma unroll
        for (int j = 0; j < 8; ++j)
            #pragma unroll
            for (int q = 0; q < 4; ++q) acc[i][j][q] = 0.f;

    auto issue = [&](int s) {
        int buf = s & 3;
        int t = s >> 3, kc = s & 7;
        int aoff = ((t == 2) ? 256 : 0) + kc * 32;
        int woff = ((t == 1) ? 256 : 0) + kc * 32;
        {   // A: 64x32 = 4KB = 256 chunks, 1/thread
            int row = tid >> 2, c = tid & 3;
            uint32_t so = SWZ64((uint32_t)(row * 64 + c * 16));
            cp16(baseA + (uint32_t)(buf * 4096) + so,
                 g_att2 + ((long)(mBase + row)) * 512 + aoff + c * 8);
        }
        #pragma unroll
        for (int i = 0; i < 4; ++i) {  // W: 256x32 = 16KB = 1024 chunks, 4/thread
            int f = i * 256 + tid;
            int row = f >> 2, c = f & 3;
            uint32_t so = SWZ64((uint32_t)(row * 64 + c * 16));
            cp16(baseW + (uint32_t)(buf * 16384) + so,
                 g_wo2 + ((long)row) * 512 + woff + c * 8);
        }
    };

    issue(0); CP_COMMIT();
    issue(1); CP_COMMIT();
    issue(2); CP_COMMIT();

    for (int s = 0; s < 24; ++s) {
        if (s <= 21)      { CP_WAIT2(); }
        else if (s == 22) { CP_WAIT1(); }
        else              { CP_WAIT0(); }
        __syncthreads();

        const int buf = s & 3;
        const uint32_t bA = baseA + buf * 4096;
        const uint32_t bW = baseW + buf * 16384;
        #pragma unroll
        for (int ks = 0; ks < 2; ++ks) {
            uint32_t a[2][4];
            #pragma unroll
            for (int mf = 0; mf < 2; ++mf) {
                uint32_t off = SWZ64((uint32_t)((wm * 32 + mf * 16 + (lane & 15)) * 64
                                                + ks * 32 + (lane >> 4) * 16));
                ldsm_x4(a[mf][0], a[mf][1], a[mf][2], a[mf][3], bA + off);
            }
            uint32_t b[4][4];
            #pragma unroll
            for (int g = 0; g < 4; ++g) {
                uint32_t off = SWZ64((uint32_t)((wn * 64 + g * 16 + (lane >> 4) * 8 + (lane & 7)) * 64
                                                + ks * 32 + ((lane >> 3) & 1) * 16));
                ldsm_x4(b[g][0], b[g][1], b[g][2], b[g][3], bW + off);
            }
            #pragma unroll
            for (int mf = 0; mf < 2; ++mf)
                #pragma unroll
                for (int nf = 0; nf < 8; ++nf) {
                    const uint32_t* bp = b[nf >> 1];
                    if (nf & 1) mma_bf16(acc[mf][nf], a[mf], bp[2], bp[3]);
                    else        mma_bf16(acc[mf][nf], a[mf], bp[0], bp[1]);
                }
        }
        if (s + 3 < 24) { issue(s + 3); CP_COMMIT(); }
    }
    __syncthreads();

    // epilogue: add bias + residual, per-row LN across warps, write d_out
    const int colq = (lane & 3) * 2;
    #pragma unroll
    for (int mf = 0; mf < 2; ++mf) {
        #pragma unroll
        for (int rr = 0; rr < 2; ++rr) {
            int rl = wm * 32 + mf * 16 + rr * 8 + (lane >> 2);   // local row 0..63
            int t = mBase + rl;
            int bnn = t >> 9, ss = t & 511;
            int bb = bnn >> 3, nn = bnn & 7;
            const float* xrow = x + (((long)(bb * S_ + ss)) * N_ + nn) * D_;
            float sum = 0.f, sq = 0.f;
            #pragma unroll
            for (int nf = 0; nf < 8; ++nf) {
                int col = wn * 64 + nf * 8 + colq;
                float2 xv = *(const float2*)(xrow + col);
                float2 bv = *(const float2*)(bo + col);
                float v0 = acc[mf][nf][rr * 2]     + xv.x + bv.x;
                float v1 = acc[mf][nf][rr * 2 + 1] + xv.y + bv.y;
                acc[mf][nf][rr * 2]     = v0;
                acc[mf][nf][rr * 2 + 1] = v1;
                sum += v0 + v1;
                sq = fmaf(v0, v0, sq);
                sq = fmaf(v1, v1, sq);
            }
            sum += __shfl_xor_sync(0xFFFFFFFFu, sum, 1);
            sum += __shfl_xor_sync(0xFFFFFFFFu, sum, 2);
            sq  += __shfl_xor_sync(0xFFFFFFFFu, sq,  1);
            sq  += __shfl_xor_sync(0xFFFFFFFFu, sq,  2);
            if ((lane & 3) == 0) {
                pSum[wn][rl] = sum;
                pSq[wn][rl]  = sq;
            }
        }
    }
    __syncthreads();

    #pragma unroll
    for (int mf = 0; mf < 2; ++mf) {
        #pragma unroll
        for (int rr = 0; rr < 2; ++rr) {
            int rl = wm * 32 + mf * 16 + rr * 8 + (lane >> 2);
            int t = mBase + rl;
            int bnn = t >> 9, ss = t & 511;
            int bb = bnn >> 3, nn = bnn & 7;
            float S  = pSum[0][rl] + pSum[1][rl] + pSum[2][rl] + pSum[3][rl];
            float Q  = pSq[0][rl]  + pSq[1][rl]  + pSq[2][rl]  + pSq[3][rl];
            float mu = S * (1.f / 256.f);
            float var = Q * (1.f / 256.f) - mu * mu;
            float rstd = rsqrtf(var + 1e-5f);
            float* orow = out + (((long)(bb * S_ + ss)) * N_ + nn) * D_;
            #pragma unroll
            for (int nf = 0; nf < 8; ++nf) {
                int col = wn * 64 + nf * 8 + colq;
                float2 gv = *(const float2*)(gamma + col);
                float2 tv = *(const float2*)(beta + col);
                float2 ov;
                ov.x = (acc[mf][nf][rr * 2]     - mu) * rstd * gv.x + tv.x;
                ov.y = (acc[mf][nf][rr * 2 + 1] - mu) * rstd * gv.y + tv.y;
                *(float2*)(orow + col) = ov;
            }
        }
    }
}

// ------------------------------ launch ----------------------------------------
// Input order per metadata (dict insertion order in setup_inputs):
//   0:x 1:Wq 2:Wk 3:Wv 4:Wo 5:bq 6:bk 7:bv 8:bo 9:gamma 10:beta 11:num_heads
extern "C" void kernel_launch(void* const* d_in, const int* in_sizes, int n_in,
                              void* d_out, int out_size) {
    const float* x     = (const float*)d_in[0];
    const float* Wq    = (const float*)d_in[1];
    const float* Wk    = (const float*)d_in[2];
    const float* Wv    = (const float*)d_in[3];
    const float* Wo    = (const float*)d_in[4];
    const float* bq    = (const float*)d_in[5];
    const float* bk    = (const float*)d_in[6];
    const float* bv    = (const float*)d_in[7];
    const float* bo    = (const float*)d_in[8];
    const float* gamma = (const float*)d_in[9];
    const float* beta  = (const float*)d_in[10];
    float* out = (float*)d_out;

    // idempotent; host-side attribute set (not a stream op, graph-capture safe)
    cudaFuncSetAttribute(qkv_gemm_kernel, cudaFuncAttributeMaxDynamicSharedMemorySize, QKV_SMEM);
    cudaFuncSetAttribute(attn_mma_kernel, cudaFuncAttributeMaxDynamicSharedMemorySize, ATTN_SMEM);
    cudaFuncSetAttribute(oproj_ln_kernel, cudaFuncAttributeMaxDynamicSharedMemorySize, OPROJ_SMEM);

    pe_kernel<<<256, 256>>>();
    addpe_split_kernel<<<4096, 256>>>(x);
    wsplit_all_kernel<<<1024, 256>>>(Wq, bq, Wk, bk, Wv, bv, Wo);
    qkv_gemm_kernel<<<dim3(6, 128), 256, QKV_SMEM>>>();
    attn_mma_kernel<<<dim3(4, H_, BN_), 256, ATTN_SMEM>>>();
    oproj_ln_kernel<<<256, 256, OPROJ_SMEM>>>(x, bo, gamma, beta, out);
}

// round 14
// speedup vs baseline: 1.3194x; 1.2418x over previous
#include <cuda_runtime.h>
#include <cuda_bf16.h>
#include <math.h>
#include <stdint.h>

// Problem constants (fixed by the dataset)
#define B_   4
#define S_   512
#define N_   8
#define D_   256
#define H_   8
#define HD_  32
#define BN_  (B_ * N_)          // 32
#define T_   (BN_ * S_)         // 16384 rows
#define QKVN 768                // 3*D

// ---------------- warp-mma helpers (baseline PTX, sm_80+) ---------------------
__device__ __forceinline__ uint32_t smem_u32(const void* p) {
    uint32_t a;
    asm("{ .reg .u64 t; cvta.to.shared.u64 t, %1; cvt.u32.u64 %0, t; }" : "=r"(a) : "l"(p));
    return a;
}
__device__ __forceinline__ void ldsm_x4(uint32_t& r0, uint32_t& r1, uint32_t& r2, uint32_t& r3,
                                        uint32_t addr) {
    asm volatile("ldmatrix.sync.aligned.m8n8.x4.shared.b16 {%0,%1,%2,%3}, [%4];"
        : "=r"(r0), "=r"(r1), "=r"(r2), "=r"(r3) : "r"(addr));
}
__device__ __forceinline__ void mma_bf16(float* c, const uint32_t* a, uint32_t b0, uint32_t b1) {
    asm volatile(
        "mma.sync.aligned.m16n8k16.row.col.f32.bf16.bf16.f32 "
        "{%0,%1,%2,%3}, {%4,%5,%6,%7}, {%8,%9}, {%0,%1,%2,%3};"
        : "+f"(c[0]), "+f"(c[1]), "+f"(c[2]), "+f"(c[3])
        : "r"(a[0]), "r"(a[1]), "r"(a[2]), "r"(a[3]), "r"(b0), "r"(b1));
}
__device__ __forceinline__ uint32_t bf16x2pack(float v0, float v1) {
    uint32_t r;
    asm("cvt.rn.bf16x2.f32 %0, %1, %2;" : "=r"(r) : "f"(v1), "f"(v0));
    return r;
}
__device__ __forceinline__ void split2(float v0, float v1, uint32_t& hi, uint32_t& lo) {
    hi = bf16x2pack(v0, v1);
    float h0 = __uint_as_float(hi << 16);
    float h1 = __uint_as_float(hi & 0xFFFF0000u);
    lo = bf16x2pack(v0 - h0, v1 - h1);
}
__device__ __forceinline__ void cp16(uint32_t dst, const void* src) {
    asm volatile("cp.async.cg.shared.global [%0], [%1], 16;" :: "r"(dst), "l"(src));
}
#define CP_COMMIT() asm volatile("cp.async.commit_group;" ::: "memory")
#define CP_WAIT2()  asm volatile("cp.async.wait_group 2;" ::: "memory")
#define CP_WAIT1()  asm volatile("cp.async.wait_group 1;" ::: "memory")
#define CP_WAIT0()  asm volatile("cp.async.wait_group 0;" ::: "memory")
#define SWZ128(off) ((off) ^ (((off) >> 3) & 0x70))
// SW64 for 64-byte-pitch rows: XOR 16B-column bits [5:4] with row bits [2:1].
#define SWZ64(off)  ((off) ^ (((off) >> 3) & 0x30))

// ---------------- scratch (device globals; no runtime allocation) -------------
__device__ float g_pe[S_ * D_];
__device__ __nv_bfloat16 g_a2[(long)T_ * 512];         // [hi(256)|lo(256)] per row
__device__ __nv_bfloat16 g_w2[QKVN * 512];
__device__ __nv_bfloat16 g_wo2[D_ * 512];
__device__ float g_bcat[QKVN];
__device__ __nv_bfloat16 g_qh[(long)BN_ * H_ * S_ * HD_];   // [bnh][s][e] Q*scale hi
__device__ __nv_bfloat16 g_ql[(long)BN_ * H_ * S_ * HD_];
__device__ __nv_bfloat16 g_kh[(long)BN_ * H_ * S_ * HD_];
__device__ __nv_bfloat16 g_kl[(long)BN_ * H_ * S_ * HD_];
__device__ __nv_bfloat16 g_vth[(long)BN_ * H_ * HD_ * S_];  // [bnh][e][s]  V^T
__device__ __nv_bfloat16 g_vtl[(long)BN_ * H_ * HD_ * S_];
__device__ __nv_bfloat16 g_att2[(long)T_ * 512];       // only hi(256) used now

// ---------------- 1) positional encoding table -------------------------------
__global__ void pe_kernel() {
    int idx = blockIdx.x * 256 + threadIdx.x;       // 65536 = S * D/2
    int s = idx >> 7;
    int i = idx & 127;
    float div = expf((float)(2 * i) * (-0.035977892078031970f)); // -ln(10000)/256
    float sn, cs;
    sincosf((float)s * div, &sn, &cs);
    g_pe[s * D_ + 2 * i]     = sn;
    g_pe[s * D_ + 2 * i + 1] = cs;
}

// ---------------- 2) x + pe -> bf16 hi/lo split, (B,S,N,D)->(BN,S,D) ----------
__global__ void addpe_split_kernel(const float* __restrict__ x) {
    int idx = blockIdx.x * 256 + threadIdx.x;       // 1,048,576 groups of 4
    int d4 = idx & 63;
    int s  = (idx >> 6) & 511;
    int bn = idx >> 15;
    int b = bn >> 3, n = bn & 7;
    const float4 xv = *(const float4*)(x + ((((long)b * S_ + s) * N_ + n) * D_ + d4 * 4));
    const float4 pv = *(const float4*)(g_pe + (s * D_ + d4 * 4));
    float v[4] = {xv.x + pv.x, xv.y + pv.y, xv.z + pv.z, xv.w + pv.w};
    long t = (long)bn * S_ + s;
    __nv_bfloat16* hb = g_a2 + t * 512 + d4 * 4;
    uint32_t h01, l01, h23, l23;
    split2(v[0], v[1], h01, l01);
    split2(v[2], v[3], h23, l23);
    ((uint32_t*)hb)[0] = h01;
    ((uint32_t*)hb)[1] = h23;
    ((uint32_t*)(hb + 256))[0] = l01;
    ((uint32_t*)(hb + 256))[1] = l23;
}

// ---------------- 3) all weights: concat + hi/lo split (one launch) -----------
__global__ void wsplit_all_kernel(const float* __restrict__ Wq, const float* __restrict__ bq,
                                  const float* __restrict__ Wk, const float* __restrict__ bk,
                                  const float* __restrict__ Wv, const float* __restrict__ bv,
                                  const float* __restrict__ Wo) {
    int idx = blockIdx.x * 256 + threadIdx.x;       // 262144 = 1024 rows * 256
    int j = idx >> 8, k = idx & 255;
    int jj = j & 255;
    if (j < 768) {
        const float* src; const float* bsrc;
        if (j < 256)      { src = Wq; bsrc = bq; }
        else if (j < 512) { src = Wk; bsrc = bk; }
        else              { src = Wv; bsrc = bv; }
        float v = src[jj * D_ + k];
        __nv_bfloat16 h = __float2bfloat16(v);
        g_w2[j * 512 + k]       = h;
        g_w2[j * 512 + 256 + k] = __float2bfloat16(v - __bfloat162float(h));
        if (k == 0) g_bcat[j] = bsrc[jj];
    } else {
        float v = Wo[jj * D_ + k];
        __nv_bfloat16 h = __float2bfloat16(v);
        g_wo2[jj * 512 + k]       = h;
        g_wo2[jj * 512 + 256 + k] = __float2bfloat16(v - __bfloat162float(h));
    }
}

// ---------------- 4) qkv GEMM: 2-term split (Ah·Wh + Ah·Wl), 16 stages --------
// C[16384,768]. Block 128x128, K-chunk 32, 4-stage multistage, SW64, smem 64KB.
// Epilogue writes split bf16 Q(scaled)/K and transposed V.
#define QKV_SMEM (4 * 8192 * 2)
__global__ void __launch_bounds__(256) qkv_gemm_kernel() {
    extern __shared__ __align__(128) char dsmem[];
    const int tid = threadIdx.x;
    const int wid = tid >> 5, lane = tid & 31;
    const int wm = wid & 3;          // 4 warps along M
    const int wn = wid >> 2;         // 2 warps along N
    const int mBase = blockIdx.y * 128;
    const int nBase = blockIdx.x * 128;

    const uint32_t baseA = smem_u32(dsmem);            // 4 bufs x 8KB
    const uint32_t baseW = baseA + 32768;              // 4 bufs x 8KB

    float acc[2][8][4];
    #pragma unroll
    for (int i = 0; i < 2; ++i)
        #pragma unroll
        for (int j = 0; j < 8; ++j)
            #pragma unroll
            for (int q = 0; q < 4; ++q) acc[i][j][q] = 0.f;

    // stages 0..15: seg = s>>3 (0: Ah·Wh, 1: Ah·Wl); kc = s&7
    auto issue = [&](int s) {
        int buf = s & 3;
        int t = s >> 3, kc = s & 7;
        int aoff = kc * 32;                          // A hi always
        int woff = ((t == 1) ? 256 : 0) + kc * 32;   // W hi then lo
        #pragma unroll
        for (int i = 0; i < 2; ++i) {
            int f = i * 256 + tid;
            int row = f >> 2, c = f & 3;
            uint32_t so = SWZ64((uint32_t)(row * 64 + c * 16));
            cp16(baseA + (uint32_t)(buf * 8192) + so,
                 g_a2 + ((long)(mBase + row)) * 512 + aoff + c * 8);
            cp16(baseW + (uint32_t)(buf * 8192) + so,
                 g_w2 + ((long)(nBase + row)) * 512 + woff + c * 8);
        }
    };

    issue(0); CP_COMMIT();
    issue(1); CP_COMMIT();
    issue(2); CP_COMMIT();

    for (int s = 0; s < 16; ++s) {
        if (s <= 13)      { CP_WAIT2(); }
        else if (s == 14) { CP_WAIT1(); }
        else              { CP_WAIT0(); }
        __syncthreads();   // single barrier per stage

        const int buf = s & 3;
        const uint32_t bA = baseA + buf * 8192;
        const uint32_t bW = baseW + buf * 8192;
        #pragma unroll
        for (int ks = 0; ks < 2; ++ks) {
            uint32_t a[2][4];
            #pragma unroll
            for (int mf = 0; mf < 2; ++mf) {
                uint32_t off = SWZ64((uint32_t)((wm * 32 + mf * 16 + (lane & 15)) * 64
                                                + ks * 32 + (lane >> 4) * 16));
                ldsm_x4(a[mf][0], a[mf][1], a[mf][2], a[mf][3], bA + off);
            }
            uint32_t b[4][4];
            #pragma unroll
            for (int g = 0; g < 4; ++g) {
                uint32_t off = SWZ64((uint32_t)((wn * 64 + g * 16 + (lane >> 4) * 8 + (lane & 7)) * 64
                                                + ks * 32 + ((lane >> 3) & 1) * 16));
                ldsm_x4(b[g][0], b[g][1], b[g][2], b[g][3], bW + off);
            }
            #pragma unroll
            for (int mf = 0; mf < 2; ++mf)
                #pragma unroll
                for (int nf = 0; nf < 8; ++nf) {
                    const uint32_t* bp = b[nf >> 1];
                    if (nf & 1) mma_bf16(acc[mf][nf], a[mf], bp[2], bp[3]);
                    else        mma_bf16(acc[mf][nf], a[mf], bp[0], bp[1]);
                }
        }
        if (s + 3 < 16) { issue(s + 3); CP_COMMIT(); }   // overlapped with next wait
    }

    // epilogue: route to split Q (scaled) / K / V^T
    const int colq = (lane & 3) * 2;
    const float qscale = 0.17677669529663687f;   // 1/sqrt(32)
    #pragma unroll
    for (int mf = 0; mf < 2; ++mf) {
        int r0 = mBase + wm * 32 + mf * 16 + (lane >> 2);
        #pragma unroll
        for (int nf = 0; nf < 8; ++nf) {
            int col = nBase + wn * 64 + nf * 8 + colq;
            float bx = g_bcat[col], by = g_bcat[col + 1];
            float v00 = acc[mf][nf][0] + bx, v01 = acc[mf][nf][1] + by;   // row r0
            float v10 = acc[mf][nf][2] + bx, v11 = acc[mf][nf][3] + by;   // row r0+8
            int type = col >> 8, d = col & 255, hh = d >> 5, e = d & 31;
            if (type == 0) { v00 *= qscale; v01 *= qscale; v10 *= qscale; v11 *= qscale; }
            uint32_t h01, l01, h23, l23;
            split2(v00, v01, h01, l01);
            split2(v10, v11, h23, l23);
            int bnh0 = ((r0 >> 9) * H_ + hh);
            int s0 = r0 & 511;
            if (type < 2) {
                __nv_bfloat16* dh = type ? g_kh : g_qh;
                __nv_bfloat16* dl = type ? g_kl : g_ql;
                long a0 = ((long)bnh0 * S_ + s0) * HD_ + e;
                *(uint32_t*)(dh + a0)            = h01;
                *(uint32_t*)(dl + a0)            = l01;
                *(uint32_t*)(dh + a0 + 8 * HD_)  = h23;
                *(uint32_t*)(dl + a0 + 8 * HD_)  = l23;
            } else {
                long vb = ((long)bnh0 * HD_ + e) * S_ + s0;
                unsigned short* vh = (unsigned short*)g_vth;
                unsigned short* vl = (unsigned short*)g_vtl;
                vh[vb]           = (unsigned short)(h01 & 0xFFFF);
                vh[vb + S_]      = (unsigned short)(h01 >> 16);
                vh[vb + 8]       = (unsigned short)(h23 & 0xFFFF);
                vh[vb + S_ + 8]  = (unsigned short)(h23 >> 16);
                vl[vb]           = (unsigned short)(l01 & 0xFFFF);
                vl[vb + S_]      = (unsigned short)(l01 >> 16);
                vl[vb + 8]       = (unsigned short)(l23 & 0xFFFF);
                vl[vb + S_ + 8]  = (unsigned short)(l23 >> 16);
            }
        }
    }
}

// ---------------- 5) causal flash attention: pipelined K/V, 2-term P·V --------
// grid (4 q-tiles of 128, 8 heads, 32 bn); 8 warps; warp = 16 query rows.
// Dynamic smem: 3 buffers x 18KB, each [Kh(5K)|Kl(5K)|Vh(4K)|Vl(4K)].
#define ATTN_BUF   18432
#define ATTN_SMEM  (3 * ATTN_BUF)
__global__ void __launch_bounds__(256) attn_mma_kernel() {
    extern __shared__ __align__(128) char dsm[];
    __shared__ __align__(128)  __nv_bfloat16 sQh[128 * 40];
    __shared__ __align__(128)  __nv_bfloat16 sQl[128 * 40];
    const int tid = threadIdx.x, wid = tid >> 5, lane = tid & 31;
    const int qBase = blockIdx.x * 128;
    const int h = blockIdx.y, bn = blockIdx.z;
    const int bnh = bn * H_ + h;
    const int qw = qBase + wid * 16;
    const long kvoff = (long)bnh * S_ * HD_;
    const __nv_bfloat16* qhg = g_qh + kvoff;
    const __nv_bfloat16* qlg = g_ql + kvoff;
    const __nv_bfloat16* khg = g_kh + kvoff;
    const __nv_bfloat16* klg = g_kl + kvoff;
    const __nv_bfloat16* vhg = g_vth + kvoff;
    const __nv_bfloat16* vlg = g_vtl + kvoff;

    const uint32_t bufBase = smem_u32(dsm);
    const int nkt_w = (qw >> 6) + 1;          // tiles this warp computes
    const int nkt_b = (qBase >> 6) + 2;       // tiles the block loads

    auto issueKV = [&](int kt) {
        uint32_t bb = bufBase + (uint32_t)((kt % 3) * ATTN_BUF);
        int row = tid >> 2, c = tid & 3;
        cp16(bb + (uint32_t)(row * 80 + c * 16),        khg + (long)(kt * 64 + row) * 32 + c * 8);
        cp16(bb + 5120 + (uint32_t)(row * 80 + c * 16), klg + (long)(kt * 64 + row) * 32 + c * 8);
        int vr = tid >> 3, vc = tid & 7;
        uint32_t so = SWZ128((uint32_t)(vr * 128 + vc * 16));
        cp16(bb + 10240 + so, vhg + (long)vr * S_ + kt * 64 + vc * 8);
        cp16(bb + 14336 + so, vlg + (long)vr * S_ + kt * 64 + vc * 8);
    };

    issueKV(0); CP_COMMIT();
    issueKV(1); CP_COMMIT();           // nkt_b >= 2 always

    #pragma unroll
    for (int i = 0; i < 2; ++i) {
        int f = i * 256 + tid, row = f >> 2, c = f & 3;
        *(float4*)((char*)sQh + row * 80 + c * 16) = *(const float4*)(qhg + (long)(qBase + row) * 32 + c * 8);
        *(float4*)((char*)sQl + row * 80 + c * 16) = *(const float4*)(qlg + (long)(qBase + row) * 32 + c * 8);
    }
    __syncthreads();

    const uint32_t bQh = smem_u32(sQh), bQl = smem_u32(sQl);
    uint32_t qfh[2][4], qfl[2][4];
    #pragma unroll
    for (int ks = 0; ks < 2; ++ks) {
        uint32_t off = (uint32_t)((wid * 16 + (lane & 15)) * 80 + ks * 32 + (lane >> 4) * 16);
        ldsm_x4(qfh[ks][0], qfh[ks][1], qfh[ks][2], qfh[ks][3], bQh + off);
        ldsm_x4(qfl[ks][0], qfl[ks][1], qfl[ks][2], qfl[ks][3], bQl + off);
    }

    float o[4][4];
    #pragma unroll
    for (int i = 0; i < 4; ++i)
        #pragma unroll
        for (int j = 0; j < 4; ++j) o[i][j] = 0.f;
    float m0 = -1e30f, m1 = -1e30f, l0 = 0.f, l1 = 0.f;

    for (int kt = 0; kt < nkt_b; ++kt) {
        if (kt + 1 < nkt_b) { CP_WAIT1(); }
        else                { CP_WAIT0(); }
        __syncthreads();

        const uint32_t bb = bufBase + (uint32_t)((kt % 3) * ATTN_BUF);
        const uint32_t bKh = bb, bKl = bb + 5120, bVh = bb + 10240, bVl = bb + 14336;

        if (kt < nkt_w) {
            float s[8][4];
            #pragma unroll
            for (int nt = 0; nt < 8; ++nt)
                #pragma unroll
                for (int j = 0; j < 4; ++j) s[nt][j] = 0.f;

            #pragma unroll
            for (int ks = 0; ks < 2; ++ks) {
                uint32_t bh[4][4], bl[4][4];
                #pragma unroll
                for (int g = 0; g < 4; ++g) {
                    uint32_t off = (uint32_t)((g * 16 + (lane >> 4) * 8 + (lane & 7)) * 80
                                              + ks * 32 + ((lane >> 3) & 1) * 16);
                    ldsm_x4(bh[g][0], bh[g][1], bh[g][2], bh[g][3], bKh + off);
                    ldsm_x4(bl[g][0], bl[g][1], bl[g][2], bl[g][3], bKl + off);
                }
                #pragma unroll
                for (int nt = 0; nt < 8; ++nt) {
                    const uint32_t* ph = bh[nt >> 1];
                    const uint32_t* pl = bl[nt >> 1];
                    int e0 = (nt & 1) * 2, e1 = e0 + 1;
                    mma_bf16(s[nt], qfh[ks], ph[e0], ph[e1]);
                    mma_bf16(s[nt], qfh[ks], pl[e0], pl[e1]);
                    mma_bf16(s[nt], qfl[ks], ph[e0], ph[e1]);
                }
            }

            if (kt == (qw >> 6)) {
                int q0 = qw + (lane >> 2), q1 = q0 + 8;
                #pragma unroll
                for (int nt = 0; nt < 8; ++nt) {
                    int k0 = kt * 64 + nt * 8 + ((lane & 3) << 1);
                    if (k0 > q0)     s[nt][0] = -1e9f;
                    if (k0 + 1 > q0) s[nt][1] = -1e9f;
                    if (k0 > q1)     s[nt][2] = -1e9f;
                    if (k0 + 1 > q1) s[nt][3] = -1e9f;
                }
            }

            float mx0 = -1e30f, mx1 = -1e30f;
            #pragma unroll
            for (int nt = 0; nt < 8; ++nt) {
                mx0 = fmaxf(mx0, fmaxf(s[nt][0], s[nt][1]));
                mx1 = fmaxf(mx1, fmaxf(s[nt][2], s[nt][3]));
            }
            mx0 = fmaxf(mx0, __shfl_xor_sync(0xFFFFFFFFu, mx0, 1));
            mx0 = fmaxf(mx0, __shfl_xor_sync(0xFFFFFFFFu, mx0, 2));
            mx1 = fmaxf(mx1, __shfl_xor_sync(0xFFFFFFFFu, mx1, 1));
            mx1 = fmaxf(mx1, __shfl_xor_sync(0xFFFFFFFFu, mx1, 2));
            float nm0 = fmaxf(m0, mx0), nm1 = fmaxf(m1, mx1);
            float a0 = __expf(m0 - nm0), a1 = __expf(m1 - nm1);
            m0 = nm0; m1 = nm1;

            float sum0 = 0.f, sum1 = 0.f;
            uint32_t aph[4][4];                    // P hi only (2-term P·V)
            #pragma unroll
            for (int nt = 0; nt < 8; ++nt) {
                float p0 = __expf(s[nt][0] - m0), p1 = __expf(s[nt][1] - m0);
                float p2 = __expf(s[nt][2] - m1), p3 = __expf(s[nt][3] - m1);
                sum0 += p0 + p1; sum1 += p2 + p3;
                int kk = nt >> 1, r = (nt & 1) * 2;
                aph[kk][r]     = bf16x2pack(p0, p1);
                aph[kk][r + 1] = bf16x2pack(p2, p3);
            }
            sum0 += __shfl_xor_sync(0xFFFFFFFFu, sum0, 1);
            sum0 += __shfl_xor_sync(0xFFFFFFFFu, sum0, 2);
            sum1 += __shfl_xor_sync(0xFFFFFFFFu, sum1, 1);
            sum1 += __shfl_xor_sync(0xFFFFFFFFu, sum1, 2);
            l0 = l0 * a0 + sum0;
            l1 = l1 * a1 + sum1;
            #pragma unroll
            for (int nt = 0; nt < 4; ++nt) {
                o[nt][0] *= a0; o[nt][1] *= a0;
                o[nt][2] *= a1; o[nt][3] *= a1;
            }

            #pragma unroll
            for (int kk = 0; kk < 4; ++kk) {
                uint32_t vh[2][4], vl[2][4];
                #pragma unroll
                for (int g = 0; g < 2; ++g) {
                    uint32_t off = SWZ128((uint32_t)((g * 16 + (lane >> 4) * 8 + (lane & 7)) * 128
                                                     + kk * 32 + ((lane >> 3) & 1) * 16));
                    ldsm_x4(vh[g][0], vh[g][1], vh[g][2], vh[g][3], bVh + off);
                    ldsm_x4(vl[g][0], vl[g][1], vl[g][2], vl[g][3], bVl + off);
                }
                #pragma unroll
                for (int nt = 0; nt < 4; ++nt) {
                    const uint32_t* ph = vh[nt >> 1];
                    const uint32_t* pl = vl[nt >> 1];
                    int e0 = (nt & 1) * 2, e1 = e0 + 1;
                    mma_bf16(o[nt], aph[kk], ph[e0], ph[e1]);
                    mma_bf16(o[nt], aph[kk], pl[e0], pl[e1]);
                }
            }
        }

        if (kt + 2 < nkt_b) { issueKV(kt + 2); CP_COMMIT(); }
    }

    // epilogue: normalize, write hi-only bf16 attention output
    float i0 = 1.f / l0, i1 = 1.f / l1;
    long t0 = (long)bn * S_ + qw + (lane >> 2);
    #pragma unroll
    for (int nt = 0; nt < 4; ++nt) {
        int col = h * 32 + nt * 8 + ((lane & 3) << 1);
        *(uint32_t*)(g_att2 + t0 * 512 + col)       = bf16x2pack(o[nt][0] * i0, o[nt][1] * i0);
        *(uint32_t*)(g_att2 + (t0 + 8) * 512 + col) = bf16x2pack(o[nt][2] * i1, o[nt][3] * i1);
    }
}

// ---------------- 6) fused out-proj GEMM + bias + residual + LayerNorm --------
// 2-term split (Ah·Wh + Ah·Wl), 16 stages. Block 64x256, SW64. Writes d_out.
#define OPROJ_SMEM (4 * 4096 + 4 * 16384)
__global__ void __launch_bounds__(256) oproj_ln_kernel(
    const float* __restrict__ x,  const float* __restrict__ bo,
    const float* __restrict__ gamma, const float* __restrict__ beta,
    float* __restrict__ out)
{
    extern __shared__ __align__(128) char dsmem[];
    __shared__ float pSum[4][64], pSq[4][64];
    const int tid = threadIdx.x;
    const int wid = tid >> 5, lane = tid & 31;
    const int wm = wid & 1;          // 2 warps along M (32 rows each)
    const int wn = wid >> 1;         // 4 warps along N (64 cols each)
    const int mBase = blockIdx.x * 64;

    const uint32_t baseA = smem_u32(dsmem);            // 4 bufs x 4KB
    const uint32_t baseW = baseA + 16384;              // 4 bufs x 16KB

    float acc[2][8][4];
    #pragma unroll
    for (int i = 0; i < 2; ++i)
        #pragma unroll
        for (int j = 0; j < 8; ++j)
            #pragma unroll
            for (int q = 0; q < 4; ++q) acc[i][j][q] = 0.f;

    auto issue = [&](int s) {
        int buf = s & 3;
        int t = s >> 3, kc = s & 7;
        int aoff = kc * 32;                          // A hi always
        int woff = ((t == 1) ? 256 : 0) + kc * 32;   // W hi then lo
        {
            int row = tid >> 2, c = tid & 3;
            uint32_t so = SWZ64((uint32_t)(row * 64 + c * 16));
            cp16(baseA + (uint32_t)(buf * 4096) + so,
                 g_att2 + ((long)(mBase + row)) * 512 + aoff + c * 8);
        }
        #pragma unroll
        for (int i = 0; i < 4; ++i) {
            int f = i * 256 + tid;
            int row = f >> 2, c = f & 3;
            uint32_t so = SWZ64((uint32_t)(row * 64 + c * 16));
            cp16(baseW + (uint32_t)(buf * 16384) + so,
                 g_wo2 + ((long)row) * 512 + woff + c * 8);
        }
    };

    issue(0); CP_COMMIT();
    issue(1); CP_COMMIT();
    issue(2); CP_COMMIT();

    for (int s = 0; s < 16; ++s) {
        if (s <= 13)      { CP_WAIT2(); }
        else if (s == 14) { CP_WAIT1(); }
        else              { CP_WAIT0(); }
        __syncthreads();

        const int buf = s & 3;
        const uint32_t bA = baseA + buf * 4096;
        const uint32_t bW = baseW + buf * 16384;
        #pragma unroll
        for (int ks = 0; ks < 2; ++ks) {
            uint32_t a[2][4];
            #pragma unroll
            for (int mf = 0; mf < 2; ++mf) {
                uint32_t off = SWZ64((uint32_t)((wm * 32 + mf * 16 + (lane & 15)) * 64
                                                + ks * 32 + (lane >> 4) * 16));
                ldsm_x4(a[mf][0], a[mf][1], a[mf][2], a[mf][3], bA + off);
            }
            uint32_t b[4][4];
            #pragma unroll
            for (int g = 0; g < 4; ++g) {
                uint32_t off = SWZ64((uint32_t)((wn * 64 + g * 16 + (lane >> 4) * 8 + (lane & 7)) * 64
                                                + ks * 32 + ((lane >> 3) & 1) * 16));
                ldsm_x4(b[g][0], b[g][1], b[g][2], b[g][3], bW + off);
            }
            #pragma unroll
            for (int mf = 0; mf < 2; ++mf)
                #pragma unroll
                for (int nf = 0; nf < 8; ++nf) {
                    const uint32_t* bp = b[nf >> 1];
                    if (nf & 1) mma_bf16(acc[mf][nf], a[mf], bp[2], bp[3]);
                    else        mma_bf16(acc[mf][nf], a[mf], bp[0], bp[1]);
                }
        }
        if (s + 3 < 16) { issue(s + 3); CP_COMMIT(); }
    }
    __syncthreads();

    // epilogue: add bias + residual, per-row LN across warps, write d_out
    const int colq = (lane & 3) * 2;
    #pragma unroll
    for (int mf = 0; mf < 2; ++mf) {
        #pragma unroll
        for (int rr = 0; rr < 2; ++rr) {
            int rl = wm * 32 + mf * 16 + rr * 8 + (lane >> 2);   // local row 0..63
            int t = mBase + rl;
            int bnn = t >> 9, ss = t & 511;
            int bb = bnn >> 3, nn = bnn & 7;
            const float* xrow = x + (((long)(bb * S_ + ss)) * N_ + nn) * D_;
            float sum = 0.f, sq = 0.f;
            #pragma unroll
            for (int nf = 0; nf < 8; ++nf) {
                int col = wn * 64 + nf * 8 + colq;
                float2 xv = *(const float2*)(xrow + col);
                float2 bv = *(const float2*)(bo + col);
                float v0 = acc[mf][nf][rr * 2]     + xv.x + bv.x;
                float v1 = acc[mf][nf][rr * 2 + 1] + xv.y + bv.y;
                acc[mf][nf][rr * 2]     = v0;
                acc[mf][nf][rr * 2 + 1] = v1;
                sum += v0 + v1;
                sq = fmaf(v0, v0, sq);
                sq = fmaf(v1, v1, sq);
            }
            sum += __shfl_xor_sync(0xFFFFFFFFu, sum, 1);
            sum += __shfl_xor_sync(0xFFFFFFFFu, sum, 2);
            sq  += __shfl_xor_sync(0xFFFFFFFFu, sq,  1);
            sq  += __shfl_xor_sync(0xFFFFFFFFu, sq,  2);
            if ((lane & 3) == 0) {
                pSum[wn][rl] = sum;
                pSq[wn][rl]  = sq;
            }
        }
    }
    __syncthreads();

    #pragma unroll
    for (int mf = 0; mf < 2; ++mf) {
        #pragma unroll
        for (int rr = 0; rr < 2; ++rr) {
            int rl = wm * 32 + mf * 16 + rr * 8 + (lane >> 2);
            int t = mBase + rl;
            int bnn = t >> 9, ss = t & 511;
            int bb = bnn >> 3, nn = bnn & 7;
            float S  = pSum[0][rl] + pSum[1][rl] + pSum[2][rl] + pSum[3][rl];
            float Q  = pSq[0][rl]  + pSq[1][rl]  + pSq[2][rl]  + pSq[3][rl];
            float mu = S * (1.f / 256.f);
            float var = Q * (1.f / 256.f) - mu * mu;
            float rstd = rsqrtf(var + 1e-5f);
            float* orow = out + (((long)(bb * S_ + ss)) * N_ + nn) * D_;
            #pragma unroll
            for (int nf = 0; nf < 8; ++nf) {
                int col = wn * 64 + nf * 8 + colq;
                float2 gv = *(const float2*)(gamma + col);
                float2 tv = *(const float2*)(beta + col);
                float2 ov;
                ov.x = (acc[mf][nf][rr * 2]     - mu) * rstd * gv.x + tv.x;
                ov.y = (acc[mf][nf][rr * 2 + 1] - mu) * rstd * gv.y + tv.y;
                *(float2*)(orow + col) = ov;
            }
        }
    }
}

// ------------------------------ launch ----------------------------------------
// Input order per metadata (dict insertion order in setup_inputs):
//   0:x 1:Wq 2:Wk 3:Wv 4:Wo 5:bq 6:bk 7:bv 8:bo 9:gamma 10:beta 11:num_heads
extern "C" void kernel_launch(void* const* d_in, const int* in_sizes, int n_in,
                              void* d_out, int out_size) {
    const float* x     = (const float*)d_in[0];
    const float* Wq    = (const float*)d_in[1];
    const float* Wk    = (const float*)d_in[2];
    const float* Wv    = (const float*)d_in[3];
    const float* Wo    = (const float*)d_in[4];
    const float* bq    = (const float*)d_in[5];
    const float* bk    = (const float*)d_in[6];
    const float* bv    = (const float*)d_in[7];
    const float* bo    = (const float*)d_in[8];
    const float* gamma = (const float*)d_in[9];
    const float* beta  = (const float*)d_in[10];
    float* out = (float*)d_out;

    // idempotent; host-side attribute set (not a stream op, graph-capture safe)
    cudaFuncSetAttribute(qkv_gemm_kernel, cudaFuncAttributeMaxDynamicSharedMemorySize, QKV_SMEM);
    cudaFuncSetAttribute(attn_mma_kernel, cudaFuncAttributeMaxDynamicSharedMemorySize, ATTN_SMEM);
    cudaFuncSetAttribute(oproj_ln_kernel, cudaFuncAttributeMaxDynamicSharedMemorySize, OPROJ_SMEM);

    pe_kernel<<<256, 256>>>();
    addpe_split_kernel<<<4096, 256>>>(x);
    wsplit_all_kernel<<<1024, 256>>>(Wq, bq, Wk, bk, Wv, bv, Wo);
    qkv_gemm_kernel<<<dim3(6, 128), 256, QKV_SMEM>>>();
    attn_mma_kernel<<<dim3(4, H_, BN_), 256, ATTN_SMEM>>>();
    oproj_ln_kernel<<<256, 256, OPROJ_SMEM>>>(x, bo, gamma, beta, out);
}

// round 15
// speedup vs baseline: 1.4039x; 1.0640x over previous
#include <cuda_runtime.h>
#include <cuda_bf16.h>
#include <math.h>
#include <stdint.h>

// Problem constants (fixed by the dataset)
#define B_   4
#define S_   512
#define N_   8
#define D_   256
#define H_   8
#define HD_  32
#define BN_  (B_ * N_)          // 32
#define T_   (BN_ * S_)         // 16384 rows
#define QKVN 768                // 3*D

// ---------------- warp-mma helpers (baseline PTX, sm_80+) ---------------------
__device__ __forceinline__ uint32_t smem_u32(const void* p) {
    uint32_t a;
    asm("{ .reg .u64 t; cvta.to.shared.u64 t, %1; cvt.u32.u64 %0, t; }" : "=r"(a) : "l"(p));
    return a;
}
__device__ __forceinline__ void ldsm_x4(uint32_t& r0, uint32_t& r1, uint32_t& r2, uint32_t& r3,
                                        uint32_t addr) {
    asm volatile("ldmatrix.sync.aligned.m8n8.x4.shared.b16 {%0,%1,%2,%3}, [%4];"
        : "=r"(r0), "=r"(r1), "=r"(r2), "=r"(r3) : "r"(addr));
}
__device__ __forceinline__ void mma_bf16(float* c, const uint32_t* a, uint32_t b0, uint32_t b1) {
    asm volatile(
        "mma.sync.aligned.m16n8k16.row.col.f32.bf16.bf16.f32 "
        "{%0,%1,%2,%3}, {%4,%5,%6,%7}, {%8,%9}, {%0,%1,%2,%3};"
        : "+f"(c[0]), "+f"(c[1]), "+f"(c[2]), "+f"(c[3])
        : "r"(a[0]), "r"(a[1]), "r"(a[2]), "r"(a[3]), "r"(b0), "r"(b1));
}
__device__ __forceinline__ uint32_t bf16x2pack(float v0, float v1) {
    uint32_t r;
    asm("cvt.rn.bf16x2.f32 %0, %1, %2;" : "=r"(r) : "f"(v1), "f"(v0));
    return r;
}
__device__ __forceinline__ void split2(float v0, float v1, uint32_t& hi, uint32_t& lo) {
    hi = bf16x2pack(v0, v1);
    float h0 = __uint_as_float(hi << 16);
    float h1 = __uint_as_float(hi & 0xFFFF0000u);
    lo = bf16x2pack(v0 - h0, v1 - h1);
}
__device__ __forceinline__ void cp16(uint32_t dst, const void* src) {
    asm volatile("cp.async.cg.shared.global [%0], [%1], 16;" :: "r"(dst), "l"(src));
}
#define CP_COMMIT() asm volatile("cp.async.commit_group;" ::: "memory")
#define CP_WAIT2()  asm volatile("cp.async.wait_group 2;" ::: "memory")
#define CP_WAIT1()  asm volatile("cp.async.wait_group 1;" ::: "memory")
#define CP_WAIT0()  asm volatile("cp.async.wait_group 0;" ::: "memory")
#define SWZ128(off) ((off) ^ (((off) >> 3) & 0x70))
// SW64 for 64-byte-pitch rows: XOR 16B-column bits [5:4] with row bits [2:1].
#define SWZ64(off)  ((off) ^ (((off) >> 3) & 0x30))

// ---------------- scratch (device globals; no runtime allocation) -------------
__device__ float g_pe[S_ * D_];
__device__ __nv_bfloat16 g_a2[(long)T_ * 512];         // [hi(256)| (lo unused)] per row
__device__ __nv_bfloat16 g_w2[QKVN * 512];
__device__ __nv_bfloat16 g_wo2[D_ * 512];
__device__ float g_bcat[QKVN];
__device__ __nv_bfloat16 g_qh[(long)BN_ * H_ * S_ * HD_];   // [bnh][s][e] Q*scale hi
__device__ __nv_bfloat16 g_ql[(long)BN_ * H_ * S_ * HD_];
__device__ __nv_bfloat16 g_kh[(long)BN_ * H_ * S_ * HD_];
__device__ __nv_bfloat16 g_kl[(long)BN_ * H_ * S_ * HD_];
__device__ __nv_bfloat16 g_vth[(long)BN_ * H_ * HD_ * S_];  // [bnh][e][s]  V^T
__device__ __nv_bfloat16 g_vtl[(long)BN_ * H_ * HD_ * S_];
__device__ __nv_bfloat16 g_att2[(long)T_ * 512];       // only hi(256) used

// ---------------- 1) positional encoding table -------------------------------
__global__ void pe_kernel() {
    int idx = blockIdx.x * 256 + threadIdx.x;       // 65536 = S * D/2
    int s = idx >> 7;
    int i = idx & 127;
    float div = expf((float)(2 * i) * (-0.035977892078031970f)); // -ln(10000)/256
    float sn, cs;
    sincosf((float)s * div, &sn, &cs);
    g_pe[s * D_ + 2 * i]     = sn;
    g_pe[s * D_ + 2 * i + 1] = cs;
}

// ---------------- 2) x + pe -> bf16 hi only, (B,S,N,D)->(BN,S,D) --------------
// (the 2-term qkv GEMM never reads the A-lo half; skip computing/storing it)
__global__ void addpe_split_kernel(const float* __restrict__ x) {
    int idx = blockIdx.x * 256 + threadIdx.x;       // 1,048,576 groups of 4
    int d4 = idx & 63;
    int s  = (idx >> 6) & 511;
    int bn = idx >> 15;
    int b = bn >> 3, n = bn & 7;
    const float4 xv = *(const float4*)(x + ((((long)b * S_ + s) * N_ + n) * D_ + d4 * 4));
    const float4 pv = *(const float4*)(g_pe + (s * D_ + d4 * 4));
    long t = (long)bn * S_ + s;
    __nv_bfloat16* hb = g_a2 + t * 512 + d4 * 4;
    ((uint32_t*)hb)[0] = bf16x2pack(xv.x + pv.x, xv.y + pv.y);
    ((uint32_t*)hb)[1] = bf16x2pack(xv.z + pv.z, xv.w + pv.w);
}

// ---------------- 3) all weights: concat + hi/lo split (one launch) -----------
__global__ void wsplit_all_kernel(const float* __restrict__ Wq, const float* __restrict__ bq,
                                  const float* __restrict__ Wk, const float* __restrict__ bk,
                                  const float* __restrict__ Wv, const float* __restrict__ bv,
                                  const float* __restrict__ Wo) {
    int idx = blockIdx.x * 256 + threadIdx.x;       // 262144 = 1024 rows * 256
    int j = idx >> 8, k = idx & 255;
    int jj = j & 255;
    if (j < 768) {
        const float* src; const float* bsrc;
        if (j < 256)      { src = Wq; bsrc = bq; }
        else if (j < 512) { src = Wk; bsrc = bk; }
        else              { src = Wv; bsrc = bv; }
        float v = src[jj * D_ + k];
        __nv_bfloat16 h = __float2bfloat16(v);
        g_w2[j * 512 + k]       = h;
        g_w2[j * 512 + 256 + k] = __float2bfloat16(v - __bfloat162float(h));
        if (k == 0) g_bcat[j] = bsrc[jj];
    } else {
        float v = Wo[jj * D_ + k];
        __nv_bfloat16 h = __float2bfloat16(v);
        g_wo2[jj * 512 + k]       = h;
        g_wo2[jj * 512 + 256 + k] = __float2bfloat16(v - __bfloat162float(h));
    }
}

// ---------------- 4) qkv GEMM: 8 stages, A loaded once, Wh+Wl per stage -------
// C[16384,768] = Ah·(Wh+Wl)^T. Block 128x128, K-chunk 32, 4-buffer ring, SW64.
// Dynamic smem: A 4x8KB + W 4x16KB = 96KB (2 CTAs/SM).
#define QKV_SMEM (4 * 8192 + 4 * 16384)
__global__ void __launch_bounds__(256) qkv_gemm_kernel() {
    extern __shared__ __align__(128) char dsmem[];
    const int tid = threadIdx.x;
    const int wid = tid >> 5, lane = tid & 31;
    const int wm = wid & 3;          // 4 warps along M
    const int wn = wid >> 2;         // 2 warps along N
    const int mBase = blockIdx.y * 128;
    const int nBase = blockIdx.x * 128;

    const uint32_t baseA = smem_u32(dsmem);            // 4 bufs x 8KB
    const uint32_t baseW = baseA + 32768;              // 4 bufs x 16KB [Wh 8K | Wl 8K]

    float acc[2][8][4];
    #pragma unroll
    for (int i = 0; i < 2; ++i)
        #pragma unroll
        for (int j = 0; j < 8; ++j)
            #pragma unroll
            for (int q = 0; q < 4; ++q) acc[i][j][q] = 0.f;

    // stage s = K-chunk kc (0..7); per stage: A-hi chunk + Wh chunk + Wl chunk
    auto issue = [&](int s) {
        int buf = s & 3;
        #pragma unroll
        for (int i = 0; i < 2; ++i) {
            int f = i * 256 + tid;
            int row = f >> 2, c = f & 3;
            uint32_t so = SWZ64((uint32_t)(row * 64 + c * 16));
            cp16(baseA + (uint32_t)(buf * 8192) + so,
                 g_a2 + ((long)(mBase + row)) * 512 + s * 32 + c * 8);
            cp16(baseW + (uint32_t)(buf * 16384) + so,
                 g_w2 + ((long)(nBase + row)) * 512 + s * 32 + c * 8);          // Wh
            cp16(baseW + (uint32_t)(buf * 16384 + 8192) + so,
                 g_w2 + ((long)(nBase + row)) * 512 + 256 + s * 32 + c * 8);    // Wl
        }
    };

    issue(0); CP_COMMIT();
    issue(1); CP_COMMIT();
    issue(2); CP_COMMIT();

    for (int s = 0; s < 8; ++s) {
        if (s <= 5)      { CP_WAIT2(); }
        else if (s == 6) { CP_WAIT1(); }
        else             { CP_WAIT0(); }
        __syncthreads();   // single barrier per stage

        const int buf = s & 3;
        const uint32_t bA = baseA + buf * 8192;
        const uint32_t bW = baseW + buf * 16384;
        #pragma unroll
        for (int ks = 0; ks < 2; ++ks) {
            uint32_t a[2][4];
            #pragma unroll
            for (int mf = 0; mf < 2; ++mf) {
                uint32_t off = SWZ64((uint32_t)((wm * 32 + mf * 16 + (lane & 15)) * 64
                                                + ks * 32 + (lane >> 4) * 16));
                ldsm_x4(a[mf][0], a[mf][1], a[mf][2], a[mf][3], bA + off);
            }
            uint32_t bh[4][4], bl[4][4];
            #pragma unroll
            for (int g = 0; g < 4; ++g) {
                uint32_t off = SWZ64((uint32_t)((wn * 64 + g * 16 + (lane >> 4) * 8 + (lane & 7)) * 64
                                                + ks * 32 + ((lane >> 3) & 1) * 16));
                ldsm_x4(bh[g][0], bh[g][1], bh[g][2], bh[g][3], bW + off);
                ldsm_x4(bl[g][0], bl[g][1], bl[g][2], bl[g][3], bW + 8192 + off);
            }
            #pragma unroll
            for (int mf = 0; mf < 2; ++mf)
                #pragma unroll
                for (int nf = 0; nf < 8; ++nf) {
                    const uint32_t* bph = bh[nf >> 1];
                    const uint32_t* bpl = bl[nf >> 1];
                    int e0 = (nf & 1) * 2, e1 = e0 + 1;
                    mma_bf16(acc[mf][nf], a[mf], bph[e0], bph[e1]);
                    mma_bf16(acc[mf][nf], a[mf], bpl[e0], bpl[e1]);
                }
        }
        if (s + 3 < 8) { issue(s + 3); CP_COMMIT(); }   // buf (s+3)&3 != s&3
    }

    // epilogue: route to split Q (scaled) / K / V^T
    const int colq = (lane & 3) * 2;
    const float qscale = 0.17677669529663687f;   // 1/sqrt(32)
    #pragma unroll
    for (int mf = 0; mf < 2; ++mf) {
        int r0 = mBase + wm * 32 + mf * 16 + (lane >> 2);
        #pragma unroll
        for (int nf = 0; nf < 8; ++nf) {
            int col = nBase + wn * 64 + nf * 8 + colq;
            float bx = g_bcat[col], by = g_bcat[col + 1];
            float v00 = acc[mf][nf][0] + bx, v01 = acc[mf][nf][1] + by;   // row r0
            float v10 = acc[mf][nf][2] + bx, v11 = acc[mf][nf][3] + by;   // row r0+8
            int type = col >> 8, d = col & 255, hh = d >> 5, e = d & 31;
            if (type == 0) { v00 *= qscale; v01 *= qscale; v10 *= qscale; v11 *= qscale; }
            uint32_t h01, l01, h23, l23;
            split2(v00, v01, h01, l01);
            split2(v10, v11, h23, l23);
            int bnh0 = ((r0 >> 9) * H_ + hh);
            int s0 = r0 & 511;
            if (type < 2) {
                __nv_bfloat16* dh = type ? g_kh : g_qh;
                __nv_bfloat16* dl = type ? g_kl : g_ql;
                long a0 = ((long)bnh0 * S_ + s0) * HD_ + e;
                *(uint32_t*)(dh + a0)            = h01;
                *(uint32_t*)(dl + a0)            = l01;
                *(uint32_t*)(dh + a0 + 8 * HD_)  = h23;
                *(uint32_t*)(dl + a0 + 8 * HD_)  = l23;
            } else {
                long vb = ((long)bnh0 * HD_ + e) * S_ + s0;
                unsigned short* vh = (unsigned short*)g_vth;
                unsigned short* vl = (unsigned short*)g_vtl;
                vh[vb]           = (unsigned short)(h01 & 0xFFFF);
                vh[vb + S_]      = (unsigned short)(h01 >> 16);
                vh[vb + 8]       = (unsigned short)(h23 & 0xFFFF);
                vh[vb + S_ + 8]  = (unsigned short)(h23 >> 16);
                vl[vb]           = (unsigned short)(l01 & 0xFFFF);
                vl[vb + S_]      = (unsigned short)(l01 >> 16);
                vl[vb + 8]       = (unsigned short)(l23 & 0xFFFF);
                vl[vb + S_ + 8]  = (unsigned short)(l23 >> 16);
            }
        }
    }
}

// ---------------- 5) causal flash attention: pipelined K/V, 2-term P·V --------
// grid (4 q-tiles of 128, 8 heads, 32 bn); 8 warps; warp = 16 query rows.
// Dynamic smem: 3 buffers x 18KB, each [Kh(5K)|Kl(5K)|Vh(4K)|Vl(4K)].
#define ATTN_BUF   18432
#define ATTN_SMEM  (3 * ATTN_BUF)
__global__ void __launch_bounds__(256) attn_mma_kernel() {
    extern __shared__ __align__(128) char dsm[];
    __shared__ __align__(128)  __nv_bfloat16 sQh[128 * 40];
    __shared__ __align__(128)  __nv_bfloat16 sQl[128 * 40];
    const int tid = threadIdx.x, wid = tid >> 5, lane = tid & 31;
    const int qBase = blockIdx.x * 128;
    const int h = blockIdx.y, bn = blockIdx.z;
    const int bnh = bn * H_ + h;
    const int qw = qBase + wid * 16;
    const long kvoff = (long)bnh * S_ * HD_;
    const __nv_bfloat16* qhg = g_qh + kvoff;
    const __nv_bfloat16* qlg = g_ql + kvoff;
    const __nv_bfloat16* khg = g_kh + kvoff;
    const __nv_bfloat16* klg = g_kl + kvoff;
    const __nv_bfloat16* vhg = g_vth + kvoff;
    const __nv_bfloat16* vlg = g_vtl + kvoff;

    const uint32_t bufBase = smem_u32(dsm);
    const int nkt_w = (qw >> 6) + 1;          // tiles this warp computes
    const int nkt_b = (qBase >> 6) + 2;       // tiles the block loads

    auto issueKV = [&](int kt) {
        uint32_t bb = bufBase + (uint32_t)((kt % 3) * ATTN_BUF);
        int row = tid >> 2, c = tid & 3;
        cp16(bb + (uint32_t)(row * 80 + c * 16),        khg + (long)(kt * 64 + row) * 32 + c * 8);
        cp16(bb + 5120 + (uint32_t)(row * 80 + c * 16), klg + (long)(kt * 64 + row) * 32 + c * 8);
        int vr = tid >> 3, vc = tid & 7;
        uint32_t so = SWZ128((uint32_t)(vr * 128 + vc * 16));
        cp16(bb + 10240 + so, vhg + (long)vr * S_ + kt * 64 + vc * 8);
        cp16(bb + 14336 + so, vlg + (long)vr * S_ + kt * 64 + vc * 8);
    };

    issueKV(0); CP_COMMIT();
    issueKV(1); CP_COMMIT();           // nkt_b >= 2 always

    #pragma unroll
    for (int i = 0; i < 2; ++i) {
        int f = i * 256 + tid, row = f >> 2, c = f & 3;
        *(float4*)((char*)sQh + row * 80 + c * 16) = *(const float4*)(qhg + (long)(qBase + row) * 32 + c * 8);
        *(float4*)((char*)sQl + row * 80 + c * 16) = *(const float4*)(qlg + (long)(qBase + row) * 32 + c * 8);
    }
    __syncthreads();

    const uint32_t bQh = smem_u32(sQh), bQl = smem_u32(sQl);
    uint32_t qfh[2][4], qfl[2][4];
    #pragma unroll
    for (int ks = 0; ks < 2; ++ks) {
        uint32_t off = (uint32_t)((wid * 16 + (lane & 15)) * 80 + ks * 32 + (lane >> 4) * 16);
        ldsm_x4(qfh[ks][0], qfh[ks][1], qfh[ks][2], qfh[ks][3], bQh + off);
        ldsm_x4(qfl[ks][0], qfl[ks][1], qfl[ks][2], qfl[ks][3], bQl + off);
    }

    float o[4][4];
    #pragma unroll
    for (int i = 0; i < 4; ++i)
        #pragma unroll
        for (int j = 0; j < 4; ++j) o[i][j] = 0.f;
    float m0 = -1e30f, m1 = -1e30f, l0 = 0.f, l1 = 0.f;

    for (int kt = 0; kt < nkt_b; ++kt) {
        if (kt + 1 < nkt_b) { CP_WAIT1(); }
        else                { CP_WAIT0(); }
        __syncthreads();

        const uint32_t bb = bufBase + (uint32_t)((kt % 3) * ATTN_BUF);
        const uint32_t bKh = bb, bKl = bb + 5120, bVh = bb + 10240, bVl = bb + 14336;

        if (kt < nkt_w) {
            float s[8][4];
            #pragma unroll
            for (int nt = 0; nt < 8; ++nt)
                #pragma unroll
                for (int j = 0; j < 4; ++j) s[nt][j] = 0.f;

            #pragma unroll
            for (int ks = 0; ks < 2; ++ks) {
                uint32_t bh[4][4], bl[4][4];
                #pragma unroll
                for (int g = 0; g < 4; ++g) {
                    uint32_t off = (uint32_t)((g * 16 + (lane >> 4) * 8 + (lane & 7)) * 80
                                              + ks * 32 + ((lane >> 3) & 1) * 16);
                    ldsm_x4(bh[g][0], bh[g][1], bh[g][2], bh[g][3], bKh + off);
                    ldsm_x4(bl[g][0], bl[g][1], bl[g][2], bl[g][3], bKl + off);
                }
                #pragma unroll
                for (int nt = 0; nt < 8; ++nt) {
                    const uint32_t* ph = bh[nt >> 1];
                    const uint32_t* pl = bl[nt >> 1];
                    int e0 = (nt & 1) * 2, e1 = e0 + 1;
                    mma_bf16(s[nt], qfh[ks], ph[e0], ph[e1]);
                    mma_bf16(s[nt], qfh[ks], pl[e0], pl[e1]);
                    mma_bf16(s[nt], qfl[ks], ph[e0], ph[e1]);
                }
            }

            if (kt == (qw >> 6)) {
                int q0 = qw + (lane >> 2), q1 = q0 + 8;
                #pragma unroll
                for (int nt = 0; nt < 8; ++nt) {
                    int k0 = kt * 64 + nt * 8 + ((lane & 3) << 1);
                    if (k0 > q0)     s[nt][0] = -1e9f;
                    if (k0 + 1 > q0) s[nt][1] = -1e9f;
                    if (k0 > q1)     s[nt][2] = -1e9f;
                    if (k0 + 1 > q1) s[nt][3] = -1e9f;
                }
            }

            float mx0 = -1e30f, mx1 = -1e30f;
            #pragma unroll
            for (int nt = 0; nt < 8; ++nt) {
                mx0 = fmaxf(mx0, fmaxf(s[nt][0], s[nt][1]));
                mx1 = fmaxf(mx1, fmaxf(s[nt][2], s[nt][3]));
            }
            mx0 = fmaxf(mx0, __shfl_xor_sync(0xFFFFFFFFu, mx0, 1));
            mx0 = fmaxf(mx0, __shfl_xor_sync(0xFFFFFFFFu, mx0, 2));
            mx1 = fmaxf(mx1, __shfl_xor_sync(0xFFFFFFFFu, mx1, 1));
            mx1 = fmaxf(mx1, __shfl_xor_sync(0xFFFFFFFFu, mx1, 2));
            float nm0 = fmaxf(m0, mx0), nm1 = fmaxf(m1, mx1);
            float a0 = __expf(m0 - nm0), a1 = __expf(m1 - nm1);
            m0 = nm0; m1 = nm1;

            float sum0 = 0.f, sum1 = 0.f;
            uint32_t aph[4][4];                    // P hi only (2-term P·V)
            #pragma unroll
            for (int nt = 0; nt < 8; ++nt) {
                float p0 = __expf(s[nt][0] - m0), p1 = __expf(s[nt][1] - m0);
                float p2 = __expf(s[nt][2] - m1), p3 = __expf(s[nt][3] - m1);
                sum0 += p0 + p1; sum1 += p2 + p3;
                int kk = nt >> 1, r = (nt & 1) * 2;
                aph[kk][r]     = bf16x2pack(p0, p1);
                aph[kk][r + 1] = bf16x2pack(p2, p3);
            }
            sum0 += __shfl_xor_sync(0xFFFFFFFFu, sum0, 1);
            sum0 += __shfl_xor_sync(0xFFFFFFFFu, sum0, 2);
            sum1 += __shfl_xor_sync(0xFFFFFFFFu, sum1, 1);
            sum1 += __shfl_xor_sync(0xFFFFFFFFu, sum1, 2);
            l0 = l0 * a0 + sum0;
            l1 = l1 * a1 + sum1;
            #pragma unroll
            for (int nt = 0; nt < 4; ++nt) {
                o[nt][0] *= a0; o[nt][1] *= a0;
                o[nt][2] *= a1; o[nt][3] *= a1;
            }

            #pragma unroll
            for (int kk = 0; kk < 4; ++kk) {
                uint32_t vh[2][4], vl[2][4];
                #pragma unroll
                for (int g = 0; g < 2; ++g) {
                    uint32_t off = SWZ128((uint32_t)((g * 16 + (lane >> 4) * 8 + (lane & 7)) * 128
                                                     + kk * 32 + ((lane >> 3) & 1) * 16));
                    ldsm_x4(vh[g][0], vh[g][1], vh[g][2], vh[g][3], bVh + off);
                    ldsm_x4(vl[g][0], vl[g][1], vl[g][2], vl[g][3], bVl + off);
                }
                #pragma unroll
                for (int nt = 0; nt < 4; ++nt) {
                    const uint32_t* ph = vh[nt >> 1];
                    const uint32_t* pl = vl[nt >> 1];
                    int e0 = (nt & 1) * 2, e1 = e0 + 1;
                    mma_bf16(o[nt], aph[kk], ph[e0], ph[e1]);
                    mma_bf16(o[nt], aph[kk], pl[e0], pl[e1]);
                }
            }
        }

        if (kt + 2 < nkt_b) { issueKV(kt + 2); CP_COMMIT(); }
    }

    // epilogue: normalize, write hi-only bf16 attention output
    float i0 = 1.f / l0, i1 = 1.f / l1;
    long t0 = (long)bn * S_ + qw + (lane >> 2);
    #pragma unroll
    for (int nt = 0; nt < 4; ++nt) {
        int col = h * 32 + nt * 8 + ((lane & 3) << 1);
        *(uint32_t*)(g_att2 + t0 * 512 + col)       = bf16x2pack(o[nt][0] * i0, o[nt][1] * i0);
        *(uint32_t*)(g_att2 + (t0 + 8) * 512 + col) = bf16x2pack(o[nt][2] * i1, o[nt][3] * i1);
    }
}

// ---------------- 6) fused out-proj GEMM + bias + residual + LayerNorm --------
// 2-term split (Ah·Wh + Ah·Wl), 16 stages. Block 64x256, SW64. Writes d_out.
#define OPROJ_SMEM (4 * 4096 + 4 * 16384)
__global__ void __launch_bounds__(256) oproj_ln_kernel(
    const float* __restrict__ x,  const float* __restrict__ bo,
    const float* __restrict__ gamma, const float* __restrict__ beta,
    float* __restrict__ out)
{
    extern __shared__ __align__(128) char dsmem[];
    __shared__ float pSum[4][64], pSq[4][64];
    const int tid = threadIdx.x;
    const int wid = tid >> 5, lane = tid & 31;
    const int wm = wid & 1;          // 2 warps along M (32 rows each)
    const int wn = wid >> 1;         // 4 warps along N (64 cols each)
    const int mBase = blockIdx.x * 64;

    const uint32_t baseA = smem_u32(dsmem);            // 4 bufs x 4KB
    const uint32_t baseW = baseA + 16384;              // 4 bufs x 16KB

    float acc[2][8][4];
    #pragma unroll
    for (int i = 0; i < 2; ++i)
        #pragma unroll
        for (int j = 0; j < 8; ++j)
            #pragma unroll
            for (int q = 0; q < 4; ++q) acc[i][j][q] = 0.f;

    auto issue = [&](int s) {
        int buf = s & 3;
        int t = s >> 3, kc = s & 7;
        int aoff = kc * 32;                          // A hi always
        int woff = ((t == 1) ? 256 : 0) + kc * 32;   // W hi then lo
        {
            int row = tid >> 2, c = tid & 3;
            uint32_t so = SWZ64((uint32_t)(row * 64 + c * 16));
            cp16(baseA + (uint32_t)(buf * 4096) + so,
                 g_att2 + ((long)(mBase + row)) * 512 + aoff + c * 8);
        }
        #pragma unroll
        for (int i = 0; i < 4; ++i) {
            int f = i * 256 + tid;
            int row = f >> 2, c = f & 3;
            uint32_t so = SWZ64((uint32_t)(row * 64 + c * 16));
            cp16(baseW + (uint32_t)(buf * 16384) + so,
                 g_wo2 + ((long)row) * 512 + woff + c * 8);
        }
    };

    issue(0); CP_COMMIT();
    issue(1); CP_COMMIT();
    issue(2); CP_COMMIT();

    for (int s = 0; s < 16; ++s) {
        if (s <= 13)      { CP_WAIT2(); }
        else if (s == 14) { CP_WAIT1(); }
        else              { CP_WAIT0(); }
        __syncthreads();

        const int buf = s & 3;
        const uint32_t bA = baseA + buf * 4096;
        const uint32_t bW = baseW + buf * 16384;
        #pragma unroll
        for (int ks = 0; ks < 2; ++ks) {
            uint32_t a[2][4];
            #pragma unroll
            for (int mf = 0; mf < 2; ++mf) {
                uint32_t off = SWZ64((uint32_t)((wm * 32 + mf * 16 + (lane & 15)) * 64
                                                + ks * 32 + (lane >> 4) * 16));
                ldsm_x4(a[mf][0], a[mf][1], a[mf][2], a[mf][3], bA + off);
            }
            uint32_t b[4][4];
            #pragma unroll
            for (int g = 0; g < 4; ++g) {
                uint32_t off = SWZ64((uint32_t)((wn * 64 + g * 16 + (lane >> 4) * 8 + (lane & 7)) * 64
                                                + ks * 32 + ((lane >> 3) & 1) * 16));
                ldsm_x4(b[g][0], b[g][1], b[g][2], b[g][3], bW + off);
            }
            #pragma unroll
            for (int mf = 0; mf < 2; ++mf)
                #pragma unroll
                for (int nf = 0; nf < 8; ++nf) {
                    const uint32_t* bp = b[nf >> 1];
                    if (nf & 1) mma_bf16(acc[mf][nf], a[mf], bp[2], bp[3]);
                    else        mma_bf16(acc[mf][nf], a[mf], bp[0], bp[1]);
                }
        }
        if (s + 3 < 16) { issue(s + 3); CP_COMMIT(); }
    }
    __syncthreads();

    // epilogue: add bias + residual, per-row LN across warps, write d_out
    const int colq = (lane & 3) * 2;
    #pragma unroll
    for (int mf = 0; mf < 2; ++mf) {
        #pragma unroll
        for (int rr = 0; rr < 2; ++rr) {
            int rl = wm * 32 + mf * 16 + rr * 8 + (lane >> 2);   // local row 0..63
            int t = mBase + rl;
            int bnn = t >> 9, ss = t & 511;
            int bb = bnn >> 3, nn = bnn & 7;
            const float* xrow = x + (((long)(bb * S_ + ss)) * N_ + nn) * D_;
            float sum = 0.f, sq = 0.f;
            #pragma unroll
            for (int nf = 0; nf < 8; ++nf) {
                int col = wn * 64 + nf * 8 + colq;
                float2 xv = *(const float2*)(xrow + col);
                float2 bv = *(const float2*)(bo + col);
                float v0 = acc[mf][nf][rr * 2]     + xv.x + bv.x;
                float v1 = acc[mf][nf][rr * 2 + 1] + xv.y + bv.y;
                acc[mf][nf][rr * 2]     = v0;
                acc[mf][nf][rr * 2 + 1] = v1;
                sum += v0 + v1;
                sq = fmaf(v0, v0, sq);
                sq = fmaf(v1, v1, sq);
            }
            sum += __shfl_xor_sync(0xFFFFFFFFu, sum, 1);
            sum += __shfl_xor_sync(0xFFFFFFFFu, sum, 2);
            sq  += __shfl_xor_sync(0xFFFFFFFFu, sq,  1);
            sq  += __shfl_xor_sync(0xFFFFFFFFu, sq,  2);
            if ((lane & 3) == 0) {
                pSum[wn][rl] = sum;
                pSq[wn][rl]  = sq;
            }
        }
    }
    __syncthreads();

    #pragma unroll
    for (int mf = 0; mf < 2; ++mf) {
        #pragma unroll
        for (int rr = 0; rr < 2; ++rr) {
            int rl = wm * 32 + mf * 16 + rr * 8 + (lane >> 2);
            int t = mBase + rl;
            int bnn = t >> 9, ss = t & 511;
            int bb = bnn >> 3, nn = bnn & 7;
            float S  = pSum[0][rl] + pSum[1][rl] + pSum[2][rl] + pSum[3][rl];
            float Q  = pSq[0][rl]  + pSq[1][rl]  + pSq[2][rl]  + pSq[3][rl];
            float mu = S * (1.f / 256.f);
            float var = Q * (1.f / 256.f) - mu * mu;
            float rstd = rsqrtf(var + 1e-5f);
            float* orow = out + (((long)(bb * S_ + ss)) * N_ + nn) * D_;
            #pragma unroll
            for (int nf = 0; nf < 8; ++nf) {
                int col = wn * 64 + nf * 8 + colq;
                float2 gv = *(const float2*)(gamma + col);
                float2 tv = *(const float2*)(beta + col);
                float2 ov;
                ov.x = (acc[mf][nf][rr * 2]     - mu) * rstd * gv.x + tv.x;
                ov.y = (acc[mf][nf][rr * 2 + 1] - mu) * rstd * gv.y + tv.y;
                *(float2*)(orow + col) = ov;
            }
        }
    }
}

// ------------------------------ launch ----------------------------------------
// Input order per metadata (dict insertion order in setup_inputs):
//   0:x 1:Wq 2:Wk 3:Wv 4:Wo 5:bq 6:bk 7:bv 8:bo 9:gamma 10:beta 11:num_heads
extern "C" void kernel_launch(void* const* d_in, const int* in_sizes, int n_in,
                              void* d_out, int out_size) {
    const float* x     = (const float*)d_in[0];
    const float* Wq    = (const float*)d_in[1];
    const float* Wk    = (const float*)d_in[2];
    const float* Wv    = (const float*)d_in[3];
    const float* Wo    = (const float*)d_in[4];
    const float* bq    = (const float*)d_in[5];
    const float* bk    = (const float*)d_in[6];
    const float* bv    = (const float*)d_in[7];
    const float* bo    = (const float*)d_in[8];
    const float* gamma = (const float*)d_in[9];
    const float* beta  = (const float*)d_in[10];
    float* out = (float*)d_out;

    // idempotent; host-side attribute set (not a stream op, graph-capture safe)
    cudaFuncSetAttribute(qkv_gemm_kernel, cudaFuncAttributeMaxDynamicSharedMemorySize, QKV_SMEM);
    cudaFuncSetAttribute(attn_mma_kernel, cudaFuncAttributeMaxDynamicSharedMemorySize, ATTN_SMEM);
    cudaFuncSetAttribute(oproj_ln_kernel, cudaFuncAttributeMaxDynamicSharedMemorySize, OPROJ_SMEM);

    pe_kernel<<<256, 256>>>();
    addpe_split_kernel<<<4096, 256>>>(x);
    wsplit_all_kernel<<<1024, 256>>>(Wq, bq, Wk, bk, Wv, bv, Wo);
    qkv_gemm_kernel<<<dim3(6, 128), 256, QKV_SMEM>>>();
    attn_mma_kernel<<<dim3(4, H_, BN_), 256, ATTN_SMEM>>>();
    oproj_ln_kernel<<<256, 256, OPROJ_SMEM>>>(x, bo, gamma, beta, out);
}

// round 16
// speedup vs baseline: 1.5353x; 1.0936x over previous
#include <cuda_runtime.h>
#include <cuda_bf16.h>
#include <math.h>
#include <stdint.h>

// Problem constants (fixed by the dataset)
#define B_   4
#define S_   512
#define N_   8
#define D_   256
#define H_   8
#define HD_  32
#define BN_  (B_ * N_)          // 32
#define T_   (BN_ * S_)         // 16384 rows
#define QKVN 768                // 3*D

// ---------------- warp-mma helpers (baseline PTX, sm_80+) ---------------------
__device__ __forceinline__ uint32_t smem_u32(const void* p) {
    uint32_t a;
    asm("{ .reg .u64 t; cvta.to.shared.u64 t, %1; cvt.u32.u64 %0, t; }" : "=r"(a) : "l"(p));
    return a;
}
__device__ __forceinline__ void ldsm_x4(uint32_t& r0, uint32_t& r1, uint32_t& r2, uint32_t& r3,
                                        uint32_t addr) {
    asm volatile("ldmatrix.sync.aligned.m8n8.x4.shared.b16 {%0,%1,%2,%3}, [%4];"
        : "=r"(r0), "=r"(r1), "=r"(r2), "=r"(r3) : "r"(addr));
}
__device__ __forceinline__ void mma_bf16(float* c, const uint32_t* a, uint32_t b0, uint32_t b1) {
    asm volatile(
        "mma.sync.aligned.m16n8k16.row.col.f32.bf16.bf16.f32 "
        "{%0,%1,%2,%3}, {%4,%5,%6,%7}, {%8,%9}, {%0,%1,%2,%3};"
        : "+f"(c[0]), "+f"(c[1]), "+f"(c[2]), "+f"(c[3])
        : "r"(a[0]), "r"(a[1]), "r"(a[2]), "r"(a[3]), "r"(b0), "r"(b1));
}
__device__ __forceinline__ uint32_t bf16x2pack(float v0, float v1) {
    uint32_t r;
    asm("cvt.rn.bf16x2.f32 %0, %1, %2;" : "=r"(r) : "f"(v1), "f"(v0));
    return r;
}
__device__ __forceinline__ void split2(float v0, float v1, uint32_t& hi, uint32_t& lo) {
    hi = bf16x2pack(v0, v1);
    float h0 = __uint_as_float(hi << 16);
    float h1 = __uint_as_float(hi & 0xFFFF0000u);
    lo = bf16x2pack(v0 - h0, v1 - h1);
}
__device__ __forceinline__ void cp16(uint32_t dst, const void* src) {
    asm volatile("cp.async.cg.shared.global [%0], [%1], 16;" :: "r"(dst), "l"(src));
}
#define CP_COMMIT() asm volatile("cp.async.commit_group;" ::: "memory")
#define CP_WAIT2()  asm volatile("cp.async.wait_group 2;" ::: "memory")
#define CP_WAIT1()  asm volatile("cp.async.wait_group 1;" ::: "memory")
#define CP_WAIT0()  asm volatile("cp.async.wait_group 0;" ::: "memory")
#define SWZ128(off) ((off) ^ (((off) >> 3) & 0x70))
// SW64 for 64-byte-pitch rows: XOR 16B-column bits [5:4] with row bits [2:1].
#define SWZ64(off)  ((off) ^ (((off) >> 3) & 0x30))

// ---------------- scratch (device globals; no runtime allocation) -------------
__device__ float g_pe[S_ * D_];
__device__ __nv_bfloat16 g_a2[(long)T_ * 512];         // [hi(256)| (lo unused)] per row
__device__ __nv_bfloat16 g_w2[QKVN * 512];
__device__ __nv_bfloat16 g_wo2[D_ * 512];
__device__ float g_bcat[QKVN];
__device__ __nv_bfloat16 g_qh[(long)BN_ * H_ * S_ * HD_];   // [bnh][s][e] Q*scale hi
__device__ __nv_bfloat16 g_ql[(long)BN_ * H_ * S_ * HD_];   // Q*scale lo
__device__ __nv_bfloat16 g_kh[(long)BN_ * H_ * S_ * HD_];   // K hi only
__device__ __nv_bfloat16 g_vth[(long)BN_ * H_ * HD_ * S_];  // [bnh][e][s]  V^T hi only
__device__ __nv_bfloat16 g_att2[(long)T_ * 512];       // only hi(256) used

// ---------------- 1) positional encoding table -------------------------------
__global__ void pe_kernel() {
    int idx = blockIdx.x * 256 + threadIdx.x;       // 65536 = S * D/2
    int s = idx >> 7;
    int i = idx & 127;
    float div = expf((float)(2 * i) * (-0.035977892078031970f)); // -ln(10000)/256
    float sn, cs;
    sincosf((float)s * div, &sn, &cs);
    g_pe[s * D_ + 2 * i]     = sn;
    g_pe[s * D_ + 2 * i + 1] = cs;
}

// ---------------- 2) x + pe -> bf16 hi only, (B,S,N,D)->(BN,S,D) --------------
__global__ void addpe_split_kernel(const float* __restrict__ x) {
    int idx = blockIdx.x * 256 + threadIdx.x;       // 1,048,576 groups of 4
    int d4 = idx & 63;
    int s  = (idx >> 6) & 511;
    int bn = idx >> 15;
    int b = bn >> 3, n = bn & 7;
    const float4 xv = *(const float4*)(x + ((((long)b * S_ + s) * N_ + n) * D_ + d4 * 4));
    const float4 pv = *(const float4*)(g_pe + (s * D_ + d4 * 4));
    long t = (long)bn * S_ + s;
    __nv_bfloat16* hb = g_a2 + t * 512 + d4 * 4;
    ((uint32_t*)hb)[0] = bf16x2pack(xv.x + pv.x, xv.y + pv.y);
    ((uint32_t*)hb)[1] = bf16x2pack(xv.z + pv.z, xv.w + pv.w);
}

// ---------------- 3) all weights: concat + hi/lo split (one launch) -----------
__global__ void wsplit_all_kernel(const float* __restrict__ Wq, const float* __restrict__ bq,
                                  const float* __restrict__ Wk, const float* __restrict__ bk,
                                  const float* __restrict__ Wv, const float* __restrict__ bv,
                                  const float* __restrict__ Wo) {
    int idx = blockIdx.x * 256 + threadIdx.x;       // 262144 = 1024 rows * 256
    int j = idx >> 8, k = idx & 255;
    int jj = j & 255;
    if (j < 768) {
        const float* src; const float* bsrc;
        if (j < 256)      { src = Wq; bsrc = bq; }
        else if (j < 512) { src = Wk; bsrc = bk; }
        else              { src = Wv; bsrc = bv; }
        float v = src[jj * D_ + k];
        __nv_bfloat16 h = __float2bfloat16(v);
        g_w2[j * 512 + k]       = h;
        g_w2[j * 512 + 256 + k] = __float2bfloat16(v - __bfloat162float(h));
        if (k == 0) g_bcat[j] = bsrc[jj];
    } else {
        float v = Wo[jj * D_ + k];
        __nv_bfloat16 h = __float2bfloat16(v);
        g_wo2[jj * 512 + k]       = h;
        g_wo2[jj * 512 + 256 + k] = __float2bfloat16(v - __bfloat162float(h));
    }
}

// ---------------- 4) qkv GEMM: 8 stages, A loaded once, Wh+Wl per stage -------
// C[16384,768] = Ah·(Wh+Wl)^T. Block 128x128, K-chunk 32, 4-buffer ring, SW64.
#define QKV_SMEM (4 * 8192 + 4 * 16384)
__global__ void __launch_bounds__(256) qkv_gemm_kernel() {
    extern __shared__ __align__(128) char dsmem[];
    const int tid = threadIdx.x;
    const int wid = tid >> 5, lane = tid & 31;
    const int wm = wid & 3;          // 4 warps along M
    const int wn = wid >> 2;         // 2 warps along N
    const int mBase = blockIdx.y * 128;
    const int nBase = blockIdx.x * 128;

    const uint32_t baseA = smem_u32(dsmem);            // 4 bufs x 8KB
    const uint32_t baseW = baseA + 32768;              // 4 bufs x 16KB [Wh 8K | Wl 8K]

    float acc[2][8][4];
    #pragma unroll
    for (int i = 0; i < 2; ++i)
        #pragma unroll
        for (int j = 0; j < 8; ++j)
            #pragma unroll
            for (int q = 0; q < 4; ++q) acc[i][j][q] = 0.f;

    auto issue = [&](int s) {
        int buf = s & 3;
        #pragma unroll
        for (int i = 0; i < 2; ++i) {
            int f = i * 256 + tid;
            int row = f >> 2, c = f & 3;
            uint32_t so = SWZ64((uint32_t)(row * 64 + c * 16));
            cp16(baseA + (uint32_t)(buf * 8192) + so,
                 g_a2 + ((long)(mBase + row)) * 512 + s * 32 + c * 8);
            cp16(baseW + (uint32_t)(buf * 16384) + so,
                 g_w2 + ((long)(nBase + row)) * 512 + s * 32 + c * 8);          // Wh
            cp16(baseW + (uint32_t)(buf * 16384 + 8192) + so,
                 g_w2 + ((long)(nBase + row)) * 512 + 256 + s * 32 + c * 8);    // Wl
        }
    };

    issue(0); CP_COMMIT();
    issue(1); CP_COMMIT();
    issue(2); CP_COMMIT();

    for (int s = 0; s < 8; ++s) {
        if (s <= 5)      { CP_WAIT2(); }
        else if (s == 6) { CP_WAIT1(); }
        else             { CP_WAIT0(); }
        __syncthreads();   // single barrier per stage

        const int buf = s & 3;
        const uint32_t bA = baseA + buf * 8192;
        const uint32_t bW = baseW + buf * 16384;
        #pragma unroll
        for (int ks = 0; ks < 2; ++ks) {
            uint32_t a[2][4];
            #pragma unroll
            for (int mf = 0; mf < 2; ++mf) {
                uint32_t off = SWZ64((uint32_t)((wm * 32 + mf * 16 + (lane & 15)) * 64
                                                + ks * 32 + (lane >> 4) * 16));
                ldsm_x4(a[mf][0], a[mf][1], a[mf][2], a[mf][3], bA + off);
            }
            uint32_t bh[4][4], bl[4][4];
            #pragma unroll
            for (int g = 0; g < 4; ++g) {
                uint32_t off = SWZ64((uint32_t)((wn * 64 + g * 16 + (lane >> 4) * 8 + (lane & 7)) * 64
                                                + ks * 32 + ((lane >> 3) & 1) * 16));
                ldsm_x4(bh[g][0], bh[g][1], bh[g][2], bh[g][3], bW + off);
                ldsm_x4(bl[g][0], bl[g][1], bl[g][2], bl[g][3], bW + 8192 + off);
            }
            #pragma unroll
            for (int mf = 0; mf < 2; ++mf)
                #pragma unroll
                for (int nf = 0; nf < 8; ++nf) {
                    const uint32_t* bph = bh[nf >> 1];
                    const uint32_t* bpl = bl[nf >> 1];
                    int e0 = (nf & 1) * 2, e1 = e0 + 1;
                    mma_bf16(acc[mf][nf], a[mf], bph[e0], bph[e1]);
                    mma_bf16(acc[mf][nf], a[mf], bpl[e0], bpl[e1]);
                }
        }
        if (s + 3 < 8) { issue(s + 3); CP_COMMIT(); }   // buf (s+3)&3 != s&3
    }

    // epilogue: route to Q hi/lo (scaled), K hi, V^T hi
    const int colq = (lane & 3) * 2;
    const float qscale = 0.17677669529663687f;   // 1/sqrt(32)
    #pragma unroll
    for (int mf = 0; mf < 2; ++mf) {
        int r0 = mBase + wm * 32 + mf * 16 + (lane >> 2);
        #pragma unroll
        for (int nf = 0; nf < 8; ++nf) {
            int col = nBase + wn * 64 + nf * 8 + colq;
            float bx = g_bcat[col], by = g_bcat[col + 1];
            float v00 = acc[mf][nf][0] + bx, v01 = acc[mf][nf][1] + by;   // row r0
            float v10 = acc[mf][nf][2] + bx, v11 = acc[mf][nf][3] + by;   // row r0+8
            int type = col >> 8, d = col & 255, hh = d >> 5, e = d & 31;
            int bnh0 = ((r0 >> 9) * H_ + hh);
            int s0 = r0 & 511;
            if (type == 0) {            // Q: scaled, hi + lo
                v00 *= qscale; v01 *= qscale; v10 *= qscale; v11 *= qscale;
                uint32_t h01, l01, h23, l23;
                split2(v00, v01, h01, l01);
                split2(v10, v11, h23, l23);
                long a0 = ((long)bnh0 * S_ + s0) * HD_ + e;
                *(uint32_t*)(g_qh + a0)            = h01;
                *(uint32_t*)(g_ql + a0)            = l01;
                *(uint32_t*)(g_qh + a0 + 8 * HD_)  = h23;
                *(uint32_t*)(g_ql + a0 + 8 * HD_)  = l23;
            } else if (type == 1) {     // K: hi only
                long a0 = ((long)bnh0 * S_ + s0) * HD_ + e;
                *(uint32_t*)(g_kh + a0)           = bf16x2pack(v00, v01);
                *(uint32_t*)(g_kh + a0 + 8 * HD_) = bf16x2pack(v10, v11);
            } else {                    // V^T: hi only
                long vb = ((long)bnh0 * HD_ + e) * S_ + s0;
                uint32_t h01 = bf16x2pack(v00, v01);
                uint32_t h23 = bf16x2pack(v10, v11);
                unsigned short* vh = (unsigned short*)g_vth;
                vh[vb]           = (unsigned short)(h01 & 0xFFFF);
                vh[vb + S_]      = (unsigned short)(h01 >> 16);
                vh[vb + 8]       = (unsigned short)(h23 & 0xFFFF);
                vh[vb + S_ + 8]  = (unsigned short)(h23 >> 16);
            }
        }
    }
}

// ---------------- 5) causal flash attention: (Qh+Ql)·Kh, Ph·Vh ----------------
// grid (4 q-tiles of 128, 8 heads, 32 bn); 8 warps; warp = 16 query rows.
// Dynamic smem: 3 buffers x 9KB, each [Kh(5K)|Vh(4K)].
#define ATTN_BUF   9216
#define ATTN_SMEM  (3 * ATTN_BUF)
__global__ void __launch_bounds__(256) attn_mma_kernel() {
    extern __shared__ __align__(128) char dsm[];
    __shared__ __align__(128)  __nv_bfloat16 sQh[128 * 40];
    __shared__ __align__(128)  __nv_bfloat16 sQl[128 * 40];
    const int tid = threadIdx.x, wid = tid >> 5, lane = tid & 31;
    const int qBase = blockIdx.x * 128;
    const int h = blockIdx.y, bn = blockIdx.z;
    const int bnh = bn * H_ + h;
    const int qw = qBase + wid * 16;
    const long kvoff = (long)bnh * S_ * HD_;
    const __nv_bfloat16* qhg = g_qh + kvoff;
    const __nv_bfloat16* qlg = g_ql + kvoff;
    const __nv_bfloat16* khg = g_kh + kvoff;
    const __nv_bfloat16* vhg = g_vth + kvoff;

    const uint32_t bufBase = smem_u32(dsm);
    const int nkt_w = (qw >> 6) + 1;          // tiles this warp computes
    const int nkt_b = (qBase >> 6) + 2;       // tiles the block loads

    auto issueKV = [&](int kt) {
        uint32_t bb = bufBase + (uint32_t)((kt % 3) * ATTN_BUF);
        int row = tid >> 2, c = tid & 3;
        cp16(bb + (uint32_t)(row * 80 + c * 16), khg + (long)(kt * 64 + row) * 32 + c * 8);
        int vr = tid >> 3, vc = tid & 7;
        uint32_t so = SWZ128((uint32_t)(vr * 128 + vc * 16));
        cp16(bb + 5120 + so, vhg + (long)vr * S_ + kt * 64 + vc * 8);
    };

    issueKV(0); CP_COMMIT();
    issueKV(1); CP_COMMIT();           // nkt_b >= 2 always

    #pragma unroll
    for (int i = 0; i < 2; ++i) {
        int f = i * 256 + tid, row = f >> 2, c = f & 3;
        *(float4*)((char*)sQh + row * 80 + c * 16) = *(const float4*)(qhg + (long)(qBase + row) * 32 + c * 8);
        *(float4*)((char*)sQl + row * 80 + c * 16) = *(const float4*)(qlg + (long)(qBase + row) * 32 + c * 8);
    }
    __syncthreads();

    const uint32_t bQh = smem_u32(sQh), bQl = smem_u32(sQl);
    uint32_t qfh[2][4], qfl[2][4];
    #pragma unroll
    for (int ks = 0; ks < 2; ++ks) {
        uint32_t off = (uint32_t)((wid * 16 + (lane & 15)) * 80 + ks * 32 + (lane >> 4) * 16);
        ldsm_x4(qfh[ks][0], qfh[ks][1], qfh[ks][2], qfh[ks][3], bQh + off);
        ldsm_x4(qfl[ks][0], qfl[ks][1], qfl[ks][2], qfl[ks][3], bQl + off);
    }

    float o[4][4];
    #pragma unroll
    for (int i = 0; i < 4; ++i)
        #pragma unroll
        for (int j = 0; j < 4; ++j) o[i][j] = 0.f;
    float m0 = -1e30f, m1 = -1e30f, l0 = 0.f, l1 = 0.f;

    for (int kt = 0; kt < nkt_b; ++kt) {
        if (kt + 1 < nkt_b) { CP_WAIT1(); }
        else                { CP_WAIT0(); }
        __syncthreads();

        const uint32_t bb = bufBase + (uint32_t)((kt % 3) * ATTN_BUF);
        const uint32_t bKh = bb, bVh = bb + 5120;

        if (kt < nkt_w) {
            float s[8][4];
            #pragma unroll
            for (int nt = 0; nt < 8; ++nt)
                #pragma unroll
                for (int j = 0; j < 4; ++j) s[nt][j] = 0.f;

            #pragma unroll
            for (int ks = 0; ks < 2; ++ks) {
                uint32_t bh[4][4];
                #pragma unroll
                for (int g = 0; g < 4; ++g) {
                    uint32_t off = (uint32_t)((g * 16 + (lane >> 4) * 8 + (lane & 7)) * 80
                                              + ks * 32 + ((lane >> 3) & 1) * 16);
                    ldsm_x4(bh[g][0], bh[g][1], bh[g][2], bh[g][3], bKh + off);
                }
                #pragma unroll
                for (int nt = 0; nt < 8; ++nt) {
                    const uint32_t* ph = bh[nt >> 1];
                    int e0 = (nt & 1) * 2, e1 = e0 + 1;
                    mma_bf16(s[nt], qfh[ks], ph[e0], ph[e1]);
                    mma_bf16(s[nt], qfl[ks], ph[e0], ph[e1]);
                }
            }

            if (kt == (qw >> 6)) {
                int q0 = qw + (lane >> 2), q1 = q0 + 8;
                #pragma unroll
                for (int nt = 0; nt < 8; ++nt) {
                    int k0 = kt * 64 + nt * 8 + ((lane & 3) << 1);
                    if (k0 > q0)     s[nt][0] = -1e9f;
                    if (k0 + 1 > q0) s[nt][1] = -1e9f;
                    if (k0 > q1)     s[nt][2] = -1e9f;
                    if (k0 + 1 > q1) s[nt][3] = -1e9f;
                }
            }

            float mx0 = -1e30f, mx1 = -1e30f;
            #pragma unroll
            for (int nt = 0; nt < 8; ++nt) {
                mx0 = fmaxf(mx0, fmaxf(s[nt][0], s[nt][1]));
                mx1 = fmaxf(mx1, fmaxf(s[nt][2], s[nt][3]));
            }
            mx0 = fmaxf(mx0, __shfl_xor_sync(0xFFFFFFFFu, mx0, 1));
            mx0 = fmaxf(mx0, __shfl_xor_sync(0xFFFFFFFFu, mx0, 2));
            mx1 = fmaxf(mx1, __shfl_xor_sync(0xFFFFFFFFu, mx1, 1));
            mx1 = fmaxf(mx1, __shfl_xor_sync(0xFFFFFFFFu, mx1, 2));
            float nm0 = fmaxf(m0, mx0), nm1 = fmaxf(m1, mx1);
            float a0 = __expf(m0 - nm0), a1 = __expf(m1 - nm1);
            m0 = nm0; m1 = nm1;

            float sum0 = 0.f, sum1 = 0.f;
            uint32_t aph[4][4];                    // P hi only
            #pragma unroll
            for (int nt = 0; nt < 8; ++nt) {
                float p0 = __expf(s[nt][0] - m0), p1 = __expf(s[nt][1] - m0);
                float p2 = __expf(s[nt][2] - m1), p3 = __expf(s[nt][3] - m1);
                sum0 += p0 + p1; sum1 += p2 + p3;
                int kk = nt >> 1, r = (nt & 1) * 2;
                aph[kk][r]     = bf16x2pack(p0, p1);
                aph[kk][r + 1] = bf16x2pack(p2, p3);
            }
            sum0 += __shfl_xor_sync(0xFFFFFFFFu, sum0, 1);
            sum0 += __shfl_xor_sync(0xFFFFFFFFu, sum0, 2);
            sum1 += __shfl_xor_sync(0xFFFFFFFFu, sum1, 1);
            sum1 += __shfl_xor_sync(0xFFFFFFFFu, sum1, 2);
            l0 = l0 * a0 + sum0;
            l1 = l1 * a1 + sum1;
            #pragma unroll
            for (int nt = 0; nt < 4; ++nt) {
                o[nt][0] *= a0; o[nt][1] *= a0;
                o[nt][2] *= a1; o[nt][3] *= a1;
            }

            #pragma unroll
            for (int kk = 0; kk < 4; ++kk) {
                uint32_t vh[2][4];
                #pragma unroll
                for (int g = 0; g < 2; ++g) {
                    uint32_t off = SWZ128((uint32_t)((g * 16 + (lane >> 4) * 8 + (lane & 7)) * 128
                                                     + kk * 32 + ((lane >> 3) & 1) * 16));
                    ldsm_x4(vh[g][0], vh[g][1], vh[g][2], vh[g][3], bVh + off);
                }
                #pragma unroll
                for (int nt = 0; nt < 4; ++nt) {
                    const uint32_t* ph = vh[nt >> 1];
                    int e0 = (nt & 1) * 2, e1 = e0 + 1;
                    mma_bf16(o[nt], aph[kk], ph[e0], ph[e1]);
                }
            }
        }

        if (kt + 2 < nkt_b) { issueKV(kt + 2); CP_COMMIT(); }
    }

    // epilogue: normalize, write hi-only bf16 attention output
    float i0 = 1.f / l0, i1 = 1.f / l1;
    long t0 = (long)bn * S_ + qw + (lane >> 2);
    #pragma unroll
    for (int nt = 0; nt < 4; ++nt) {
        int col = h * 32 + nt * 8 + ((lane & 3) << 1);
        *(uint32_t*)(g_att2 + t0 * 512 + col)       = bf16x2pack(o[nt][0] * i0, o[nt][1] * i0);
        *(uint32_t*)(g_att2 + (t0 + 8) * 512 + col) = bf16x2pack(o[nt][2] * i1, o[nt][3] * i1);
    }
}

// ---------------- 6) fused out-proj GEMM + bias + residual + LayerNorm --------
// 2-term split (Ah·Wh + Ah·Wl), 16 stages. Block 64x256, SW64. Writes d_out.
#define OPROJ_SMEM (4 * 4096 + 4 * 16384)
__global__ void __launch_bounds__(256) oproj_ln_kernel(
    const float* __restrict__ x,  const float* __restrict__ bo,
    const float* __restrict__ gamma, const float* __restrict__ beta,
    float* __restrict__ out)
{
    extern __shared__ __align__(128) char dsmem[];
    __shared__ float pSum[4][64], pSq[4][64];
    const int tid = threadIdx.x;
    const int wid = tid >> 5, lane = tid & 31;
    const int wm = wid & 1;          // 2 warps along M (32 rows each)
    const int wn = wid >> 1;         // 4 warps along N (64 cols each)
    const int mBase = blockIdx.x * 64;

    const uint32_t baseA = smem_u32(dsmem);            // 4 bufs x 4KB
    const uint32_t baseW = baseA + 16384;              // 4 bufs x 16KB

    float acc[2][8][4];
    #pragma unroll
    for (int i = 0; i < 2; ++i)
        #pragma unroll
        for (int j = 0; j < 8; ++j)
            #pragma unroll
            for (int q = 0; q < 4; ++q) acc[i][j][q] = 0.f;

    auto issue = [&](int s) {
        int buf = s & 3;
        int t = s >> 3, kc = s & 7;
        int aoff = kc * 32;                          // A hi always
        int woff = ((t == 1) ? 256 : 0) + kc * 32;   // W hi then lo
        {
            int row = tid >> 2, c = tid & 3;
            uint32_t so = SWZ64((uint32_t)(row * 64 + c * 16));
            cp16(baseA + (uint32_t)(buf * 4096) + so,
                 g_att2 + ((long)(mBase + row)) * 512 + aoff + c * 8);
        }
        #pragma unroll
        for (int i = 0; i < 4; ++i) {
            int f = i * 256 + tid;
            int row = f >> 2, c = f & 3;
            uint32_t so = SWZ64((uint32_t)(row * 64 + c * 16));
            cp16(baseW + (uint32_t)(buf * 16384) + so,
                 g_wo2 + ((long)row) * 512 + woff + c * 8);
        }
    };

    issue(0); CP_COMMIT();
    issue(1); CP_COMMIT();
    issue(2); CP_COMMIT();

    for (int s = 0; s < 16; ++s) {
        if (s <= 13)      { CP_WAIT2(); }
        else if (s == 14) { CP_WAIT1(); }
        else              { CP_WAIT0(); }
        __syncthreads();

        const int buf = s & 3;
        const uint32_t bA = baseA + buf * 4096;
        const uint32_t bW = baseW + buf * 16384;
        #pragma unroll
        for (int ks = 0; ks < 2; ++ks) {
            uint32_t a[2][4];
            #pragma unroll
            for (int mf = 0; mf < 2; ++mf) {
                uint32_t off = SWZ64((uint32_t)((wm * 32 + mf * 16 + (lane & 15)) * 64
                                                + ks * 32 + (lane >> 4) * 16));
                ldsm_x4(a[mf][0], a[mf][1], a[mf][2], a[mf][3], bA + off);
            }
            uint32_t b[4][4];
            #pragma unroll
            for (int g = 0; g < 4; ++g) {
                uint32_t off = SWZ64((uint32_t)((wn * 64 + g * 16 + (lane >> 4) * 8 + (lane & 7)) * 64
                                                + ks * 32 + ((lane >> 3) & 1) * 16));
                ldsm_x4(b[g][0], b[g][1], b[g][2], b[g][3], bW + off);
            }
            #pragma unroll
            for (int mf = 0; mf < 2; ++mf)
                #pragma unroll
                for (int nf = 0; nf < 8; ++nf) {
                    const uint32_t* bp = b[nf >> 1];
                    if (nf & 1) mma_bf16(acc[mf][nf], a[mf], bp[2], bp[3]);
                    else        mma_bf16(acc[mf][nf], a[mf], bp[0], bp[1]);
                }
        }
        if (s + 3 < 16) { issue(s + 3); CP_COMMIT(); }
    }
    __syncthreads();

    // epilogue: add bias + residual, per-row LN across warps, write d_out
    const int colq = (lane & 3) * 2;
    #pragma unroll
    for (int mf = 0; mf < 2; ++mf) {
        #pragma unroll
        for (int rr = 0; rr < 2; ++rr) {
            int rl = wm * 32 + mf * 16 + rr * 8 + (lane >> 2);   // local row 0..63
            int t = mBase + rl;
            int bnn = t >> 9, ss = t & 511;
            int bb = bnn >> 3, nn = bnn & 7;
            const float* xrow = x + (((long)(bb * S_ + ss)) * N_ + nn) * D_;
            float sum = 0.f, sq = 0.f;
            #pragma unroll
            for (int nf = 0; nf < 8; ++nf) {
                int col = wn * 64 + nf * 8 + colq;
                float2 xv = *(const float2*)(xrow + col);
                float2 bv = *(const float2*)(bo + col);
                float v0 = acc[mf][nf][rr * 2]     + xv.x + bv.x;
                float v1 = acc[mf][nf][rr * 2 + 1] + xv.y + bv.y;
                acc[mf][nf][rr * 2]     = v0;
                acc[mf][nf][rr * 2 + 1] = v1;
                sum += v0 + v1;
                sq = fmaf(v0, v0, sq);
                sq = fmaf(v1, v1, sq);
            }
            sum += __shfl_xor_sync(0xFFFFFFFFu, sum, 1);
            sum += __shfl_xor_sync(0xFFFFFFFFu, sum, 2);
            sq  += __shfl_xor_sync(0xFFFFFFFFu, sq,  1);
            sq  += __shfl_xor_sync(0xFFFFFFFFu, sq,  2);
            if ((lane & 3) == 0) {
                pSum[wn][rl] = sum;
                pSq[wn][rl]  = sq;
            }
        }
    }
    __syncthreads();

    #pragma unroll
    for (int mf = 0; mf < 2; ++mf) {
        #pragma unroll
        for (int rr = 0; rr < 2; ++rr) {
            int rl = wm * 32 + mf * 16 + rr * 8 + (lane >> 2);
            int t = mBase + rl;
            int bnn = t >> 9, ss = t & 511;
            int bb = bnn >> 3, nn = bnn & 7;
            float S  = pSum[0][rl] + pSum[1][rl] + pSum[2][rl] + pSum[3][rl];
            float Q  = pSq[0][rl]  + pSq[1][rl]  + pSq[2][rl]  + pSq[3][rl];
            float mu = S * (1.f / 256.f);
            float var = Q * (1.f / 256.f) - mu * mu;
            float rstd = rsqrtf(var + 1e-5f);
            float* orow = out + (((long)(bb * S_ + ss)) * N_ + nn) * D_;
            #pragma unroll
            for (int nf = 0; nf < 8; ++nf) {
                int col = wn * 64 + nf * 8 + colq;
                float2 gv = *(const float2*)(gamma + col);
                float2 tv = *(const float2*)(beta + col);
                float2 ov;
                ov.x = (acc[mf][nf][rr * 2]     - mu) * rstd * gv.x + tv.x;
                ov.y = (acc[mf][nf][rr * 2 + 1] - mu) * rstd * gv.y + tv.y;
                *(float2*)(orow + col) = ov;
            }
        }
    }
}

// ------------------------------ launch ----------------------------------------
// Input order per metadata (dict insertion order in setup_inputs):
//   0:x 1:Wq 2:Wk 3:Wv 4:Wo 5:bq 6:bk 7:bv 8:bo 9:gamma 10:beta 11:num_heads
extern "C" void kernel_launch(void* const* d_in, const int* in_sizes, int n_in,
                              void* d_out, int out_size) {
    const float* x     = (const float*)d_in[0];
    const float* Wq    = (const float*)d_in[1];
    const float* Wk    = (const float*)d_in[2];
    const float* Wv    = (const float*)d_in[3];
    const float* Wo    = (const float*)d_in[4];
    const float* bq    = (const float*)d_in[5];
    const float* bk    = (const float*)d_in[6];
    const float* bv    = (const float*)d_in[7];
    const float* bo    = (const float*)d_in[8];
    const float* gamma = (const float*)d_in[9];
    const float* beta  = (const float*)d_in[10];
    float* out = (float*)d_out;

    // idempotent; host-side attribute set (not a stream op, graph-capture safe)
    cudaFuncSetAttribute(qkv_gemm_kernel, cudaFuncAttributeMaxDynamicSharedMemorySize, QKV_SMEM);
    cudaFuncSetAttribute(attn_mma_kernel, cudaFuncAttributeMaxDynamicSharedMemorySize, ATTN_SMEM);
    cudaFuncSetAttribute(oproj_ln_kernel, cudaFuncAttributeMaxDynamicSharedMemorySize, OPROJ_SMEM);

    pe_kernel<<<256, 256>>>();
    addpe_split_kernel<<<4096, 256>>>(x);
    wsplit_all_kernel<<<1024, 256>>>(Wq, bq, Wk, bk, Wv, bv, Wo);
    qkv_gemm_kernel<<<dim3(6, 128), 256, QKV_SMEM>>>();
    attn_mma_kernel<<<dim3(4, H_, BN_), 256, ATTN_SMEM>>>();
    oproj_ln_kernel<<<256, 256, OPROJ_SMEM>>>(x, bo, gamma, beta, out);
}

// round 17
// speedup vs baseline: 1.8195x; 1.1851x over previous
#include <cuda_runtime.h>
#include <cuda_bf16.h>
#include <math.h>
#include <stdint.h>

// Problem constants (fixed by the dataset)
#define B_   4
#define S_   512
#define N_   8
#define D_   256
#define H_   8
#define HD_  32
#define BN_  (B_ * N_)          // 32
#define T_   (BN_ * S_)         // 16384 rows
#define QKVN 768                // 3*D

// ---------------- warp-mma helpers (baseline PTX, sm_80+) ---------------------
__device__ __forceinline__ uint32_t smem_u32(const void* p) {
    uint32_t a;
    asm("{ .reg .u64 t; cvta.to.shared.u64 t, %1; cvt.u32.u64 %0, t; }" : "=r"(a) : "l"(p));
    return a;
}
__device__ __forceinline__ void ldsm_x4(uint32_t& r0, uint32_t& r1, uint32_t& r2, uint32_t& r3,
                                        uint32_t addr) {
    asm volatile("ldmatrix.sync.aligned.m8n8.x4.shared.b16 {%0,%1,%2,%3}, [%4];"
        : "=r"(r0), "=r"(r1), "=r"(r2), "=r"(r3) : "r"(addr));
}
__device__ __forceinline__ void mma_bf16(float* c, const uint32_t* a, uint32_t b0, uint32_t b1) {
    asm volatile(
        "mma.sync.aligned.m16n8k16.row.col.f32.bf16.bf16.f32 "
        "{%0,%1,%2,%3}, {%4,%5,%6,%7}, {%8,%9}, {%0,%1,%2,%3};"
        : "+f"(c[0]), "+f"(c[1]), "+f"(c[2]), "+f"(c[3])
        : "r"(a[0]), "r"(a[1]), "r"(a[2]), "r"(a[3]), "r"(b0), "r"(b1));
}
__device__ __forceinline__ uint32_t bf16x2pack(float v0, float v1) {
    uint32_t r;
    asm("cvt.rn.bf16x2.f32 %0, %1, %2;" : "=r"(r) : "f"(v1), "f"(v0));
    return r;
}
__device__ __forceinline__ void split2(float v0, float v1, uint32_t& hi, uint32_t& lo) {
    hi = bf16x2pack(v0, v1);
    float h0 = __uint_as_float(hi << 16);
    float h1 = __uint_as_float(hi & 0xFFFF0000u);
    lo = bf16x2pack(v0 - h0, v1 - h1);
}
__device__ __forceinline__ void cp16(uint32_t dst, const void* src) {
    asm volatile("cp.async.cg.shared.global [%0], [%1], 16;" :: "r"(dst), "l"(src));
}
#define CP_COMMIT() asm volatile("cp.async.commit_group;" ::: "memory")
#define CP_WAIT2()  asm volatile("cp.async.wait_group 2;" ::: "memory")
#define CP_WAIT1()  asm volatile("cp.async.wait_group 1;" ::: "memory")
#define CP_WAIT0()  asm volatile("cp.async.wait_group 0;" ::: "memory")
#define SWZ128(off) ((off) ^ (((off) >> 3) & 0x70))
// SW64 for 64-byte-pitch rows: XOR 16B-column bits [5:4] with row bits [2:1].
#define SWZ64(off)  ((off) ^ (((off) >> 3) & 0x30))

// ---------------- scratch (device globals; no runtime allocation) -------------
__device__ float g_pe[S_ * D_];
__device__ __nv_bfloat16 g_a2[(long)T_ * 512];         // [hi(256)] per row (lo unused)
__device__ __nv_bfloat16 g_w2[QKVN * 512];             // [hi(256)] per row (lo unused)
__device__ __nv_bfloat16 g_wo2[D_ * 512];              // [hi(256)] per row (lo unused)
__device__ float g_bcat[QKVN];
__device__ __nv_bfloat16 g_qh[(long)BN_ * H_ * S_ * HD_];   // [bnh][s][e] Q*scale hi
__device__ __nv_bfloat16 g_ql[(long)BN_ * H_ * S_ * HD_];   // Q*scale lo
__device__ __nv_bfloat16 g_kh[(long)BN_ * H_ * S_ * HD_];   // K hi only
__device__ __nv_bfloat16 g_vth[(long)BN_ * H_ * HD_ * S_];  // [bnh][e][s]  V^T hi only
__device__ __nv_bfloat16 g_att2[(long)T_ * 512];       // only hi(256) used

// ---------------- 1) positional encoding table -------------------------------
__global__ void pe_kernel() {
    int idx = blockIdx.x * 256 + threadIdx.x;       // 65536 = S * D/2
    int s = idx >> 7;
    int i = idx & 127;
    float div = expf((float)(2 * i) * (-0.035977892078031970f)); // -ln(10000)/256
    float sn, cs;
    sincosf((float)s * div, &sn, &cs);
    g_pe[s * D_ + 2 * i]     = sn;
    g_pe[s * D_ + 2 * i + 1] = cs;
}

// ---------------- 2) x + pe -> bf16 hi only, (B,S,N,D)->(BN,S,D) --------------
__global__ void addpe_split_kernel(const float* __restrict__ x) {
    int idx = blockIdx.x * 256 + threadIdx.x;       // 1,048,576 groups of 4
    int d4 = idx & 63;
    int s  = (idx >> 6) & 511;
    int bn = idx >> 15;
    int b = bn >> 3, n = bn & 7;
    const float4 xv = *(const float4*)(x + ((((long)b * S_ + s) * N_ + n) * D_ + d4 * 4));
    const float4 pv = *(const float4*)(g_pe + (s * D_ + d4 * 4));
    long t = (long)bn * S_ + s;
    __nv_bfloat16* hb = g_a2 + t * 512 + d4 * 4;
    ((uint32_t*)hb)[0] = bf16x2pack(xv.x + pv.x, xv.y + pv.y);
    ((uint32_t*)hb)[1] = bf16x2pack(xv.z + pv.z, xv.w + pv.w);
}

// ---------------- 3) all weights: concat, bf16 hi only (one launch) -----------
__global__ void wsplit_all_kernel(const float* __restrict__ Wq, const float* __restrict__ bq,
                                  const float* __restrict__ Wk, const float* __restrict__ bk,
                                  const float* __restrict__ Wv, const float* __restrict__ bv,
                                  const float* __restrict__ Wo) {
    int idx = blockIdx.x * 256 + threadIdx.x;       // 262144 = 1024 rows * 256
    int j = idx >> 8, k = idx & 255;
    int jj = j & 255;
    if (j < 768) {
        const float* src; const float* bsrc;
        if (j < 256)      { src = Wq; bsrc = bq; }
        else if (j < 512) { src = Wk; bsrc = bk; }
        else              { src = Wv; bsrc = bv; }
        g_w2[j * 512 + k] = __float2bfloat16(src[jj * D_ + k]);
        if (k == 0) g_bcat[j] = bsrc[jj];
    } else {
        g_wo2[jj * 512 + k] = __float2bfloat16(Wo[jj * D_ + k]);
    }
}

// ---------------- 4) qkv GEMM: pure bf16 (Ah·Wh), 8 stages --------------------
// C[16384,768]. Block 128x128, K-chunk 32, 4-buffer ring, SW64, 64KB smem.
// Epilogue writes Q hi/lo (scaled), K hi, V^T hi.
#define QKV_SMEM (4 * 8192 * 2)
__global__ void __launch_bounds__(256) qkv_gemm_kernel() {
    extern __shared__ __align__(128) char dsmem[];
    const int tid = threadIdx.x;
    const int wid = tid >> 5, lane = tid & 31;
    const int wm = wid & 3;          // 4 warps along M
    const int wn = wid >> 2;         // 2 warps along N
    const int mBase = blockIdx.y * 128;
    const int nBase = blockIdx.x * 128;

    const uint32_t baseA = smem_u32(dsmem);            // 4 bufs x 8KB
    const uint32_t baseW = baseA + 32768;              // 4 bufs x 8KB

    float acc[2][8][4];
    #pragma unroll
    for (int i = 0; i < 2; ++i)
        #pragma unroll
        for (int j = 0; j < 8; ++j)
            #pragma unroll
            for (int q = 0; q < 4; ++q) acc[i][j][q] = 0.f;

    auto issue = [&](int s) {
        int buf = s & 3;
        #pragma unroll
        for (int i = 0; i < 2; ++i) {
            int f = i * 256 + tid;
            int row = f >> 2, c = f & 3;
            uint32_t so = SWZ64((uint32_t)(row * 64 + c * 16));
            cp16(baseA + (uint32_t)(buf * 8192) + so,
                 g_a2 + ((long)(mBase + row)) * 512 + s * 32 + c * 8);
            cp16(baseW + (uint32_t)(buf * 8192) + so,
                 g_w2 + ((long)(nBase + row)) * 512 + s * 32 + c * 8);
        }
    };

    issue(0); CP_COMMIT();
    issue(1); CP_COMMIT();
    issue(2); CP_COMMIT();

    for (int s = 0; s < 8; ++s) {
        if (s <= 5)      { CP_WAIT2(); }
        else if (s == 6) { CP_WAIT1(); }
        else             { CP_WAIT0(); }
        __syncthreads();   // single barrier per stage

        const int buf = s & 3;
        const uint32_t bA = baseA + buf * 8192;
        const uint32_t bW = baseW + buf * 8192;
        #pragma unroll
        for (int ks = 0; ks < 2; ++ks) {
            uint32_t a[2][4];
            #pragma unroll
            for (int mf = 0; mf < 2; ++mf) {
                uint32_t off = SWZ64((uint32_t)((wm * 32 + mf * 16 + (lane & 15)) * 64
                                                + ks * 32 + (lane >> 4) * 16));
                ldsm_x4(a[mf][0], a[mf][1], a[mf][2], a[mf][3], bA + off);
            }
            uint32_t b[4][4];
            #pragma unroll
            for (int g = 0; g < 4; ++g) {
                uint32_t off = SWZ64((uint32_t)((wn * 64 + g * 16 + (lane >> 4) * 8 + (lane & 7)) * 64
                                                + ks * 32 + ((lane >> 3) & 1) * 16));
                ldsm_x4(b[g][0], b[g][1], b[g][2], b[g][3], bW + off);
            }
            #pragma unroll
            for (int mf = 0; mf < 2; ++mf)
                #pragma unroll
                for (int nf = 0; nf < 8; ++nf) {
                    const uint32_t* bp = b[nf >> 1];
                    if (nf & 1) mma_bf16(acc[mf][nf], a[mf], bp[2], bp[3]);
                    else        mma_bf16(acc[mf][nf], a[mf], bp[0], bp[1]);
                }
        }
        if (s + 3 < 8) { issue(s + 3); CP_COMMIT(); }   // buf (s+3)&3 != s&3
    }

    // epilogue: route to Q hi/lo (scaled), K hi, V^T hi
    const int colq = (lane & 3) * 2;
    const float qscale = 0.17677669529663687f;   // 1/sqrt(32)
    #pragma unroll
    for (int mf = 0; mf < 2; ++mf) {
        int r0 = mBase + wm * 32 + mf * 16 + (lane >> 2);
        #pragma unroll
        for (int nf = 0; nf < 8; ++nf) {
            int col = nBase + wn * 64 + nf * 8 + colq;
            float bx = g_bcat[col], by = g_bcat[col + 1];
            float v00 = acc[mf][nf][0] + bx, v01 = acc[mf][nf][1] + by;   // row r0
            float v10 = acc[mf][nf][2] + bx, v11 = acc[mf][nf][3] + by;   // row r0+8
            int type = col >> 8, d = col & 255, hh = d >> 5, e = d & 31;
            int bnh0 = ((r0 >> 9) * H_ + hh);
            int s0 = r0 & 511;
            if (type == 0) {            // Q: scaled, hi + lo
                v00 *= qscale; v01 *= qscale; v10 *= qscale; v11 *= qscale;
                uint32_t h01, l01, h23, l23;
                split2(v00, v01, h01, l01);
                split2(v10, v11, h23, l23);
                long a0 = ((long)bnh0 * S_ + s0) * HD_ + e;
                *(uint32_t*)(g_qh + a0)            = h01;
                *(uint32_t*)(g_ql + a0)            = l01;
                *(uint32_t*)(g_qh + a0 + 8 * HD_)  = h23;
                *(uint32_t*)(g_ql + a0 + 8 * HD_)  = l23;
            } else if (type == 1) {     // K: hi only
                long a0 = ((long)bnh0 * S_ + s0) * HD_ + e;
                *(uint32_t*)(g_kh + a0)           = bf16x2pack(v00, v01);
                *(uint32_t*)(g_kh + a0 + 8 * HD_) = bf16x2pack(v10, v11);
            } else {                    // V^T: hi only
                long vb = ((long)bnh0 * HD_ + e) * S_ + s0;
                uint32_t h01 = bf16x2pack(v00, v01);
                uint32_t h23 = bf16x2pack(v10, v11);
                unsigned short* vh = (unsigned short*)g_vth;
                vh[vb]           = (unsigned short)(h01 & 0xFFFF);
                vh[vb + S_]      = (unsigned short)(h01 >> 16);
                vh[vb + 8]       = (unsigned short)(h23 & 0xFFFF);
                vh[vb + S_ + 8]  = (unsigned short)(h23 >> 16);
            }
        }
    }
}

// ---------------- 5) causal flash attention: (Qh+Ql)·Kh, Ph·Vh ----------------
// grid (4 q-tiles of 128, 8 heads, 32 bn); 8 warps; warp = 16 query rows.
// Dynamic smem: 3 buffers x 9KB, each [Kh(5K)|Vh(4K)].
#define ATTN_BUF   9216
#define ATTN_SMEM  (3 * ATTN_BUF)
__global__ void __launch_bounds__(256) attn_mma_kernel() {
    extern __shared__ __align__(128) char dsm[];
    __shared__ __align__(128)  __nv_bfloat16 sQh[128 * 40];
    __shared__ __align__(128)  __nv_bfloat16 sQl[128 * 40];
    const int tid = threadIdx.x, wid = tid >> 5, lane = tid & 31;
    const int qBase = blockIdx.x * 128;
    const int h = blockIdx.y, bn = blockIdx.z;
    const int bnh = bn * H_ + h;
    const int qw = qBase + wid * 16;
    const long kvoff = (long)bnh * S_ * HD_;
    const __nv_bfloat16* qhg = g_qh + kvoff;
    const __nv_bfloat16* qlg = g_ql + kvoff;
    const __nv_bfloat16* khg = g_kh + kvoff;
    const __nv_bfloat16* vhg = g_vth + kvoff;

    const uint32_t bufBase = smem_u32(dsm);
    const int nkt_w = (qw >> 6) + 1;          // tiles this warp computes
    const int nkt_b = (qBase >> 6) + 2;       // tiles the block loads

    auto issueKV = [&](int kt) {
        uint32_t bb = bufBase + (uint32_t)((kt % 3) * ATTN_BUF);
        int row = tid >> 2, c = tid & 3;
        cp16(bb + (uint32_t)(row * 80 + c * 16), khg + (long)(kt * 64 + row) * 32 + c * 8);
        int vr = tid >> 3, vc = tid & 7;
        uint32_t so = SWZ128((uint32_t)(vr * 128 + vc * 16));
        cp16(bb + 5120 + so, vhg + (long)vr * S_ + kt * 64 + vc * 8);
    };

    issueKV(0); CP_COMMIT();
    issueKV(1); CP_COMMIT();           // nkt_b >= 2 always

    #pragma unroll
    for (int i = 0; i < 2; ++i) {
        int f = i * 256 + tid, row = f >> 2, c = f & 3;
        *(float4*)((char*)sQh + row * 80 + c * 16) = *(const float4*)(qhg + (long)(qBase + row) * 32 + c * 8);
        *(float4*)((char*)sQl + row * 80 + c * 16) = *(const float4*)(qlg + (long)(qBase + row) * 32 + c * 8);
    }
    __syncthreads();

    const uint32_t bQh = smem_u32(sQh), bQl = smem_u32(sQl);
    uint32_t qfh[2][4], qfl[2][4];
    #pragma unroll
    for (int ks = 0; ks < 2; ++ks) {
        uint32_t off = (uint32_t)((wid * 16 + (lane & 15)) * 80 + ks * 32 + (lane >> 4) * 16);
        ldsm_x4(qfh[ks][0], qfh[ks][1], qfh[ks][2], qfh[ks][3], bQh + off);
        ldsm_x4(qfl[ks][0], qfl[ks][1], qfl[ks][2], qfl[ks][3], bQl + off);
    }

    float o[4][4];
    #pragma unroll
    for (int i = 0; i < 4; ++i)
        #pragma unroll
        for (int j = 0; j < 4; ++j) o[i][j] = 0.f;
    float m0 = -1e30f, m1 = -1e30f, l0 = 0.f, l1 = 0.f;

    for (int kt = 0; kt < nkt_b; ++kt) {
        if (kt + 1 < nkt_b) { CP_WAIT1(); }
        else                { CP_WAIT0(); }
        __syncthreads();

        const uint32_t bb = bufBase + (uint32_t)((kt % 3) * ATTN_BUF);
        const uint32_t bKh = bb, bVh = bb + 5120;

        if (kt < nkt_w) {
            float s[8][4];
            #pragma unroll
            for (int nt = 0; nt < 8; ++nt)
                #pragma unroll
                for (int j = 0; j < 4; ++j) s[nt][j] = 0.f;

            #pragma unroll
            for (int ks = 0; ks < 2; ++ks) {
                uint32_t bh[4][4];
                #pragma unroll
                for (int g = 0; g < 4; ++g) {
                    uint32_t off = (uint32_t)((g * 16 + (lane >> 4) * 8 + (lane & 7)) * 80
                                              + ks * 32 + ((lane >> 3) & 1) * 16);
                    ldsm_x4(bh[g][0], bh[g][1], bh[g][2], bh[g][3], bKh + off);
                }
                #pragma unroll
                for (int nt = 0; nt < 8; ++nt) {
                    const uint32_t* ph = bh[nt >> 1];
                    int e0 = (nt & 1) * 2, e1 = e0 + 1;
                    mma_bf16(s[nt], qfh[ks], ph[e0], ph[e1]);
                    mma_bf16(s[nt], qfl[ks], ph[e0], ph[e1]);
                }
            }

            if (kt == (qw >> 6)) {
                int q0 = qw + (lane >> 2), q1 = q0 + 8;
                #pragma unroll
                for (int nt = 0; nt < 8; ++nt) {
                    int k0 = kt * 64 + nt * 8 + ((lane & 3) << 1);
                    if (k0 > q0)     s[nt][0] = -1e9f;
                    if (k0 + 1 > q0) s[nt][1] = -1e9f;
                    if (k0 > q1)     s[nt][2] = -1e9f;
                    if (k0 + 1 > q1) s[nt][3] = -1e9f;
                }
            }

            float mx0 = -1e30f, mx1 = -1e30f;
            #pragma unroll
            for (int nt = 0; nt < 8; ++nt) {
                mx0 = fmaxf(mx0, fmaxf(s[nt][0], s[nt][1]));
                mx1 = fmaxf(mx1, fmaxf(s[nt][2], s[nt][3]));
            }
            mx0 = fmaxf(mx0, __shfl_xor_sync(0xFFFFFFFFu, mx0, 1));
            mx0 = fmaxf(mx0, __shfl_xor_sync(0xFFFFFFFFu, mx0, 2));
            mx1 = fmaxf(mx1, __shfl_xor_sync(0xFFFFFFFFu, mx1, 1));
            mx1 = fmaxf(mx1, __shfl_xor_sync(0xFFFFFFFFu, mx1, 2));
            float nm0 = fmaxf(m0, mx0), nm1 = fmaxf(m1, mx1);
            float a0 = __expf(m0 - nm0), a1 = __expf(m1 - nm1);
            m0 = nm0; m1 = nm1;

            float sum0 = 0.f, sum1 = 0.f;
            uint32_t aph[4][4];                    // P hi only
            #pragma unroll
            for (int nt = 0; nt < 8; ++nt) {
                float p0 = __expf(s[nt][0] - m0), p1 = __expf(s[nt][1] - m0);
                float p2 = __expf(s[nt][2] - m1), p3 = __expf(s[nt][3] - m1);
                sum0 += p0 + p1; sum1 += p2 + p3;
                int kk = nt >> 1, r = (nt & 1) * 2;
                aph[kk][r]     = bf16x2pack(p0, p1);
                aph[kk][r + 1] = bf16x2pack(p2, p3);
            }
            sum0 += __shfl_xor_sync(0xFFFFFFFFu, sum0, 1);
            sum0 += __shfl_xor_sync(0xFFFFFFFFu, sum0, 2);
            sum1 += __shfl_xor_sync(0xFFFFFFFFu, sum1, 1);
            sum1 += __shfl_xor_sync(0xFFFFFFFFu, sum1, 2);
            l0 = l0 * a0 + sum0;
            l1 = l1 * a1 + sum1;
            #pragma unroll
            for (int nt = 0; nt < 4; ++nt) {
                o[nt][0] *= a0; o[nt][1] *= a0;
                o[nt][2] *= a1; o[nt][3] *= a1;
            }

            #pragma unroll
            for (int kk = 0; kk < 4; ++kk) {
                uint32_t vh[2][4];
                #pragma unroll
                for (int g = 0; g < 2; ++g) {
                    uint32_t off = SWZ128((uint32_t)((g * 16 + (lane >> 4) * 8 + (lane & 7)) * 128
                                                     + kk * 32 + ((lane >> 3) & 1) * 16));
                    ldsm_x4(vh[g][0], vh[g][1], vh[g][2], vh[g][3], bVh + off);
                }
                #pragma unroll
                for (int nt = 0; nt < 4; ++nt) {
                    const uint32_t* ph = vh[nt >> 1];
                    int e0 = (nt & 1) * 2, e1 = e0 + 1;
                    mma_bf16(o[nt], aph[kk], ph[e0], ph[e1]);
                }
            }
        }

        if (kt + 2 < nkt_b) { issueKV(kt + 2); CP_COMMIT(); }
    }

    // epilogue: normalize, write hi-only bf16 attention output
    float i0 = 1.f / l0, i1 = 1.f / l1;
    long t0 = (long)bn * S_ + qw + (lane >> 2);
    #pragma unroll
    for (int nt = 0; nt < 4; ++nt) {
        int col = h * 32 + nt * 8 + ((lane & 3) << 1);
        *(uint32_t*)(g_att2 + t0 * 512 + col)       = bf16x2pack(o[nt][0] * i0, o[nt][1] * i0);
        *(uint32_t*)(g_att2 + (t0 + 8) * 512 + col) = bf16x2pack(o[nt][2] * i1, o[nt][3] * i1);
    }
}

// ---------------- 6) fused out-proj GEMM + bias + residual + LayerNorm --------
// Pure bf16 (Ah·Woh), 8 stages. Block 64x256, SW64. Writes d_out.
#define OPROJ_SMEM (4 * 4096 + 4 * 16384)
__global__ void __launch_bounds__(256) oproj_ln_kernel(
    const float* __restrict__ x,  const float* __restrict__ bo,
    const float* __restrict__ gamma, const float* __restrict__ beta,
    float* __restrict__ out)
{
    extern __shared__ __align__(128) char dsmem[];
    __shared__ float pSum[4][64], pSq[4][64];
    const int tid = threadIdx.x;
    const int wid = tid >> 5, lane = tid & 31;
    const int wm = wid & 1;          // 2 warps along M (32 rows each)
    const int wn = wid >> 1;         // 4 warps along N (64 cols each)
    const int mBase = blockIdx.x * 64;

    const uint32_t baseA = smem_u32(dsmem);            // 4 bufs x 4KB
    const uint32_t baseW = baseA + 16384;              // 4 bufs x 16KB

    float acc[2][8][4];
    #pragma unroll
    for (int i = 0; i < 2; ++i)
        #pragma unroll
        for (int j = 0; j < 8; ++j)
            #pragma unroll
            for (int q = 0; q < 4; ++q) acc[i][j][q] = 0.f;

    auto issue = [&](int s) {
        int buf = s & 3;
        {
            int row = tid >> 2, c = tid & 3;
            uint32_t so = SWZ64((uint32_t)(row * 64 + c * 16));
            cp16(baseA + (uint32_t)(buf * 4096) + so,
                 g_att2 + ((long)(mBase + row)) * 512 + s * 32 + c * 8);
        }
        #pragma unroll
        for (int i = 0; i < 4; ++i) {
            int f = i * 256 + tid;
            int row = f >> 2, c = f & 3;
            uint32_t so = SWZ64((uint32_t)(row * 64 + c * 16));
            cp16(baseW + (uint32_t)(buf * 16384) + so,
                 g_wo2 + ((long)row) * 512 + s * 32 + c * 8);
        }
    };

    issue(0); CP_COMMIT();
    issue(1); CP_COMMIT();
    issue(2); CP_COMMIT();

    for (int s = 0; s < 8; ++s) {
        if (s <= 5)      { CP_WAIT2(); }
        else if (s == 6) { CP_WAIT1(); }
        else             { CP_WAIT0(); }
        __syncthreads();

        const int buf = s & 3;
        const uint32_t bA = baseA + buf * 4096;
        const uint32_t bW = baseW + buf * 16384;
        #pragma unroll
        for (int ks = 0; ks < 2; ++ks) {
            uint32_t a[2][4];
            #pragma unroll
            for (int mf = 0; mf < 2; ++mf) {
                uint32_t off = SWZ64((uint32_t)((wm * 32 + mf * 16 + (lane & 15)) * 64
                                                + ks * 32 + (lane >> 4) * 16));
                ldsm_x4(a[mf][0], a[mf][1], a[mf][2], a[mf][3], bA + off);
            }
            uint32_t b[4][4];
            #pragma unroll
            for (int g = 0; g < 4; ++g) {
                uint32_t off = SWZ64((uint32_t)((wn * 64 + g * 16 + (lane >> 4) * 8 + (lane & 7)) * 64
                                                + ks * 32 + ((lane >> 3) & 1) * 16));
                ldsm_x4(b[g][0], b[g][1], b[g][2], b[g][3], bW + off);
            }
            #pragma unroll
            for (int mf = 0; mf < 2; ++mf)
                #pragma unroll
                for (int nf = 0; nf < 8; ++nf) {
                    const uint32_t* bp = b[nf >> 1];
                    if (nf & 1) mma_bf16(acc[mf][nf], a[mf], bp[2], bp[3]);
                    else        mma_bf16(acc[mf][nf], a[mf], bp[0], bp[1]);
                }
        }
        if (s + 3 < 8) { issue(s + 3); CP_COMMIT(); }
    }
    __syncthreads();

    // epilogue: add bias + residual, per-row LN across warps, write d_out
    const int colq = (lane & 3) * 2;
    #pragma unroll
    for (int mf = 0; mf < 2; ++mf) {
        #pragma unroll
        for (int rr = 0; rr < 2; ++rr) {
            int rl = wm * 32 + mf * 16 + rr * 8 + (lane >> 2);   // local row 0..63
            int t = mBase + rl;
            int bnn = t >> 9, ss = t & 511;
            int bb = bnn >> 3, nn = bnn & 7;
            const float* xrow = x + (((long)(bb * S_ + ss)) * N_ + nn) * D_;
            float sum = 0.f, sq = 0.f;
            #pragma unroll
            for (int nf = 0; nf < 8; ++nf) {
                int col = wn * 64 + nf * 8 + colq;
                float2 xv = *(const float2*)(xrow + col);
                float2 bv = *(const float2*)(bo + col);
                float v0 = acc[mf][nf][rr * 2]     + xv.x + bv.x;
                float v1 = acc[mf][nf][rr * 2 + 1] + xv.y + bv.y;
                acc[mf][nf][rr * 2]     = v0;
                acc[mf][nf][rr * 2 + 1] = v1;
                sum += v0 + v1;
                sq = fmaf(v0, v0, sq);
                sq = fmaf(v1, v1, sq);
            }
            sum += __shfl_xor_sync(0xFFFFFFFFu, sum, 1);
            sum += __shfl_xor_sync(0xFFFFFFFFu, sum, 2);
            sq  += __shfl_xor_sync(0xFFFFFFFFu, sq,  1);
            sq  += __shfl_xor_sync(0xFFFFFFFFu, sq,  2);
            if ((lane & 3) == 0) {
                pSum[wn][rl] = sum;
                pSq[wn][rl]  = sq;
            }
        }
    }
    __syncthreads();

    #pragma unroll
    for (int mf = 0; mf < 2; ++mf) {
        #pragma unroll
        for (int rr = 0; rr < 2; ++rr) {
            int rl = wm * 32 + mf * 16 + rr * 8 + (lane >> 2);
            int t = mBase + rl;
            int bnn = t >> 9, ss = t & 511;
            int bb = bnn >> 3, nn = bnn & 7;
            float S  = pSum[0][rl] + pSum[1][rl] + pSum[2][rl] + pSum[3][rl];
            float Q  = pSq[0][rl]  + pSq[1][rl]  + pSq[2][rl]  + pSq[3][rl];
            float mu = S * (1.f / 256.f);
            float var = Q * (1.f / 256.f) - mu * mu;
            float rstd = rsqrtf(var + 1e-5f);
            float* orow = out + (((long)(bb * S_ + ss)) * N_ + nn) * D_;
            #pragma unroll
            for (int nf = 0; nf < 8; ++nf) {
                int col = wn * 64 + nf * 8 + colq;
                float2 gv = *(const float2*)(gamma + col);
                float2 tv = *(const float2*)(beta + col);
                float2 ov;
                ov.x = (acc[mf][nf][rr * 2]     - mu) * rstd * gv.x + tv.x;
                ov.y = (acc[mf][nf][rr * 2 + 1] - mu) * rstd * gv.y + tv.y;
                *(float2*)(orow + col) = ov;
            }
        }
    }
}

// ------------------------------ launch ----------------------------------------
// Input order per metadata (dict insertion order in setup_inputs):
//   0:x 1:Wq 2:Wk 3:Wv 4:Wo 5:bq 6:bk 7:bv 8:bo 9:gamma 10:beta 11:num_heads
extern "C" void kernel_launch(void* const* d_in, const int* in_sizes, int n_in,
                              void* d_out, int out_size) {
    const float* x     = (const float*)d_in[0];
    const float* Wq    = (const float*)d_in[1];
    const float* Wk    = (const float*)d_in[2];
    const float* Wv    = (const float*)d_in[3];
    const float* Wo    = (const float*)d_in[4];
    const float* bq    = (const float*)d_in[5];
    const float* bk    = (const float*)d_in[6];
    const float* bv    = (const float*)d_in[7];
    const float* bo    = (const float*)d_in[8];
    const float* gamma = (const float*)d_in[9];
    const float* beta  = (const float*)d_in[10];
    float* out = (float*)d_out;

    // idempotent; host-side attribute set (not a stream op, graph-capture safe)
    cudaFuncSetAttribute(qkv_gemm_kernel, cudaFuncAttributeMaxDynamicSharedMemorySize, QKV_SMEM);
    cudaFuncSetAttribute(attn_mma_kernel, cudaFuncAttributeMaxDynamicSharedMemorySize, ATTN_SMEM);
    cudaFuncSetAttribute(oproj_ln_kernel, cudaFuncAttributeMaxDynamicSharedMemorySize, OPROJ_SMEM);

    pe_kernel<<<256, 256>>>();
    addpe_split_kernel<<<4096, 256>>>(x);
    wsplit_all_kernel<<<1024, 256>>>(Wq, bq, Wk, bk, Wv, bv, Wo);
    qkv_gemm_kernel<<<dim3(6, 128), 256, QKV_SMEM>>>();
    attn_mma_kernel<<<dim3(4, H_, BN_), 256, ATTN_SMEM>>>();
    oproj_ln_kernel<<<256, 256, OPROJ_SMEM>>>(x, bo, gamma, beta, out);
}